// round 4
// baseline (speedup 1.0000x reference)
#include <cuda_runtime.h>
#include <math.h>

#define B_    2
#define C_    256
#define NTOK  9216
#define L_    6

#define BR 64
#define BC 64

// ---------------- scratch (no allocations allowed) ----------------
__device__ float g_Wf[L_*C_*C_];     // BN-folded weights
__device__ float g_bf[L_*C_];        // BN-folded bias
__device__ float g_t  [B_*C_*NTOK];  // temp (psi1 / phi1)
__device__ float g_q  [B_*C_*NTOK];  // psi2 out  [B][C][N]
__device__ float g_k  [B_*C_*NTOK];  // phi2 out  [B][C][N]
__device__ float g_v  [B_*C_*NTOK];  // f_down out [B][C][N]
__device__ float g_ctx[B_*C_*NTOK];  // attention out [B][C][N]

// ---------------- prep: fold BN into W and bias ----------------
// convbn(x) = (s*W) @ x + (b - m*s), s = g*rsqrt(v+eps)
__global__ void prep_kernel(const float* __restrict__ Ws, const float* __restrict__ gam,
                            const float* __restrict__ bet, const float* __restrict__ mu,
                            const float* __restrict__ var) {
    int l = blockIdx.x;
    int tid = threadIdx.x;
    __shared__ float sc[C_];
    float s = gam[l*C_+tid] * rsqrtf(var[l*C_+tid] + 1e-5f);
    sc[tid] = s;
    g_bf[l*C_+tid] = bet[l*C_+tid] - mu[l*C_+tid]*s;
    __syncthreads();
    const float* Wl = Ws + l*C_*C_;
    float*       Wo = g_Wf + l*C_*C_;
    for (int t = tid; t < C_*C_; t += blockDim.x) {
        Wo[t] = Wl[t] * sc[t >> 8];
    }
}

// ---------------- fused convbn+relu GEMM ----------------
// out[b][o][n] = relu( sum_c Wf[o][c]*in[b][c][n] + bf[o] )
// Tile: 64(o) x 128(n), K-step 16, 256 threads, 4x8 per thread.
__global__ __launch_bounds__(256) void convbn_kernel(const float* __restrict__ in,
                                                     float* __restrict__ out, int layer) {
    const float* Wf = g_Wf + layer*C_*C_;
    const float* bf = g_bf + layer*C_;
    const int n0 = blockIdx.x * 128;
    const int o0 = blockIdx.y * 64;
    const float* inb  = in  + (size_t)blockIdx.z * C_ * NTOK;
    float*       outb = out + (size_t)blockIdx.z * C_ * NTOK;

    __shared__ float As[16][64];    // [k][o]
    __shared__ float Bs[16][128];   // [k][n]

    const int tid = threadIdx.x;
    const int tx = tid & 15, ty = tid >> 4;

    float acc[4][8];
#pragma unroll
    for (int i = 0; i < 4; i++)
#pragma unroll
        for (int j = 0; j < 8; j++) acc[i][j] = 0.f;

    const int oA = tid >> 2, cA = (tid & 3) << 2;
    const int bRow = tid >> 5, bCol4 = (tid & 31);

    for (int c0 = 0; c0 < C_; c0 += 16) {
        // prefetch global into regs (overlaps with previous tile's compute)
        float4 w  = *(const float4*)&Wf[(o0+oA)*C_ + c0 + cA];
        float4 b0 = *(const float4*)&inb[(size_t)(c0 + bRow    )*NTOK + n0 + bCol4*4];
        float4 b1 = *(const float4*)&inb[(size_t)(c0 + 8 + bRow)*NTOK + n0 + bCol4*4];
        __syncthreads();
        As[cA+0][oA] = w.x; As[cA+1][oA] = w.y; As[cA+2][oA] = w.z; As[cA+3][oA] = w.w;
        *(float4*)&Bs[bRow    ][bCol4*4] = b0;
        *(float4*)&Bs[8 + bRow][bCol4*4] = b1;
        __syncthreads();
#pragma unroll
        for (int k = 0; k < 16; k++) {
            float4 a = *(const float4*)&As[k][ty*4];
            float4 p = *(const float4*)&Bs[k][tx*8];
            float4 q = *(const float4*)&Bs[k][tx*8+4];
            float av[4] = {a.x, a.y, a.z, a.w};
            float bv[8] = {p.x, p.y, p.z, p.w, q.x, q.y, q.z, q.w};
#pragma unroll
            for (int i = 0; i < 4; i++)
#pragma unroll
                for (int j = 0; j < 8; j++)
                    acc[i][j] = fmaf(av[i], bv[j], acc[i][j]);
        }
    }

#pragma unroll
    for (int i = 0; i < 4; i++) {
        int o = o0 + ty*4 + i;
        float bias = bf[o];
        float4 r0, r1;
        r0.x = fmaxf(acc[i][0]+bias, 0.f);
        r0.y = fmaxf(acc[i][1]+bias, 0.f);
        r0.z = fmaxf(acc[i][2]+bias, 0.f);
        r0.w = fmaxf(acc[i][3]+bias, 0.f);
        r1.x = fmaxf(acc[i][4]+bias, 0.f);
        r1.y = fmaxf(acc[i][5]+bias, 0.f);
        r1.z = fmaxf(acc[i][6]+bias, 0.f);
        r1.w = fmaxf(acc[i][7]+bias, 0.f);
        *(float4*)&outb[(size_t)o*NTOK + n0 + tx*8    ] = r0;
        *(float4*)&outb[(size_t)o*NTOK + n0 + tx*8 + 4] = r1;
    }
}

// ---------------- flash attention (fp32, online softmax) ----------------
// q,k,v stored [B][C=256][N].  sim[n,m] = sum_c q[c,n]k[c,m]; softmax over m;
// ctx[c,n] = sum_m p[n,m] v[c,m].  One CTA = 64 query rows; loops all 9216 keys.
#define ATTN_SMEM_FLOATS (256*64 + 256*64 + 64*260 + 64*65 + 64*16 + 3*64)

__global__ __launch_bounds__(256) void attn_kernel(const float* __restrict__ qg,
                                                   const float* __restrict__ kg,
                                                   const float* __restrict__ vg,
                                                   float* __restrict__ cg) {
    extern __shared__ float smf[];
    float* sQ  = smf;               // [256][64]  (row k, col i)
    float* sK  = sQ + 256*64;       // [256][64]  (row k, col j)
    float* sV  = sK + 256*64;       // [64][260]  (row j, col k')  (transposed, padded)
    float* sP  = sV + 64*260;       // [64][65]   (row j, col i)
    float* red = sP + 64*65;        // [64][16]   partial max / partial sum
    float* m_s = red + 64*16;       // [64] running max
    float* l_s = m_s + 64;          // [64] running sum
    float* fac = l_s + 64;          // [64] rescale factor

    const int n0 = blockIdx.x * BR;
    const size_t boff = (size_t)blockIdx.y * C_ * NTOK;
    const float* qb = qg + boff;
    const float* kb = kg + boff;
    const float* vb = vg + boff;
    float*       cb = cg + boff;

    const int tid = threadIdx.x;
    const int tx = tid & 15, ty = tid >> 4;
    const int i0 = ty * 4, j0 = tx * 4;
    const int jg = tid & 15, kb16 = tid >> 4;

    // load Q tile once: sQ[k][i]
#pragma unroll
    for (int rep = 0; rep < 16; rep++) {
        int k = kb16 + rep*16;
        *(float4*)&sQ[k*64 + jg*4] = *(const float4*)&qb[(size_t)k*NTOK + n0 + jg*4];
    }
    if (tid < 64) { m_s[tid] = -1e30f; l_s[tid] = 0.f; }

    float o_acc[4][16];
#pragma unroll
    for (int i = 0; i < 4; i++)
#pragma unroll
        for (int c = 0; c < 16; c++) o_acc[i][c] = 0.f;

    __syncthreads();

    for (int t = 0; t < NTOK/BC; t++) {
        const int m0 = t * BC;
        // ---- load K tile [k][j] and V tile transposed [j][k'] ----
#pragma unroll
        for (int rep = 0; rep < 16; rep++) {
            int k = kb16 + rep*16;
            *(float4*)&sK[k*64 + jg*4] = *(const float4*)&kb[(size_t)k*NTOK + m0 + jg*4];
        }
#pragma unroll
        for (int rep = 0; rep < 16; rep++) {
            int k = kb16 + rep*16;
            float4 vl = *(const float4*)&vb[(size_t)k*NTOK + m0 + jg*4];
            sV[(jg*4+0)*260 + k] = vl.x;
            sV[(jg*4+1)*260 + k] = vl.y;
            sV[(jg*4+2)*260 + k] = vl.z;
            sV[(jg*4+3)*260 + k] = vl.w;
        }
        __syncthreads();

        // ---- S = Q^T K  (4x4 per thread) ----
        float s[4][4];
#pragma unroll
        for (int i = 0; i < 4; i++)
#pragma unroll
            for (int j = 0; j < 4; j++) s[i][j] = 0.f;

#pragma unroll 4
        for (int k = 0; k < 256; k++) {
            float4 a = *(const float4*)&sQ[k*64 + i0];
            float4 b = *(const float4*)&sK[k*64 + j0];
            s[0][0] = fmaf(a.x, b.x, s[0][0]); s[0][1] = fmaf(a.x, b.y, s[0][1]);
            s[0][2] = fmaf(a.x, b.z, s[0][2]); s[0][3] = fmaf(a.x, b.w, s[0][3]);
            s[1][0] = fmaf(a.y, b.x, s[1][0]); s[1][1] = fmaf(a.y, b.y, s[1][1]);
            s[1][2] = fmaf(a.y, b.z, s[1][2]); s[1][3] = fmaf(a.y, b.w, s[1][3]);
            s[2][0] = fmaf(a.z, b.x, s[2][0]); s[2][1] = fmaf(a.z, b.y, s[2][1]);
            s[2][2] = fmaf(a.z, b.z, s[2][2]); s[2][3] = fmaf(a.z, b.w, s[2][3]);
            s[3][0] = fmaf(a.w, b.x, s[3][0]); s[3][1] = fmaf(a.w, b.y, s[3][1]);
            s[3][2] = fmaf(a.w, b.z, s[3][2]); s[3][3] = fmaf(a.w, b.w, s[3][3]);
        }

        // ---- row-max partials ----
#pragma unroll
        for (int i = 0; i < 4; i++) {
            float lm = fmaxf(fmaxf(s[i][0], s[i][1]), fmaxf(s[i][2], s[i][3]));
            red[(i0+i)*16 + tx] = lm;
        }
        __syncthreads();
        if (tid < 64) {
            float mt = red[tid*16];
#pragma unroll
            for (int u = 1; u < 16; u++) mt = fmaxf(mt, red[tid*16+u]);
            float mo = m_s[tid];
            float mn = fmaxf(mo, mt);
            m_s[tid] = mn;
            fac[tid] = __expf(mo - mn);
        }
        __syncthreads();

        // ---- exp, write P^T, partial sums ----
#pragma unroll
        for (int i = 0; i < 4; i++) {
            float mi = m_s[i0+i];
            float ps = 0.f;
#pragma unroll
            for (int j = 0; j < 4; j++) {
                float p = __expf(s[i][j] - mi);
                sP[(j0+j)*65 + i0 + i] = p;
                ps += p;
            }
            red[(i0+i)*16 + tx] = ps;
        }
        __syncthreads();
        if (tid < 64) {
            float st = 0.f;
#pragma unroll
            for (int u = 0; u < 16; u++) st += red[tid*16+u];
            l_s[tid] = l_s[tid]*fac[tid] + st;
        }

        // ---- rescale O (fac stable: written 2 syncs ago) ----
        float f0 = fac[i0+0], f1 = fac[i0+1], f2 = fac[i0+2], f3 = fac[i0+3];
#pragma unroll
        for (int c = 0; c < 16; c++) {
            o_acc[0][c] *= f0; o_acc[1][c] *= f1;
            o_acc[2][c] *= f2; o_acc[3][c] *= f3;
        }

        // ---- O += P V   (4 rows x 16 k' per thread) ----
#pragma unroll 2
        for (int j = 0; j < BC; j++) {
            float p0 = sP[j*65 + i0    ];
            float p1 = sP[j*65 + i0 + 1];
            float p2 = sP[j*65 + i0 + 2];
            float p3 = sP[j*65 + i0 + 3];
#pragma unroll
            for (int c = 0; c < 4; c++) {
                float4 v4 = *(const float4*)&sV[j*260 + tx*4 + c*64];
                o_acc[0][c*4+0] = fmaf(p0, v4.x, o_acc[0][c*4+0]);
                o_acc[0][c*4+1] = fmaf(p0, v4.y, o_acc[0][c*4+1]);
                o_acc[0][c*4+2] = fmaf(p0, v4.z, o_acc[0][c*4+2]);
                o_acc[0][c*4+3] = fmaf(p0, v4.w, o_acc[0][c*4+3]);
                o_acc[1][c*4+0] = fmaf(p1, v4.x, o_acc[1][c*4+0]);
                o_acc[1][c*4+1] = fmaf(p1, v4.y, o_acc[1][c*4+1]);
                o_acc[1][c*4+2] = fmaf(p1, v4.z, o_acc[1][c*4+2]);
                o_acc[1][c*4+3] = fmaf(p1, v4.w, o_acc[1][c*4+3]);
                o_acc[2][c*4+0] = fmaf(p2, v4.x, o_acc[2][c*4+0]);
                o_acc[2][c*4+1] = fmaf(p2, v4.y, o_acc[2][c*4+1]);
                o_acc[2][c*4+2] = fmaf(p2, v4.z, o_acc[2][c*4+2]);
                o_acc[2][c*4+3] = fmaf(p2, v4.w, o_acc[2][c*4+3]);
                o_acc[3][c*4+0] = fmaf(p3, v4.x, o_acc[3][c*4+0]);
                o_acc[3][c*4+1] = fmaf(p3, v4.y, o_acc[3][c*4+1]);
                o_acc[3][c*4+2] = fmaf(p3, v4.z, o_acc[3][c*4+2]);
                o_acc[3][c*4+3] = fmaf(p3, v4.w, o_acc[3][c*4+3]);
            }
        }
        __syncthreads();
    }

    // ---- finalize: divide by l, write ctx[k'][n] ----
    float inv0 = 1.f / l_s[i0+0];
    float inv1 = 1.f / l_s[i0+1];
    float inv2 = 1.f / l_s[i0+2];
    float inv3 = 1.f / l_s[i0+3];
#pragma unroll
    for (int c = 0; c < 4; c++) {
#pragma unroll
        for (int cc = 0; cc < 4; cc++) {
            int kcol = c*64 + tx*4 + cc;
            float4 r;
            r.x = o_acc[0][c*4+cc] * inv0;
            r.y = o_acc[1][c*4+cc] * inv1;
            r.z = o_acc[2][c*4+cc] * inv2;
            r.w = o_acc[3][c*4+cc] * inv3;
            *(float4*)&cb[(size_t)kcol*NTOK + n0 + i0] = r;
        }
    }
}

// ---------------- launch ----------------
extern "C" void kernel_launch(void* const* d_in, const int* in_sizes, int n_in,
                              void* d_out, int out_size) {
    const float* x   = (const float*)d_in[0];
    const float* fk  = (const float*)d_in[1];
    const float* Ws  = (const float*)d_in[2];
    const float* gam = (const float*)d_in[3];
    const float* bet = (const float*)d_in[4];
    const float* mu  = (const float*)d_in[5];
    const float* var = (const float*)d_in[6];
    float* out = (float*)d_out;

    float *p_t, *p_q, *p_k, *p_v, *p_ctx;
    cudaGetSymbolAddress((void**)&p_t,   g_t);
    cudaGetSymbolAddress((void**)&p_q,   g_q);
    cudaGetSymbolAddress((void**)&p_k,   g_k);
    cudaGetSymbolAddress((void**)&p_v,   g_v);
    cudaGetSymbolAddress((void**)&p_ctx, g_ctx);

    const int attn_smem = ATTN_SMEM_FLOATS * 4;   // 219,136 B
    cudaFuncSetAttribute(attn_kernel, cudaFuncAttributeMaxDynamicSharedMemorySize, attn_smem);

    prep_kernel<<<L_, 256>>>(Ws, gam, bet, mu, var);

    dim3 cgrid(NTOK/128, C_/64, B_);
    convbn_kernel<<<cgrid, 256>>>(x,     p_t, 0);   // psi1
    convbn_kernel<<<cgrid, 256>>>(p_t,   p_q, 1);   // psi2  -> q
    convbn_kernel<<<cgrid, 256>>>(fk,    p_t, 2);   // phi1
    convbn_kernel<<<cgrid, 256>>>(p_t,   p_k, 3);   // phi2  -> k
    convbn_kernel<<<cgrid, 256>>>(fk,    p_v, 4);   // f_down -> v

    attn_kernel<<<dim3(NTOK/BR, B_), 256, attn_smem>>>(p_q, p_k, p_v, p_ctx);

    convbn_kernel<<<cgrid, 256>>>(p_ctx, out, 5);   // f_up -> output
}

// round 5
// speedup vs baseline: 1.6113x; 1.6113x over previous
#include <cuda_runtime.h>
#include <math.h>

#define B_    2
#define C_    256
#define NTOK  9216
#define L_    6

#define BR 64
#define BC 64

// ---------------- scratch (no allocations allowed) ----------------
__device__ float g_Wf[L_*C_*C_];     // BN-folded weights
__device__ float g_bf[L_*C_];        // BN-folded bias
__device__ float g_t  [B_*C_*NTOK];  // temp (psi1 / phi1)
__device__ float g_q  [B_*C_*NTOK];  // psi2 out  [B][C][N]
__device__ float g_k  [B_*C_*NTOK];  // phi2 out  [B][C][N]
__device__ float g_v  [B_*C_*NTOK];  // f_down out [B][C][N]
__device__ float g_ctx[B_*C_*NTOK];  // attention out [B][C][N]

// ---------------- prep: fold BN into W and bias ----------------
// convbn(x) = (s*W) @ x + (b - m*s), s = g*rsqrt(v+eps)
__global__ void prep_kernel(const float* __restrict__ Ws, const float* __restrict__ gam,
                            const float* __restrict__ bet, const float* __restrict__ mu,
                            const float* __restrict__ var) {
    int l = blockIdx.x;
    int tid = threadIdx.x;
    __shared__ float sc[C_];
    float s = gam[l*C_+tid] * rsqrtf(var[l*C_+tid] + 1e-5f);
    sc[tid] = s;
    g_bf[l*C_+tid] = bet[l*C_+tid] - mu[l*C_+tid]*s;
    __syncthreads();
    const float* Wl = Ws + l*C_*C_;
    float*       Wo = g_Wf + l*C_*C_;
    for (int t = tid; t < C_*C_; t += blockDim.x) {
        Wo[t] = Wl[t] * sc[t >> 8];
    }
}

// ---------------- fused convbn+relu GEMM ----------------
// out[b][o][n] = relu( sum_c Wf[o][c]*in[b][c][n] + bf[o] )
// Tile: 64(o) x 128(n), K-step 16, 256 threads, 4x8 per thread.
__global__ __launch_bounds__(256) void convbn_kernel(const float* __restrict__ in,
                                                     float* __restrict__ out, int layer) {
    const float* Wf = g_Wf + layer*C_*C_;
    const float* bf = g_bf + layer*C_;
    const int n0 = blockIdx.x * 128;
    const int o0 = blockIdx.y * 64;
    const float* inb  = in  + (size_t)blockIdx.z * C_ * NTOK;
    float*       outb = out + (size_t)blockIdx.z * C_ * NTOK;

    __shared__ float As[16][64];    // [k][o]
    __shared__ float Bs[16][128];   // [k][n]

    const int tid = threadIdx.x;
    const int tx = tid & 15, ty = tid >> 4;

    float acc[4][8];
#pragma unroll
    for (int i = 0; i < 4; i++)
#pragma unroll
        for (int j = 0; j < 8; j++) acc[i][j] = 0.f;

    const int oA = tid >> 2, cA = (tid & 3) << 2;
    const int bRow = tid >> 5, bCol4 = (tid & 31);

    for (int c0 = 0; c0 < C_; c0 += 16) {
        // prefetch global into regs (overlaps with previous tile's compute)
        float4 w  = *(const float4*)&Wf[(o0+oA)*C_ + c0 + cA];
        float4 b0 = *(const float4*)&inb[(size_t)(c0 + bRow    )*NTOK + n0 + bCol4*4];
        float4 b1 = *(const float4*)&inb[(size_t)(c0 + 8 + bRow)*NTOK + n0 + bCol4*4];
        __syncthreads();
        As[cA+0][oA] = w.x; As[cA+1][oA] = w.y; As[cA+2][oA] = w.z; As[cA+3][oA] = w.w;
        *(float4*)&Bs[bRow    ][bCol4*4] = b0;
        *(float4*)&Bs[8 + bRow][bCol4*4] = b1;
        __syncthreads();
#pragma unroll
        for (int k = 0; k < 16; k++) {
            float4 a = *(const float4*)&As[k][ty*4];
            float4 p = *(const float4*)&Bs[k][tx*8];
            float4 q = *(const float4*)&Bs[k][tx*8+4];
            float av[4] = {a.x, a.y, a.z, a.w};
            float bv[8] = {p.x, p.y, p.z, p.w, q.x, q.y, q.z, q.w};
#pragma unroll
            for (int i = 0; i < 4; i++)
#pragma unroll
                for (int j = 0; j < 8; j++)
                    acc[i][j] = fmaf(av[i], bv[j], acc[i][j]);
        }
    }

#pragma unroll
    for (int i = 0; i < 4; i++) {
        int o = o0 + ty*4 + i;
        float bias = bf[o];
        float4 r0, r1;
        r0.x = fmaxf(acc[i][0]+bias, 0.f);
        r0.y = fmaxf(acc[i][1]+bias, 0.f);
        r0.z = fmaxf(acc[i][2]+bias, 0.f);
        r0.w = fmaxf(acc[i][3]+bias, 0.f);
        r1.x = fmaxf(acc[i][4]+bias, 0.f);
        r1.y = fmaxf(acc[i][5]+bias, 0.f);
        r1.z = fmaxf(acc[i][6]+bias, 0.f);
        r1.w = fmaxf(acc[i][7]+bias, 0.f);
        *(float4*)&outb[(size_t)o*NTOK + n0 + tx*8    ] = r0;
        *(float4*)&outb[(size_t)o*NTOK + n0 + tx*8 + 4] = r1;
    }
}

// ---------------- flash attention (fp32, online softmax) ----------------
// q,k,v stored [B][C=256][N].  sim[n,m] = sum_c q[c,n]k[c,m]; softmax over m;
// ctx[c,n] = sum_m p[n,m] v[c,m].  One CTA = 64 query rows; loops all 9216 keys.
#define ATTN_SMEM_FLOATS (256*64 + 256*64 + 64*260 + 64*65 + 64*16 + 3*64)

__global__ __launch_bounds__(256) void attn_kernel(const float* __restrict__ qg,
                                                   const float* __restrict__ kg,
                                                   const float* __restrict__ vg,
                                                   float* __restrict__ cg) {
    extern __shared__ float smf[];
    float* sQ  = smf;               // [256][64]  (row k, col i)
    float* sK  = sQ + 256*64;       // [256][64]  (row k, col j)
    float* sV  = sK + 256*64;       // [64][260]  (row j, col k')  (transposed, padded)
    float* sP  = sV + 64*260;       // [64][65]   (row j, col i)
    float* red = sP + 64*65;        // [64][16]   partial max / partial sum
    float* m_s = red + 64*16;       // [64] running max
    float* l_s = m_s + 64;          // [64] running sum
    float* fac = l_s + 64;          // [64] rescale factor

    const int n0 = blockIdx.x * BR;
    const size_t boff = (size_t)blockIdx.y * C_ * NTOK;
    const float* qb = qg + boff;
    const float* kb = kg + boff;
    const float* vb = vg + boff;
    float*       cb = cg + boff;

    const int tid = threadIdx.x;
    const int tx = tid & 15, ty = tid >> 4;
    const int i0 = ty * 4, j0 = tx * 4;
    const int jg = tid & 15, kb16 = tid >> 4;

    // load Q tile once: sQ[k][i]
#pragma unroll
    for (int rep = 0; rep < 16; rep++) {
        int k = kb16 + rep*16;
        *(float4*)&sQ[k*64 + jg*4] = *(const float4*)&qb[(size_t)k*NTOK + n0 + jg*4];
    }
    if (tid < 64) { m_s[tid] = -1e30f; l_s[tid] = 0.f; }

    float o_acc[4][16];
#pragma unroll
    for (int i = 0; i < 4; i++)
#pragma unroll
        for (int c = 0; c < 16; c++) o_acc[i][c] = 0.f;

    __syncthreads();

    for (int t = 0; t < NTOK/BC; t++) {
        const int m0 = t * BC;
        // ---- load K tile [k][j] and V tile transposed [j][k'] ----
#pragma unroll
        for (int rep = 0; rep < 16; rep++) {
            int k = kb16 + rep*16;
            *(float4*)&sK[k*64 + jg*4] = *(const float4*)&kb[(size_t)k*NTOK + m0 + jg*4];
        }
#pragma unroll
        for (int rep = 0; rep < 16; rep++) {
            int k = kb16 + rep*16;
            float4 vl = *(const float4*)&vb[(size_t)k*NTOK + m0 + jg*4];
            sV[(jg*4+0)*260 + k] = vl.x;
            sV[(jg*4+1)*260 + k] = vl.y;
            sV[(jg*4+2)*260 + k] = vl.z;
            sV[(jg*4+3)*260 + k] = vl.w;
        }
        __syncthreads();

        // ---- S = Q^T K  (4x4 per thread) ----
        float s[4][4];
#pragma unroll
        for (int i = 0; i < 4; i++)
#pragma unroll
            for (int j = 0; j < 4; j++) s[i][j] = 0.f;

#pragma unroll 4
        for (int k = 0; k < 256; k++) {
            float4 a = *(const float4*)&sQ[k*64 + i0];
            float4 b = *(const float4*)&sK[k*64 + j0];
            s[0][0] = fmaf(a.x, b.x, s[0][0]); s[0][1] = fmaf(a.x, b.y, s[0][1]);
            s[0][2] = fmaf(a.x, b.z, s[0][2]); s[0][3] = fmaf(a.x, b.w, s[0][3]);
            s[1][0] = fmaf(a.y, b.x, s[1][0]); s[1][1] = fmaf(a.y, b.y, s[1][1]);
            s[1][2] = fmaf(a.y, b.z, s[1][2]); s[1][3] = fmaf(a.y, b.w, s[1][3]);
            s[2][0] = fmaf(a.z, b.x, s[2][0]); s[2][1] = fmaf(a.z, b.y, s[2][1]);
            s[2][2] = fmaf(a.z, b.z, s[2][2]); s[2][3] = fmaf(a.z, b.w, s[2][3]);
            s[3][0] = fmaf(a.w, b.x, s[3][0]); s[3][1] = fmaf(a.w, b.y, s[3][1]);
            s[3][2] = fmaf(a.w, b.z, s[3][2]); s[3][3] = fmaf(a.w, b.w, s[3][3]);
        }

        // ---- row-max partials ----
#pragma unroll
        for (int i = 0; i < 4; i++) {
            float lm = fmaxf(fmaxf(s[i][0], s[i][1]), fmaxf(s[i][2], s[i][3]));
            red[(i0+i)*16 + tx] = lm;
        }
        __syncthreads();
        if (tid < 64) {
            float mt = red[tid*16];
#pragma unroll
            for (int u = 1; u < 16; u++) mt = fmaxf(mt, red[tid*16+u]);
            float mo = m_s[tid];
            float mn = fmaxf(mo, mt);
            m_s[tid] = mn;
            fac[tid] = __expf(mo - mn);
        }
        __syncthreads();

        // ---- exp, write P^T, partial sums ----
#pragma unroll
        for (int i = 0; i < 4; i++) {
            float mi = m_s[i0+i];
            float ps = 0.f;
#pragma unroll
            for (int j = 0; j < 4; j++) {
                float p = __expf(s[i][j] - mi);
                sP[(j0+j)*65 + i0 + i] = p;
                ps += p;
            }
            red[(i0+i)*16 + tx] = ps;
        }
        __syncthreads();
        if (tid < 64) {
            float st = 0.f;
#pragma unroll
            for (int u = 0; u < 16; u++) st += red[tid*16+u];
            l_s[tid] = l_s[tid]*fac[tid] + st;
        }

        // ---- rescale O (fac stable: written 2 syncs ago) ----
        float f0 = fac[i0+0], f1 = fac[i0+1], f2 = fac[i0+2], f3 = fac[i0+3];
#pragma unroll
        for (int c = 0; c < 16; c++) {
            o_acc[0][c] *= f0; o_acc[1][c] *= f1;
            o_acc[2][c] *= f2; o_acc[3][c] *= f3;
        }

        // ---- O += P V   (4 rows x 16 k' per thread) ----
#pragma unroll 2
        for (int j = 0; j < BC; j++) {
            float p0 = sP[j*65 + i0    ];
            float p1 = sP[j*65 + i0 + 1];
            float p2 = sP[j*65 + i0 + 2];
            float p3 = sP[j*65 + i0 + 3];
#pragma unroll
            for (int c = 0; c < 4; c++) {
                float4 v4 = *(const float4*)&sV[j*260 + tx*4 + c*64];
                o_acc[0][c*4+0] = fmaf(p0, v4.x, o_acc[0][c*4+0]);
                o_acc[0][c*4+1] = fmaf(p0, v4.y, o_acc[0][c*4+1]);
                o_acc[0][c*4+2] = fmaf(p0, v4.z, o_acc[0][c*4+2]);
                o_acc[0][c*4+3] = fmaf(p0, v4.w, o_acc[0][c*4+3]);
                o_acc[1][c*4+0] = fmaf(p1, v4.x, o_acc[1][c*4+0]);
                o_acc[1][c*4+1] = fmaf(p1, v4.y, o_acc[1][c*4+1]);
                o_acc[1][c*4+2] = fmaf(p1, v4.z, o_acc[1][c*4+2]);
                o_acc[1][c*4+3] = fmaf(p1, v4.w, o_acc[1][c*4+3]);
                o_acc[2][c*4+0] = fmaf(p2, v4.x, o_acc[2][c*4+0]);
                o_acc[2][c*4+1] = fmaf(p2, v4.y, o_acc[2][c*4+1]);
                o_acc[2][c*4+2] = fmaf(p2, v4.z, o_acc[2][c*4+2]);
                o_acc[2][c*4+3] = fmaf(p2, v4.w, o_acc[2][c*4+3]);
                o_acc[3][c*4+0] = fmaf(p3, v4.x, o_acc[3][c*4+0]);
                o_acc[3][c*4+1] = fmaf(p3, v4.y, o_acc[3][c*4+1]);
                o_acc[3][c*4+2] = fmaf(p3, v4.z, o_acc[3][c*4+2]);
                o_acc[3][c*4+3] = fmaf(p3, v4.w, o_acc[3][c*4+3]);
            }
        }
        __syncthreads();
    }

    // ---- finalize: divide by l, write ctx[k'][n] ----
    float inv0 = 1.f / l_s[i0+0];
    float inv1 = 1.f / l_s[i0+1];
    float inv2 = 1.f / l_s[i0+2];
    float inv3 = 1.f / l_s[i0+3];
#pragma unroll
    for (int c = 0; c < 4; c++) {
#pragma unroll
        for (int cc = 0; cc < 4; cc++) {
            int kcol = c*64 + tx*4 + cc;
            float4 r;
            r.x = o_acc[0][c*4+cc] * inv0;
            r.y = o_acc[1][c*4+cc] * inv1;
            r.z = o_acc[2][c*4+cc] * inv2;
            r.w = o_acc[3][c*4+cc] * inv3;
            *(float4*)&cb[(size_t)kcol*NTOK + n0 + i0] = r;
        }
    }
}

// ---------------- launch ----------------
extern "C" void kernel_launch(void* const* d_in, const int* in_sizes, int n_in,
                              void* d_out, int out_size) {
    const float* x   = (const float*)d_in[0];
    const float* fk  = (const float*)d_in[1];
    const float* Ws  = (const float*)d_in[2];
    const float* gam = (const float*)d_in[3];
    const float* bet = (const float*)d_in[4];
    const float* mu  = (const float*)d_in[5];
    const float* var = (const float*)d_in[6];
    float* out = (float*)d_out;

    float *p_t, *p_q, *p_k, *p_v, *p_ctx;
    cudaGetSymbolAddress((void**)&p_t,   g_t);
    cudaGetSymbolAddress((void**)&p_q,   g_q);
    cudaGetSymbolAddress((void**)&p_k,   g_k);
    cudaGetSymbolAddress((void**)&p_v,   g_v);
    cudaGetSymbolAddress((void**)&p_ctx, g_ctx);

    const int attn_smem = ATTN_SMEM_FLOATS * 4;   // 219,136 B
    cudaFuncSetAttribute(attn_kernel, cudaFuncAttributeMaxDynamicSharedMemorySize, attn_smem);

    prep_kernel<<<L_, 256>>>(Ws, gam, bet, mu, var);

    dim3 cgrid(NTOK/128, C_/64, B_);
    convbn_kernel<<<cgrid, 256>>>(x,     p_t, 0);   // psi1
    convbn_kernel<<<cgrid, 256>>>(p_t,   p_q, 1);   // psi2  -> q
    convbn_kernel<<<cgrid, 256>>>(fk,    p_t, 2);   // phi1
    convbn_kernel<<<cgrid, 256>>>(p_t,   p_k, 3);   // phi2  -> k
    convbn_kernel<<<cgrid, 256>>>(fk,    p_v, 4);   // f_down -> v

    attn_kernel<<<dim3(NTOK/BR, B_), 256, attn_smem>>>(p_q, p_k, p_v, p_ctx);

    convbn_kernel<<<cgrid, 256>>>(p_ctx, out, 5);   // f_up -> output
}

// round 7
// speedup vs baseline: 5.0202x; 3.1156x over previous
#include <cuda_runtime.h>
#include <cuda_fp16.h>
#include <math.h>

#define B_    2
#define C_    256
#define NTOK  9216
#define L_    6
#define TM    128
#define TN    64
#define NT    (NTOK/TN)     // 144 key tiles
#define NQT   (NTOK/TM)     // 72 query tiles
#define LOG2E 1.4426950408889634f

// ---------------- scratch (no device allocations allowed) ----------------
__device__ float    g_Wf [L_*C_*C_];
__device__ float    g_bf [L_*C_];
__device__ float    g_t  [B_*C_*NTOK];        // fp32 temp
__device__ unsigned g_qhl[B_*C_*NTOK];        // q fp16 hi | lo<<16 (pre-scaled by log2e)
__device__ unsigned g_khl[B_*C_*NTOK];        // k fp16 hi | lo<<16
__device__ unsigned short g_vh[B_*C_*NTOK];   // v fp16
__device__ float    g_ctx[B_*C_*NTOK];        // attention out fp32 [B][C][N]

// ---------------- helpers ----------------
__device__ __forceinline__ unsigned splitpack(float v) {
    __half h = __float2half_rn(v);
    __half l = __float2half_rn(v - __half2float(h));
    return (unsigned)__half_as_ushort(h) | ((unsigned)__half_as_ushort(l) << 16);
}
__device__ __forceinline__ unsigned smem_u32(const void* p) {
    unsigned a;
    asm("{ .reg .u64 t; cvta.to.shared.u64 t, %1; cvt.u32.u64 %0, t; }" : "=r"(a) : "l"(p));
    return a;
}
__device__ __forceinline__ void ldsm4(unsigned* r, unsigned addr) {
    asm volatile("ldmatrix.sync.aligned.m8n8.x4.shared.b16 {%0,%1,%2,%3}, [%4];"
        : "=r"(r[0]), "=r"(r[1]), "=r"(r[2]), "=r"(r[3]) : "r"(addr));
}
__device__ __forceinline__ void ldsm2(unsigned* r, unsigned addr) {
    asm volatile("ldmatrix.sync.aligned.m8n8.x2.shared.b16 {%0,%1}, [%2];"
        : "=r"(r[0]), "=r"(r[1]) : "r"(addr));
}
__device__ __forceinline__ void mma16816(float* c, const unsigned* a, const unsigned* b) {
    asm volatile("mma.sync.aligned.m16n8k16.row.col.f32.f16.f16.f32 "
        "{%0,%1,%2,%3}, {%4,%5,%6,%7}, {%8,%9}, {%0,%1,%2,%3};"
        : "+f"(c[0]), "+f"(c[1]), "+f"(c[2]), "+f"(c[3])
        : "r"(a[0]), "r"(a[1]), "r"(a[2]), "r"(a[3]), "r"(b[0]), "r"(b[1]));
}
__device__ __forceinline__ float ex2f(float x) {
    float r; asm("ex2.approx.f32 %0, %1;" : "=f"(r) : "f"(x)); return r;
}
__device__ __forceinline__ unsigned packh2(float lo, float hi) {
    unsigned d;
    asm("cvt.rn.f16x2.f32 %0, %1, %2;" : "=r"(d) : "f"(hi), "f"(lo));
    return d;
}
// swizzled byte offset, 512B rows (256 fp16): chunk^(row&7) within 128B groups
__device__ __forceinline__ unsigned qoff(int row, int c) {
    unsigned ch = (unsigned)c >> 3;
    unsigned sw = (ch & ~7u) | ((ch ^ (unsigned)row) & 7u);
    return (unsigned)row * 512u + sw * 16u + ((unsigned)c & 7u) * 2u;
}
// swizzled byte offset, 128B rows (64 fp16)
__device__ __forceinline__ unsigned voff(int row, int c) {
    unsigned sw = (((unsigned)c >> 3) ^ (unsigned)row) & 7u;
    return (unsigned)row * 128u + sw * 16u + ((unsigned)c & 7u) * 2u;
}

// ---------------- prep: fold BN into W and bias ----------------
__global__ void prep_kernel(const float* __restrict__ Ws, const float* __restrict__ gam,
                            const float* __restrict__ bet, const float* __restrict__ mu,
                            const float* __restrict__ var) {
    int l = blockIdx.x;
    int tid = threadIdx.x;
    __shared__ float sc[C_];
    float s = gam[l*C_+tid] * rsqrtf(var[l*C_+tid] + 1e-5f);
    sc[tid] = s;
    g_bf[l*C_+tid] = bet[l*C_+tid] - mu[l*C_+tid]*s;
    __syncthreads();
    const float* Wl = Ws + l*C_*C_;
    float*       Wo = g_Wf + l*C_*C_;
    for (int t = tid; t < C_*C_; t += blockDim.x) Wo[t] = Wl[t] * sc[t >> 8];
}

// ---------------- fused convbn+relu GEMM (fp32 SIMT) ----------------
// out = relu(Wf @ in + bf) * oscale; output format selected by non-null pointer.
__global__ __launch_bounds__(256) void convbn_kernel(const float* __restrict__ in,
                                                     float* __restrict__ out32,
                                                     unsigned* __restrict__ outHL,
                                                     unsigned short* __restrict__ outH,
                                                     int layer, float oscale) {
    const float* Wf = g_Wf + layer*C_*C_;
    const float* bf = g_bf + layer*C_;
    const int n0 = blockIdx.x * 128;
    const int o0 = blockIdx.y * 64;
    const float* inb = in + (size_t)blockIdx.z * C_ * NTOK;

    __shared__ float As[16][64];
    __shared__ float Bs[16][128];

    const int tid = threadIdx.x;
    const int tx = tid & 15, ty = tid >> 4;

    float acc[4][8];
#pragma unroll
    for (int i = 0; i < 4; i++)
#pragma unroll
        for (int j = 0; j < 8; j++) acc[i][j] = 0.f;

    const int oA = tid >> 2, cA = (tid & 3) << 2;
    const int bRow = tid >> 5, bCol4 = (tid & 31);

    for (int c0 = 0; c0 < C_; c0 += 16) {
        float4 w  = *(const float4*)&Wf[(o0+oA)*C_ + c0 + cA];
        float4 b0 = *(const float4*)&inb[(size_t)(c0 + bRow    )*NTOK + n0 + bCol4*4];
        float4 b1 = *(const float4*)&inb[(size_t)(c0 + 8 + bRow)*NTOK + n0 + bCol4*4];
        __syncthreads();
        As[cA+0][oA] = w.x; As[cA+1][oA] = w.y; As[cA+2][oA] = w.z; As[cA+3][oA] = w.w;
        *(float4*)&Bs[bRow    ][bCol4*4] = b0;
        *(float4*)&Bs[8 + bRow][bCol4*4] = b1;
        __syncthreads();
#pragma unroll
        for (int k = 0; k < 16; k++) {
            float4 a = *(const float4*)&As[k][ty*4];
            float4 p = *(const float4*)&Bs[k][tx*8];
            float4 q = *(const float4*)&Bs[k][tx*8+4];
            float av[4] = {a.x, a.y, a.z, a.w};
            float bv[8] = {p.x, p.y, p.z, p.w, q.x, q.y, q.z, q.w};
#pragma unroll
            for (int i = 0; i < 4; i++)
#pragma unroll
                for (int j = 0; j < 8; j++)
                    acc[i][j] = fmaf(av[i], bv[j], acc[i][j]);
        }
    }

#pragma unroll
    for (int i = 0; i < 4; i++) {
        int o = o0 + ty*4 + i;
        float bias = bf[o];
        float vals[8];
#pragma unroll
        for (int j = 0; j < 8; j++) vals[j] = fmaxf(acc[i][j] + bias, 0.f) * oscale;
        size_t base = (size_t)o*NTOK + n0 + tx*8;
        if (outHL) {
            unsigned* ob = outHL + (size_t)blockIdx.z * C_ * NTOK;
            unsigned hl[8];
#pragma unroll
            for (int j = 0; j < 8; j++) hl[j] = splitpack(vals[j]);
            *(uint4*)&ob[base    ] = make_uint4(hl[0], hl[1], hl[2], hl[3]);
            *(uint4*)&ob[base + 4] = make_uint4(hl[4], hl[5], hl[6], hl[7]);
        } else if (outH) {
            unsigned short* ob = outH + (size_t)blockIdx.z * C_ * NTOK;
            unsigned p0 = packh2(vals[0], vals[1]);
            unsigned p1 = packh2(vals[2], vals[3]);
            unsigned p2 = packh2(vals[4], vals[5]);
            unsigned p3 = packh2(vals[6], vals[7]);
            *(uint4*)&ob[base] = make_uint4(p0, p1, p2, p3);
        } else {
            float* ob = out32 + (size_t)blockIdx.z * C_ * NTOK;
            *(float4*)&ob[base    ] = make_float4(vals[0], vals[1], vals[2], vals[3]);
            *(float4*)&ob[base + 4] = make_float4(vals[4], vals[5], vals[6], vals[7]);
        }
    }
}

// ---------------- warp-MMA flash attention ----------------
// smem: QH[128x256]f16 64KB | QL 64KB | KH[64x256] 32KB | KL 32KB; V[256x64] overlays KH.
#define SM_QH 0
#define SM_QL 65536
#define SM_KH 131072
#define SM_KL 163840
#define SM_V  131072
#define SMEM_ATTN 196608

__global__ void __launch_bounds__(256, 1) attn_mma(const unsigned* __restrict__ qhl,
                                                   const unsigned* __restrict__ khl,
                                                   const unsigned short* __restrict__ vh,
                                                   float* __restrict__ ctx) {
    extern __shared__ char smem[];
    const unsigned sb = smem_u32(smem);
    const int tid = threadIdx.x, wid = tid >> 5, lane = tid & 31;
    const int n0 = blockIdx.x * TM;
    const size_t boff = (size_t)blockIdx.y * C_ * NTOK;
    const unsigned* qb = qhl + boff;
    const unsigned* kb = khl + boff;
    const unsigned short* vb = vh + boff;
    float* cb = ctx + boff;

    // ---- fill Q (one-time, resident): 16384 c-pairs ----
    for (int it = 0; it < 64; it++) {
        int p = it*256 + tid;
        int row = p & 127;
        int c = (p >> 7) * 2;
        unsigned w0 = qb[(size_t)c*NTOK + n0 + row];
        unsigned w1 = qb[(size_t)(c+1)*NTOK + n0 + row];
        unsigned off = qoff(row, c);
        *(unsigned*)(smem + SM_QH + off) = (w0 & 0xFFFFu) | (w1 << 16);
        *(unsigned*)(smem + SM_QL + off) = (w0 >> 16) | (w1 & 0xFFFF0000u);
    }

    const int m0w = wid * 16;
    const int qr = lane >> 2, qc = lane & 3;
    // ldmatrix lane addressing
    const int a_row  = m0w + (lane & 7) + ((lane >> 3) & 1) * 8;
    const int a_coff = (lane >> 4) & 1;
    const int b_row8 = lane & 7;
    const int b_coff = (lane >> 3) & 1;

    float O[32][4];
#pragma unroll
    for (int i = 0; i < 32; i++) { O[i][0]=0.f; O[i][1]=0.f; O[i][2]=0.f; O[i][3]=0.f; }
    float mA = -1e30f, mB = -1e30f, lA = 0.f, lB = 0.f;

    for (int t = 0; t < NT; t++) {
        const int k0 = t * TN;
        __syncthreads();                      // prev PV done reading V (= KH region)
        // ---- fill K tile: 8192 c-pairs ----
        for (int it = 0; it < 32; it++) {
            int p = it*256 + tid;
            int row = p & 63;
            int c = (p >> 6) * 2;
            unsigned w0 = kb[(size_t)c*NTOK + k0 + row];
            unsigned w1 = kb[(size_t)(c+1)*NTOK + k0 + row];
            unsigned off = qoff(row, c);
            *(unsigned*)(smem + SM_KH + off) = (w0 & 0xFFFFu) | (w1 << 16);
            *(unsigned*)(smem + SM_KL + off) = (w0 >> 16) | (w1 & 0xFFFF0000u);
        }
        __syncthreads();

        // ---- S = Q Kᵀ (fp16 split: 3 MMA combos) ----
        float S[8][4];
#pragma unroll
        for (int i = 0; i < 8; i++) { S[i][0]=0.f; S[i][1]=0.f; S[i][2]=0.f; S[i][3]=0.f; }

#pragma unroll
        for (int kg = 0; kg < 16; kg++) {
            unsigned aH[4], aL[4];
            unsigned ach = 2u*kg + (unsigned)a_coff;
            unsigned aof = (unsigned)a_row*512u +
                           ((ach & ~7u) | ((ach ^ (unsigned)a_row) & 7u))*16u;
            ldsm4(aH, sb + SM_QH + aof);
            ldsm4(aL, sb + SM_QL + aof);
#pragma unroll
            for (int nt = 0; nt < 8; nt++) {
                unsigned bH[2], bL[2];
                int brow = nt*8 + b_row8;
                unsigned bch = 2u*kg + (unsigned)b_coff;
                unsigned bof = (unsigned)brow*512u +
                               ((bch & ~7u) | ((bch ^ (unsigned)brow) & 7u))*16u;
                ldsm2(bH, sb + SM_KH + bof);
                ldsm2(bL, sb + SM_KL + bof);
                mma16816(S[nt], aH, bH);
                mma16816(S[nt], aH, bL);
                mma16816(S[nt], aL, bH);
            }
        }

        // ---- online softmax (register-only; rows rA=qr, rB=qr+8 of strip) ----
        float mxA = -1e30f, mxB = -1e30f;
#pragma unroll
        for (int nt = 0; nt < 8; nt++) {
            mxA = fmaxf(mxA, fmaxf(S[nt][0], S[nt][1]));
            mxB = fmaxf(mxB, fmaxf(S[nt][2], S[nt][3]));
        }
        mxA = fmaxf(mxA, __shfl_xor_sync(0xffffffffu, mxA, 1));
        mxA = fmaxf(mxA, __shfl_xor_sync(0xffffffffu, mxA, 2));
        mxB = fmaxf(mxB, __shfl_xor_sync(0xffffffffu, mxB, 1));
        mxB = fmaxf(mxB, __shfl_xor_sync(0xffffffffu, mxB, 2));
        float mAn = fmaxf(mA, mxA), mBn = fmaxf(mB, mxB);
        float facA = ex2f(mA - mAn), facB = ex2f(mB - mBn);
        mA = mAn; mB = mBn;

        unsigned P[4][4];
        float sA = 0.f, sB = 0.f;
#pragma unroll
        for (int g = 0; g < 4; g++) {
#pragma unroll
            for (int h = 0; h < 2; h++) {
                int nt = 2*g + h;
                float e0 = ex2f(S[nt][0] - mAn), e1 = ex2f(S[nt][1] - mAn);
                float e2 = ex2f(S[nt][2] - mBn), e3 = ex2f(S[nt][3] - mBn);
                sA += e0 + e1; sB += e2 + e3;
                P[g][2*h]   = packh2(e0, e1);   // rows qr,   k pair
                P[g][2*h+1] = packh2(e2, e3);   // rows qr+8, k pair
            }
        }
        sA += __shfl_xor_sync(0xffffffffu, sA, 1);
        sA += __shfl_xor_sync(0xffffffffu, sA, 2);
        sB += __shfl_xor_sync(0xffffffffu, sB, 1);
        sB += __shfl_xor_sync(0xffffffffu, sB, 2);
        lA = lA * facA + sA;
        lB = lB * facB + sB;
#pragma unroll
        for (int i = 0; i < 32; i++) {
            O[i][0] *= facA; O[i][1] *= facA; O[i][2] *= facB; O[i][3] *= facB;
        }

        __syncthreads();                      // all warps done reading K
        // ---- fill V tile [256 c][64 j] (overlays KH) ----
        for (int it = 0; it < 32; it++) {
            int p = it*256 + tid;
            int j = (p & 31) * 2;
            int c = p >> 5;
            unsigned w = *(const unsigned*)&vb[(size_t)c*NTOK + k0 + j];
            *(unsigned*)(smem + SM_V + voff(c, j)) = w;
        }
        __syncthreads();

        // ---- O += P V ----
#pragma unroll
        for (int jg = 0; jg < 4; jg++) {
#pragma unroll
            for (int nt = 0; nt < 32; nt++) {
                unsigned bV[2];
                int vrow = nt*8 + b_row8;
                unsigned vch = 2u*jg + (unsigned)b_coff;
                unsigned vof = (unsigned)vrow*128u + ((vch ^ ((unsigned)vrow & 7u)) & 7u)*16u;
                ldsm2(bV, sb + SM_V + vof);
                mma16816(O[nt], P[jg], bV);
            }
        }
    }

    // ---- epilogue: normalize, store ctx[c][n] ----
    float iA = 1.f / lA, iB = 1.f / lB;
    const int gnA = n0 + m0w + qr;
    const int gnB = gnA + 8;
#pragma unroll
    for (int nt = 0; nt < 32; nt++) {
        int c = nt*8 + qc*2;
        cb[(size_t)c*NTOK + gnA]       = O[nt][0] * iA;
        cb[(size_t)(c+1)*NTOK + gnA]   = O[nt][1] * iA;
        cb[(size_t)c*NTOK + gnB]       = O[nt][2] * iB;
        cb[(size_t)(c+1)*NTOK + gnB]   = O[nt][3] * iB;
    }
}

// ---------------- launch ----------------
extern "C" void kernel_launch(void* const* d_in, const int* in_sizes, int n_in,
                              void* d_out, int out_size) {
    const float* x   = (const float*)d_in[0];
    const float* fk  = (const float*)d_in[1];
    const float* Ws  = (const float*)d_in[2];
    const float* gam = (const float*)d_in[3];
    const float* bet = (const float*)d_in[4];
    const float* mu  = (const float*)d_in[5];
    const float* var = (const float*)d_in[6];
    float* out = (float*)d_out;

    float *p_t, *p_ctx;
    unsigned *p_qhl, *p_khl;
    unsigned short *p_vh;
    cudaGetSymbolAddress((void**)&p_t,   g_t);
    cudaGetSymbolAddress((void**)&p_ctx, g_ctx);
    cudaGetSymbolAddress((void**)&p_qhl, g_qhl);
    cudaGetSymbolAddress((void**)&p_khl, g_khl);
    cudaGetSymbolAddress((void**)&p_vh,  g_vh);

    cudaFuncSetAttribute(attn_mma, cudaFuncAttributeMaxDynamicSharedMemorySize, SMEM_ATTN);

    prep_kernel<<<L_, 256>>>(Ws, gam, bet, mu, var);

    dim3 cgrid(NTOK/128, C_/64, B_);
    convbn_kernel<<<cgrid, 256>>>(x,   p_t, nullptr, nullptr, 0, 1.0f);      // psi1
    convbn_kernel<<<cgrid, 256>>>(p_t, nullptr, p_qhl, nullptr, 1, LOG2E);   // psi2 -> q (log2e folded)
    convbn_kernel<<<cgrid, 256>>>(fk,  p_t, nullptr, nullptr, 2, 1.0f);      // phi1
    convbn_kernel<<<cgrid, 256>>>(p_t, nullptr, p_khl, nullptr, 3, 1.0f);    // phi2 -> k
    convbn_kernel<<<cgrid, 256>>>(fk,  nullptr, nullptr, p_vh, 4, 1.0f);     // f_down -> v

    attn_mma<<<dim3(NQT, B_), 256, SMEM_ATTN>>>(p_qhl, p_khl, p_vh, p_ctx);

    convbn_kernel<<<cgrid, 256>>>(p_ctx, out, nullptr, nullptr, 5, 1.0f);    // f_up -> output
}

// round 8
// speedup vs baseline: 6.1197x; 1.2190x over previous
#include <cuda_runtime.h>
#include <cuda_fp16.h>
#include <math.h>

#define B_    2
#define C_    256
#define NTOK  9216
#define L_    6
#define TM    128
#define TN    64
#define NT    (NTOK/TN)     // 144
#define NQT   (NTOK/TM)     // 72
#define LOG2E 1.4426950408889634f

// ---------------- scratch ----------------
__device__ unsigned short g_Wh[L_*C_*C_], g_Wl[L_*C_*C_];
__device__ float          g_bf[L_*C_];
__device__ unsigned short g_t1h[B_*C_*NTOK], g_t1l[B_*C_*NTOK];
__device__ unsigned short g_qh [B_*C_*NTOK], g_ql [B_*C_*NTOK];
__device__ unsigned short g_kh [B_*C_*NTOK], g_kl [B_*C_*NTOK];
__device__ unsigned short g_vh [B_*C_*NTOK];
__device__ unsigned short g_ch [B_*C_*NTOK], g_cl [B_*C_*NTOK];

// ---------------- helpers ----------------
__device__ __forceinline__ unsigned smem_u32(const void* p) {
    unsigned a;
    asm("{ .reg .u64 t; cvta.to.shared.u64 t, %1; cvt.u32.u64 %0, t; }" : "=r"(a) : "l"(p));
    return a;
}
__device__ __forceinline__ void cpa16(unsigned dst, const void* src) {
    asm volatile("cp.async.cg.shared.global [%0], [%1], 16;" :: "r"(dst), "l"(src));
}
#define CP_COMMIT() asm volatile("cp.async.commit_group;" ::: "memory")
#define CP_WAIT0()  asm volatile("cp.async.wait_group 0;" ::: "memory")
#define CP_WAIT1()  asm volatile("cp.async.wait_group 1;" ::: "memory")

__device__ __forceinline__ void ldsm4(unsigned* r, unsigned a) {
    asm volatile("ldmatrix.sync.aligned.m8n8.x4.shared.b16 {%0,%1,%2,%3}, [%4];"
        : "=r"(r[0]), "=r"(r[1]), "=r"(r[2]), "=r"(r[3]) : "r"(a));
}
__device__ __forceinline__ void ldsm4t(unsigned* r, unsigned a) {
    asm volatile("ldmatrix.sync.aligned.m8n8.x4.trans.shared.b16 {%0,%1,%2,%3}, [%4];"
        : "=r"(r[0]), "=r"(r[1]), "=r"(r[2]), "=r"(r[3]) : "r"(a));
}
__device__ __forceinline__ void ldsm2(unsigned* r, unsigned a) {
    asm volatile("ldmatrix.sync.aligned.m8n8.x2.shared.b16 {%0,%1}, [%2];"
        : "=r"(r[0]), "=r"(r[1]) : "r"(a));
}
__device__ __forceinline__ void ldsm2t(unsigned* r, unsigned a) {
    asm volatile("ldmatrix.sync.aligned.m8n8.x2.trans.shared.b16 {%0,%1}, [%2];"
        : "=r"(r[0]), "=r"(r[1]) : "r"(a));
}
__device__ __forceinline__ void mma16816(float* c, const unsigned* a, const unsigned* b) {
    asm volatile("mma.sync.aligned.m16n8k16.row.col.f32.f16.f16.f32 "
        "{%0,%1,%2,%3}, {%4,%5,%6,%7}, {%8,%9}, {%0,%1,%2,%3};"
        : "+f"(c[0]), "+f"(c[1]), "+f"(c[2]), "+f"(c[3])
        : "r"(a[0]), "r"(a[1]), "r"(a[2]), "r"(a[3]), "r"(b[0]), "r"(b[1]));
}
__device__ __forceinline__ float ex2f(float x) {
    float r; asm("ex2.approx.f32 %0, %1;" : "=f"(r) : "f"(x)); return r;
}
__device__ __forceinline__ unsigned packh2(float lo, float hi) {
    unsigned d;
    asm("cvt.rn.f16x2.f32 %0, %1, %2;" : "=r"(d) : "f"(hi), "f"(lo));
    return d;
}
__device__ __forceinline__ unsigned pack2us(unsigned short a, unsigned short b) {
    return (unsigned)a | ((unsigned)b << 16);
}

// ---------------- prep: fold BN, split W into fp16 planes ----------------
__global__ void prep_kernel(const float* __restrict__ Ws, const float* __restrict__ gam,
                            const float* __restrict__ bet, const float* __restrict__ mu,
                            const float* __restrict__ var) {
    int l = blockIdx.x, tid = threadIdx.x;
    __shared__ float sc[C_];
    float s = gam[l*C_+tid] * rsqrtf(var[l*C_+tid] + 1e-5f);
    sc[tid] = s;
    g_bf[l*C_+tid] = bet[l*C_+tid] - mu[l*C_+tid]*s;
    __syncthreads();
    const float* Wl = Ws + l*C_*C_;
    for (int t = tid; t < C_*C_; t += blockDim.x) {
        float wf = Wl[t] * sc[t >> 8];
        __half h = __float2half_rn(wf);
        __half lo = __float2half_rn(wf - __half2float(h));
        g_Wh[l*C_*C_ + t] = __half_as_ushort(h);
        g_Wl[l*C_*C_ + t] = __half_as_ushort(lo);
    }
}

// ---------------- HMMA convbn+relu ----------------
// out[o][n] = relu(sum_c W[o][c] in[c][n] + b[o]) * oscale
// CTA tile 128o x 256n, k-chunks of 64. 8 warps = 4(o) x 2(n), warp 32o x 128n.
// IN_MODE: 0 = fp32 global [c][n] (manual split); 1 = fp16 hi/lo planes (cp.async)
// OUT_MODE: 0 = split planes; 1 = fp16 plane; 2 = fp32
#define CV_WH  0
#define CV_WL  16384
#define CV_INH 32768
#define CV_INL 65536
#define CV_SMEM 98304

template<int IN_MODE, int OUT_MODE>
__global__ void __launch_bounds__(256, 1) conv_hmma(
    const float* __restrict__ in32,
    const unsigned short* __restrict__ inh, const unsigned short* __restrict__ inl,
    float* __restrict__ o32, unsigned short* __restrict__ oh, unsigned short* __restrict__ ol,
    int layer, float oscale)
{
    extern __shared__ char cs[];
    const unsigned sb = smem_u32(cs);
    const int tid = threadIdx.x, wid = tid >> 5, lane = tid & 31;
    const int n0 = blockIdx.x * 256;
    const int o0 = blockIdx.y * 128;
    const int bz = blockIdx.z;
    const int warp_o = wid & 3, warp_n = wid >> 2;
    const int qr = lane >> 2, qc = lane & 3;

    float acc[2][16][4];
#pragma unroll
    for (int mf = 0; mf < 2; mf++)
#pragma unroll
        for (int nf = 0; nf < 16; nf++)
#pragma unroll
            for (int u = 0; u < 4; u++) acc[mf][nf][u] = 0.f;

    const unsigned short* gWh = g_Wh + (size_t)layer*C_*C_;
    const unsigned short* gWl = g_Wl + (size_t)layer*C_*C_;

    for (int kc = 0; kc < 4; kc++) {
        __syncthreads();
        const int c0k = kc * 64;
        // --- W planes via cp.async ---
#pragma unroll
        for (int it = 0; it < 4; it++) {
            int idx = it*256 + tid;
            int row = idx >> 3, ch = idx & 7;
            size_t g = (size_t)(o0 + row)*C_ + c0k + ch*8;
            unsigned d = sb + CV_WH + (unsigned)row*128 + (unsigned)((ch ^ (row & 7)) & 7)*16;
            cpa16(d, gWh + g);
            cpa16(d + (CV_WL - CV_WH), gWl + g);
        }
        if (IN_MODE == 1) {
#pragma unroll
            for (int it = 0; it < 8; it++) {
                int idx = it*256 + tid;
                int row = idx >> 5, ch = idx & 31;
                size_t g = (size_t)(bz*C_ + c0k + row)*NTOK + n0 + ch*8;
                unsigned d = sb + CV_INH + (unsigned)row*512 +
                             (unsigned)((ch & ~7) | ((ch ^ row) & 7))*16;
                cpa16(d, inh + g);
                cpa16(d + (CV_INL - CV_INH), inl + g);
            }
            CP_COMMIT(); CP_WAIT0();
        } else {
            CP_COMMIT();
#pragma unroll
            for (int it = 0; it < 16; it++) {
                int idx = it*256 + tid;
                int row = idx >> 6;
                int n = (idx & 63) * 4;
                float4 w = *(const float4*)&in32[(size_t)(bz*C_ + c0k + row)*NTOK + n0 + n];
                __half h0 = __float2half_rn(w.x), h1 = __float2half_rn(w.y);
                __half h2 = __float2half_rn(w.z), h3 = __float2half_rn(w.w);
                __half l0 = __float2half_rn(w.x - __half2float(h0));
                __half l1 = __float2half_rn(w.y - __half2float(h1));
                __half l2 = __float2half_rn(w.z - __half2float(h2));
                __half l3 = __float2half_rn(w.w - __half2float(h3));
                int ch = n >> 3;
                unsigned off = (unsigned)row*512 + (unsigned)((ch & ~7) | ((ch ^ row) & 7))*16 + (unsigned)(n & 7)*2;
                *(unsigned*)(cs + CV_INH + off)     = pack2us(__half_as_ushort(h0), __half_as_ushort(h1));
                *(unsigned*)(cs + CV_INH + off + 4) = pack2us(__half_as_ushort(h2), __half_as_ushort(h3));
                *(unsigned*)(cs + CV_INL + off)     = pack2us(__half_as_ushort(l0), __half_as_ushort(l1));
                *(unsigned*)(cs + CV_INL + off + 4) = pack2us(__half_as_ushort(l2), __half_as_ushort(l3));
            }
            CP_WAIT0();
        }
        __syncthreads();

        // --- MMA on this k-chunk ---
#pragma unroll
        for (int kg = 0; kg < 4; kg++) {
            unsigned aH[2][4], aL[2][4];
#pragma unroll
            for (int mf = 0; mf < 2; mf++) {
                int mrow = warp_o*32 + mf*16 + (lane & 15);
                int ch = kg*2 + (lane >> 4);
                unsigned aof = (unsigned)mrow*128 + (unsigned)((ch ^ (mrow & 7)) & 7)*16;
                ldsm4(aH[mf], sb + CV_WH + aof);
                ldsm4(aL[mf], sb + CV_WL + aof);
            }
            int krB = kg*16 + (lane & 15);
#pragma unroll
            for (int nf = 0; nf < 16; nf++) {
                unsigned bH[2], bL[2];
                int nch = warp_n*16 + nf;
                unsigned bof = (unsigned)krB*512 +
                               (unsigned)((nch & ~7) | ((nch ^ (krB & 7)) & 7))*16;
                ldsm2t(bH, sb + CV_INH + bof);
                ldsm2t(bL, sb + CV_INL + bof);
#pragma unroll
                for (int mf = 0; mf < 2; mf++) {
                    mma16816(acc[mf][nf], aH[mf], bH);
                    mma16816(acc[mf][nf], aH[mf], bL);
                    mma16816(acc[mf][nf], aL[mf], bH);
                }
            }
        }
    }

    // --- epilogue ---
#pragma unroll
    for (int mf = 0; mf < 2; mf++) {
        int oA = o0 + warp_o*32 + mf*16 + qr;
        int oB = oA + 8;
        float bA = g_bf[layer*C_ + oA], bB = g_bf[layer*C_ + oB];
#pragma unroll
        for (int nf = 0; nf < 16; nf++) {
            int n = n0 + warp_n*128 + nf*8 + qc*2;
            float v0 = fmaxf(acc[mf][nf][0] + bA, 0.f) * oscale;
            float v1 = fmaxf(acc[mf][nf][1] + bA, 0.f) * oscale;
            float v2 = fmaxf(acc[mf][nf][2] + bB, 0.f) * oscale;
            float v3 = fmaxf(acc[mf][nf][3] + bB, 0.f) * oscale;
            size_t iA = (size_t)oA*NTOK + n, iB = (size_t)oB*NTOK + n;
            if (OUT_MODE == 0) {
                unsigned short* ohp = oh + (size_t)bz*C_*NTOK;
                unsigned short* olp = ol + (size_t)bz*C_*NTOK;
                __half h0 = __float2half_rn(v0), h1 = __float2half_rn(v1);
                __half h2 = __float2half_rn(v2), h3 = __float2half_rn(v3);
                *(unsigned*)&ohp[iA] = pack2us(__half_as_ushort(h0), __half_as_ushort(h1));
                *(unsigned*)&ohp[iB] = pack2us(__half_as_ushort(h2), __half_as_ushort(h3));
                __half e0 = __float2half_rn(v0 - __half2float(h0));
                __half e1 = __float2half_rn(v1 - __half2float(h1));
                __half e2 = __float2half_rn(v2 - __half2float(h2));
                __half e3 = __float2half_rn(v3 - __half2float(h3));
                *(unsigned*)&olp[iA] = pack2us(__half_as_ushort(e0), __half_as_ushort(e1));
                *(unsigned*)&olp[iB] = pack2us(__half_as_ushort(e2), __half_as_ushort(e3));
            } else if (OUT_MODE == 1) {
                unsigned short* ohp = oh + (size_t)bz*C_*NTOK;
                *(unsigned*)&ohp[iA] = packh2(v0, v1);
                *(unsigned*)&ohp[iB] = packh2(v2, v3);
            } else {
                float* op = o32 + (size_t)bz*C_*NTOK;
                *(float2*)&op[iA] = make_float2(v0, v1);
                *(float2*)&op[iB] = make_float2(v2, v3);
            }
        }
    }
}

// ---------------- pipelined HMMA flash attention ----------------
// smem: QH[256c][128n] 64K | QL 64K | KH[256c][64j] 32K | KL 32K | V[256c][64j] 32K
#define SM_QH 0
#define SM_QL 65536
#define SM_KH 131072
#define SM_KL 163840
#define SM_V  196608
#define SMEM_ATTN 229376

__global__ void __launch_bounds__(256, 1) attn_mma(
    const unsigned short* __restrict__ qhg, const unsigned short* __restrict__ qlg,
    const unsigned short* __restrict__ khg, const unsigned short* __restrict__ klg,
    const unsigned short* __restrict__ vhg,
    unsigned short* __restrict__ chg, unsigned short* __restrict__ clg)
{
    extern __shared__ char smem[];
    const unsigned sb = smem_u32(smem);
    const int tid = threadIdx.x, wid = tid >> 5, lane = tid & 31;
    const int n0 = blockIdx.x * TM;
    const size_t boff = (size_t)blockIdx.y * C_ * NTOK;
    const unsigned short* qh = qhg + boff;
    const unsigned short* ql = qlg + boff;
    const unsigned short* kh = khg + boff;
    const unsigned short* kl = klg + boff;
    const unsigned short* vh = vhg + boff;

    const int m0w = wid * 16;
    const int qr = lane >> 2, qc = lane & 3;

    // ---- prologue: issue Q + K(0) (group 0), V(0) (group 1) ----
#pragma unroll
    for (int it = 0; it < 16; it++) {           // Q: 256 rows x 16 chunks, 2 planes
        int idx = it*256 + tid;
        int row = idx >> 4, ch = idx & 15;
        size_t g = (size_t)row*NTOK + n0 + ch*8;
        unsigned d = sb + SM_QH + (unsigned)row*256 +
                     (unsigned)((ch & ~7) | ((ch ^ row) & 7))*16;
        cpa16(d, qh + g);
        cpa16(d + (SM_QL - SM_QH), ql + g);
    }
#pragma unroll
    for (int it = 0; it < 8; it++) {            // K(0): 256 rows x 8 chunks, 2 planes
        int idx = it*256 + tid;
        int row = idx >> 3, ch = idx & 7;
        size_t g = (size_t)row*NTOK + 0 + ch*8;
        unsigned d = sb + SM_KH + (unsigned)row*128 + (unsigned)((ch ^ (row & 7)) & 7)*16;
        cpa16(d, kh + g);
        cpa16(d + (SM_KL - SM_KH), kl + g);
    }
    CP_COMMIT();
#pragma unroll
    for (int it = 0; it < 8; it++) {            // V(0)
        int idx = it*256 + tid;
        int row = idx >> 3, ch = idx & 7;
        unsigned d = sb + SM_V + (unsigned)row*128 + (unsigned)((ch ^ (row & 7)) & 7)*16;
        cpa16(d, vh + (size_t)row*NTOK + 0 + ch*8);
    }
    CP_COMMIT();

    float O[32][4];
#pragma unroll
    for (int i = 0; i < 32; i++) { O[i][0]=0.f; O[i][1]=0.f; O[i][2]=0.f; O[i][3]=0.f; }
    float mA = -1e30f, mB = -1e30f, lA = 0.f, lB = 0.f;

    for (int t = 0; t < NT; t++) {
        CP_WAIT1();                              // K(t) [and Q at t=0] ready
        __syncthreads();

        // ---- S = Q Kᵀ : A trans from QH/QL [c][n], B trans from KH/KL [c][j] ----
        float S[8][4];
#pragma unroll
        for (int i = 0; i < 8; i++) { S[i][0]=0.f; S[i][1]=0.f; S[i][2]=0.f; S[i][3]=0.f; }
#pragma unroll
        for (int kg = 0; kg < 16; kg++) {
            unsigned aH[4], aL[4];
            int krA = kg*16 + ((lane >> 4) & 1)*8 + (lane & 7);
            int mch = wid*2 + ((lane >> 3) & 1);
            unsigned aof = (unsigned)krA*256 +
                           (unsigned)((mch & ~7) | ((mch ^ (krA & 7)) & 7))*16;
            ldsm4t(aH, sb + SM_QH + aof);
            ldsm4t(aL, sb + SM_QL + aof);
            int krB = kg*16 + (lane & 15);
#pragma unroll
            for (int nt = 0; nt < 8; nt++) {
                unsigned bH[2], bL[2];
                unsigned bof = (unsigned)krB*128 + (unsigned)((nt ^ (krB & 7)) & 7)*16;
                ldsm2t(bH, sb + SM_KH + bof);
                ldsm2t(bL, sb + SM_KL + bof);
                mma16816(S[nt], aH, bH);
                mma16816(S[nt], aH, bL);
                mma16816(S[nt], aL, bH);
            }
        }
        __syncthreads();                         // all warps done reading K

        if (t + 1 < NT) {                        // prefetch K(t+1): overlaps softmax+PV
            const int k1 = (t + 1) * TN;
#pragma unroll
            for (int it = 0; it < 8; it++) {
                int idx = it*256 + tid;
                int row = idx >> 3, ch = idx & 7;
                size_t g = (size_t)row*NTOK + k1 + ch*8;
                unsigned d = sb + SM_KH + (unsigned)row*128 + (unsigned)((ch ^ (row & 7)) & 7)*16;
                cpa16(d, kh + g);
                cpa16(d + (SM_KL - SM_KH), kl + g);
            }
            CP_COMMIT();
        }

        // ---- online softmax (registers only) ----
        float mxA = -1e30f, mxB = -1e30f;
#pragma unroll
        for (int nt = 0; nt < 8; nt++) {
            mxA = fmaxf(mxA, fmaxf(S[nt][0], S[nt][1]));
            mxB = fmaxf(mxB, fmaxf(S[nt][2], S[nt][3]));
        }
        mxA = fmaxf(mxA, __shfl_xor_sync(0xffffffffu, mxA, 1));
        mxA = fmaxf(mxA, __shfl_xor_sync(0xffffffffu, mxA, 2));
        mxB = fmaxf(mxB, __shfl_xor_sync(0xffffffffu, mxB, 1));
        mxB = fmaxf(mxB, __shfl_xor_sync(0xffffffffu, mxB, 2));
        float mAn = fmaxf(mA, mxA), mBn = fmaxf(mB, mxB);
        float facA = ex2f(mA - mAn), facB = ex2f(mB - mBn);
        mA = mAn; mB = mBn;

        unsigned P[4][4];
        float sA = 0.f, sB = 0.f;
#pragma unroll
        for (int g = 0; g < 4; g++) {
#pragma unroll
            for (int h = 0; h < 2; h++) {
                int nt = 2*g + h;
                float e0 = ex2f(S[nt][0] - mAn), e1 = ex2f(S[nt][1] - mAn);
                float e2 = ex2f(S[nt][2] - mBn), e3 = ex2f(S[nt][3] - mBn);
                sA += e0 + e1; sB += e2 + e3;
                P[g][2*h]   = packh2(e0, e1);
                P[g][2*h+1] = packh2(e2, e3);
            }
        }
        sA += __shfl_xor_sync(0xffffffffu, sA, 1);
        sA += __shfl_xor_sync(0xffffffffu, sA, 2);
        sB += __shfl_xor_sync(0xffffffffu, sB, 1);
        sB += __shfl_xor_sync(0xffffffffu, sB, 2);
        lA = lA * facA + sA;
        lB = lB * facB + sB;
#pragma unroll
        for (int i = 0; i < 32; i++) {
            O[i][0] *= facA; O[i][1] *= facA; O[i][2] *= facB; O[i][3] *= facB;
        }

        if (t + 1 < NT) { CP_WAIT1(); } else { CP_WAIT0(); }   // V(t) ready
        __syncthreads();

        // ---- O += P V ----
#pragma unroll
        for (int jg = 0; jg < 4; jg++) {
#pragma unroll
            for (int nt = 0; nt < 32; nt++) {
                unsigned bV[2];
                int vrow = nt*8 + (lane & 7);
                int vch = 2*jg + ((lane >> 3) & 1);
                unsigned vof = (unsigned)vrow*128 + (unsigned)((vch ^ (vrow & 7)) & 7)*16;
                ldsm2(bV, sb + SM_V + vof);
                mma16816(O[nt], P[jg], bV);
            }
        }
        __syncthreads();                         // all warps done reading V

        if (t + 1 < NT) {                        // prefetch V(t+1): overlaps next QK
            const int k1 = (t + 1) * TN;
#pragma unroll
            for (int it = 0; it < 8; it++) {
                int idx = it*256 + tid;
                int row = idx >> 3, ch = idx & 7;
                unsigned d = sb + SM_V + (unsigned)row*128 + (unsigned)((ch ^ (row & 7)) & 7)*16;
                cpa16(d, vh + (size_t)row*NTOK + k1 + ch*8);
            }
            CP_COMMIT();
        }
    }

    // ---- epilogue: stage split O planes in (retired) Q smem, copy out coalesced ----
    float iA = 1.f / lA, iB = 1.f / lB;
    const int nlA = m0w + qr, nlB = nlA + 8;
    __syncthreads();
#pragma unroll
    for (int nt = 0; nt < 32; nt++) {
        int c = nt*8 + qc*2;
        float v0 = O[nt][0]*iA, v1 = O[nt][1]*iA, v2 = O[nt][2]*iB, v3 = O[nt][3]*iB;
        __half h0 = __float2half_rn(v0), h1 = __float2half_rn(v1);
        __half h2 = __float2half_rn(v2), h3 = __float2half_rn(v3);
        __half e0 = __float2half_rn(v0 - __half2float(h0));
        __half e1 = __float2half_rn(v1 - __half2float(h1));
        __half e2 = __float2half_rn(v2 - __half2float(h2));
        __half e3 = __float2half_rn(v3 - __half2float(h3));
        *(unsigned short*)(smem + SM_QH + (c  )*256 + nlA*2) = __half_as_ushort(h0);
        *(unsigned short*)(smem + SM_QH + (c+1)*256 + nlA*2) = __half_as_ushort(h1);
        *(unsigned short*)(smem + SM_QH + (c  )*256 + nlB*2) = __half_as_ushort(h2);
        *(unsigned short*)(smem + SM_QH + (c+1)*256 + nlB*2) = __half_as_ushort(h3);
        *(unsigned short*)(smem + SM_QL + (c  )*256 + nlA*2) = __half_as_ushort(e0);
        *(unsigned short*)(smem + SM_QL + (c+1)*256 + nlA*2) = __half_as_ushort(e1);
        *(unsigned short*)(smem + SM_QL + (c  )*256 + nlB*2) = __half_as_ushort(e2);
        *(unsigned short*)(smem + SM_QL + (c+1)*256 + nlB*2) = __half_as_ushort(e3);
    }
    __syncthreads();
    unsigned short* cho = chg + boff;
    unsigned short* clo = clg + boff;
#pragma unroll
    for (int it = 0; it < 16; it++) {
        int idx = it*256 + tid;
        int row = idx >> 4, ch = idx & 15;
        uint4 vH = *(uint4*)(smem + SM_QH + row*256 + ch*16);
        uint4 vL = *(uint4*)(smem + SM_QL + row*256 + ch*16);
        *(uint4*)&cho[(size_t)row*NTOK + n0 + ch*8] = vH;
        *(uint4*)&clo[(size_t)row*NTOK + n0 + ch*8] = vL;
    }
}

// ---------------- launch ----------------
extern "C" void kernel_launch(void* const* d_in, const int* in_sizes, int n_in,
                              void* d_out, int out_size) {
    const float* x   = (const float*)d_in[0];
    const float* fk  = (const float*)d_in[1];
    const float* Ws  = (const float*)d_in[2];
    const float* gam = (const float*)d_in[3];
    const float* bet = (const float*)d_in[4];
    const float* mu  = (const float*)d_in[5];
    const float* var = (const float*)d_in[6];
    float* out = (float*)d_out;

    unsigned short *t1h, *t1l, *qh, *ql, *kh, *kl, *vh, *ch, *cl;
    cudaGetSymbolAddress((void**)&t1h, g_t1h);
    cudaGetSymbolAddress((void**)&t1l, g_t1l);
    cudaGetSymbolAddress((void**)&qh,  g_qh);
    cudaGetSymbolAddress((void**)&ql,  g_ql);
    cudaGetSymbolAddress((void**)&kh,  g_kh);
    cudaGetSymbolAddress((void**)&kl,  g_kl);
    cudaGetSymbolAddress((void**)&vh,  g_vh);
    cudaGetSymbolAddress((void**)&ch,  g_ch);
    cudaGetSymbolAddress((void**)&cl,  g_cl);

    cudaFuncSetAttribute(conv_hmma<0,0>, cudaFuncAttributeMaxDynamicSharedMemorySize, CV_SMEM);
    cudaFuncSetAttribute(conv_hmma<1,0>, cudaFuncAttributeMaxDynamicSharedMemorySize, CV_SMEM);
    cudaFuncSetAttribute(conv_hmma<0,1>, cudaFuncAttributeMaxDynamicSharedMemorySize, CV_SMEM);
    cudaFuncSetAttribute(conv_hmma<1,2>, cudaFuncAttributeMaxDynamicSharedMemorySize, CV_SMEM);
    cudaFuncSetAttribute(attn_mma, cudaFuncAttributeMaxDynamicSharedMemorySize, SMEM_ATTN);

    prep_kernel<<<L_, 256>>>(Ws, gam, bet, mu, var);

    dim3 cgrid(NTOK/256, C_/128, B_);
    conv_hmma<0,0><<<cgrid, 256, CV_SMEM>>>(x,  nullptr, nullptr, nullptr, t1h, t1l, 0, 1.0f);
    conv_hmma<1,0><<<cgrid, 256, CV_SMEM>>>(nullptr, t1h, t1l, nullptr, qh, ql, 1, LOG2E);
    conv_hmma<0,0><<<cgrid, 256, CV_SMEM>>>(fk, nullptr, nullptr, nullptr, t1h, t1l, 2, 1.0f);
    conv_hmma<1,0><<<cgrid, 256, CV_SMEM>>>(nullptr, t1h, t1l, nullptr, kh, kl, 3, 1.0f);
    conv_hmma<0,1><<<cgrid, 256, CV_SMEM>>>(fk, nullptr, nullptr, nullptr, vh, nullptr, 4, 1.0f);

    attn_mma<<<dim3(NQT, B_), 256, SMEM_ATTN>>>(qh, ql, kh, kl, vh, ch, cl);

    conv_hmma<1,2><<<cgrid, 256, CV_SMEM>>>(nullptr, ch, cl, out, nullptr, nullptr, 5, 1.0f);
}

// round 10
// speedup vs baseline: 9.7668x; 1.5960x over previous
#include <cuda_runtime.h>
#include <cuda_fp16.h>
#include <math.h>

#define B_    2
#define C_    256
#define NTOK  9216
#define L_    6
#define TM    128
#define TN    64
#define NT    (NTOK/TN)     // 144
#define NQT   (NTOK/TM)     // 72
#define LOG2E 1.4426950408889634f

// ---------------- scratch ----------------
__device__ unsigned short g_Wh[L_*C_*C_], g_Wl[L_*C_*C_];
__device__ float          g_bf[L_*C_];
__device__ unsigned short g_t1h[B_*C_*NTOK], g_t1l[B_*C_*NTOK];
__device__ unsigned short g_qh [B_*C_*NTOK], g_ql [B_*C_*NTOK];
__device__ unsigned short g_kh [B_*C_*NTOK], g_kl [B_*C_*NTOK];
__device__ unsigned short g_vh [B_*C_*NTOK];
__device__ unsigned short g_ch [B_*C_*NTOK], g_cl [B_*C_*NTOK];

// ---------------- helpers ----------------
__device__ __forceinline__ unsigned smem_u32(const void* p) {
    unsigned a;
    asm("{ .reg .u64 t; cvta.to.shared.u64 t, %1; cvt.u32.u64 %0, t; }" : "=r"(a) : "l"(p));
    return a;
}
__device__ __forceinline__ void cpa16(unsigned dst, const void* src) {
    asm volatile("cp.async.cg.shared.global [%0], [%1], 16;" :: "r"(dst), "l"(src));
}
#define CP_COMMIT() asm volatile("cp.async.commit_group;" ::: "memory")
#define CP_WAIT0()  asm volatile("cp.async.wait_group 0;" ::: "memory")
#define CP_WAIT1()  asm volatile("cp.async.wait_group 1;" ::: "memory")

__device__ __forceinline__ void ldsm4(unsigned* r, unsigned a) {
    asm volatile("ldmatrix.sync.aligned.m8n8.x4.shared.b16 {%0,%1,%2,%3}, [%4];"
        : "=r"(r[0]), "=r"(r[1]), "=r"(r[2]), "=r"(r[3]) : "r"(a));
}
__device__ __forceinline__ void ldsm4t(unsigned* r, unsigned a) {
    asm volatile("ldmatrix.sync.aligned.m8n8.x4.trans.shared.b16 {%0,%1,%2,%3}, [%4];"
        : "=r"(r[0]), "=r"(r[1]), "=r"(r[2]), "=r"(r[3]) : "r"(a));
}
__device__ __forceinline__ void mma16816(float* c, const unsigned* a, const unsigned* b) {
    asm volatile("mma.sync.aligned.m16n8k16.row.col.f32.f16.f16.f32 "
        "{%0,%1,%2,%3}, {%4,%5,%6,%7}, {%8,%9}, {%0,%1,%2,%3};"
        : "+f"(c[0]), "+f"(c[1]), "+f"(c[2]), "+f"(c[3])
        : "r"(a[0]), "r"(a[1]), "r"(a[2]), "r"(a[3]), "r"(b[0]), "r"(b[1]));
}
__device__ __forceinline__ float ex2f(float x) {
    float r; asm("ex2.approx.f32 %0, %1;" : "=f"(r) : "f"(x)); return r;
}
__device__ __forceinline__ unsigned packh2(float lo, float hi) {
    unsigned d;
    asm("cvt.rn.f16x2.f32 %0, %1, %2;" : "=r"(d) : "f"(hi), "f"(lo));
    return d;
}
__device__ __forceinline__ unsigned pack2us(unsigned short a, unsigned short b) {
    return (unsigned)a | ((unsigned)b << 16);
}

// ---------------- prep: fold BN, split W into fp16 planes ----------------
__global__ void prep_kernel(const float* __restrict__ Ws, const float* __restrict__ gam,
                            const float* __restrict__ bet, const float* __restrict__ mu,
                            const float* __restrict__ var) {
    int l = blockIdx.x, tid = threadIdx.x;
    __shared__ float sc[C_];
    float s = gam[l*C_+tid] * rsqrtf(var[l*C_+tid] + 1e-5f);
    sc[tid] = s;
    g_bf[l*C_+tid] = bet[l*C_+tid] - mu[l*C_+tid]*s;
    __syncthreads();
    const float* Wl = Ws + l*C_*C_;
    for (int t = tid; t < C_*C_; t += blockDim.x) {
        float wf = Wl[t] * sc[t >> 8];
        __half h = __float2half_rn(wf);
        __half lo = __float2half_rn(wf - __half2float(h));
        g_Wh[l*C_*C_ + t] = __half_as_ushort(h);
        g_Wl[l*C_*C_ + t] = __half_as_ushort(lo);
    }
}

// ---------------- HMMA convbn+relu ----------------
// CTA tile 128o x 128n, 2 CTAs/SM. 8 warps = 4(o) x 2(n); warp 32o x 64n.
// IN_MODE: 0 = fp32 global (manual split); 1 = fp16 hi/lo planes (cp.async)
// OUT_MODE: 0 = split planes; 1 = fp16 plane; 2 = fp32
#define CV_WH  0
#define CV_WL  16384
#define CV_INH 32768
#define CV_INL 49152
#define CV_SMEM 65536

template<int IN_MODE, int OUT_MODE>
__global__ void __launch_bounds__(256, 2) conv_hmma(
    const float* __restrict__ in32,
    const unsigned short* __restrict__ inh, const unsigned short* __restrict__ inl,
    float* __restrict__ o32, unsigned short* __restrict__ oh, unsigned short* __restrict__ ol,
    int layer, float oscale)
{
    extern __shared__ char cs[];
    const unsigned sb = smem_u32(cs);
    const int tid = threadIdx.x, wid = tid >> 5, lane = tid & 31;
    const int n0 = blockIdx.x * 128;
    const int o0 = blockIdx.y * 128;
    const int bz = blockIdx.z;
    const int warp_o = wid & 3, warp_n = wid >> 2;
    const int qr = lane >> 2, qc = lane & 3;
    const int r8 = lane & 7, khv = (lane >> 3) & 1, nsel = (lane >> 4) & 1;

    float acc[2][8][4];
#pragma unroll
    for (int mf = 0; mf < 2; mf++)
#pragma unroll
        for (int nf = 0; nf < 8; nf++)
#pragma unroll
            for (int u = 0; u < 4; u++) acc[mf][nf][u] = 0.f;

    const unsigned short* gWh = g_Wh + (size_t)layer*C_*C_;
    const unsigned short* gWl = g_Wl + (size_t)layer*C_*C_;

    for (int kc = 0; kc < 4; kc++) {
        __syncthreads();
        const int c0k = kc * 64;
        // --- W planes: 128o x 64c, 128B rows ---
#pragma unroll
        for (int it = 0; it < 4; it++) {
            int idx = it*256 + tid;
            int row = idx >> 3, ch = idx & 7;
            size_t g = (size_t)(o0 + row)*C_ + c0k + ch*8;
            unsigned d = sb + CV_WH + (unsigned)row*128 + (unsigned)((ch ^ (row & 7)) & 7)*16;
            cpa16(d, gWh + g);
            cpa16(d + (CV_WL - CV_WH), gWl + g);
        }
        if (IN_MODE == 1) {
            // --- IN planes: 64c x 128n, 256B rows ---
#pragma unroll
            for (int it = 0; it < 4; it++) {
                int idx = it*256 + tid;
                int row = idx >> 4, ch = idx & 15;
                size_t g = (size_t)(bz*C_ + c0k + row)*NTOK + n0 + ch*8;
                unsigned d = sb + CV_INH + (unsigned)row*256 +
                             (unsigned)((ch & ~7) | ((ch ^ row) & 7))*16;
                cpa16(d, inh + g);
                cpa16(d + (CV_INL - CV_INH), inl + g);
            }
            CP_COMMIT(); CP_WAIT0();
        } else {
            CP_COMMIT();
#pragma unroll
            for (int it = 0; it < 8; it++) {
                int idx = it*256 + tid;
                int row = idx >> 5;
                int n = (idx & 31) * 4;
                float4 w = *(const float4*)&in32[(size_t)(bz*C_ + c0k + row)*NTOK + n0 + n];
                __half h0 = __float2half_rn(w.x), h1 = __float2half_rn(w.y);
                __half h2 = __float2half_rn(w.z), h3 = __float2half_rn(w.w);
                __half l0 = __float2half_rn(w.x - __half2float(h0));
                __half l1 = __float2half_rn(w.y - __half2float(h1));
                __half l2 = __float2half_rn(w.z - __half2float(h2));
                __half l3 = __float2half_rn(w.w - __half2float(h3));
                int ch = n >> 3;
                unsigned off = (unsigned)row*256 + (unsigned)((ch & ~7) | ((ch ^ row) & 7))*16 + (unsigned)(n & 7)*2;
                *(unsigned*)(cs + CV_INH + off)     = pack2us(__half_as_ushort(h0), __half_as_ushort(h1));
                *(unsigned*)(cs + CV_INH + off + 4) = pack2us(__half_as_ushort(h2), __half_as_ushort(h3));
                *(unsigned*)(cs + CV_INL + off)     = pack2us(__half_as_ushort(l0), __half_as_ushort(l1));
                *(unsigned*)(cs + CV_INL + off + 4) = pack2us(__half_as_ushort(l2), __half_as_ushort(l3));
            }
            CP_WAIT0();
        }
        __syncthreads();

        // --- MMA ---
#pragma unroll
        for (int kg = 0; kg < 4; kg++) {
            unsigned aH[2][4], aL[2][4];
#pragma unroll
            for (int mf = 0; mf < 2; mf++) {
                int mrow = warp_o*32 + mf*16 + (lane & 15);
                int ch = kg*2 + (lane >> 4);
                unsigned aof = (unsigned)mrow*128 + (unsigned)((ch ^ (mrow & 7)) & 7)*16;
                ldsm4(aH[mf], sb + CV_WH + aof);
                ldsm4(aL[mf], sb + CV_WL + aof);
            }
            int krB = kg*16 + khv*8 + r8;
#pragma unroll
            for (int nfp = 0; nfp < 4; nfp++) {
                unsigned bH4[4], bL4[4];
                int nch = warp_n*8 + nfp*2 + nsel;
                unsigned bof = (unsigned)krB*256 +
                               (unsigned)((nch & ~7) | ((nch ^ (krB & 7)) & 7))*16;
                ldsm4t(bH4, sb + CV_INH + bof);
                ldsm4t(bL4, sb + CV_INL + bof);
#pragma unroll
                for (int h = 0; h < 2; h++) {
                    int nf = nfp*2 + h;
#pragma unroll
                    for (int mf = 0; mf < 2; mf++) {
                        mma16816(acc[mf][nf], aH[mf], bH4 + 2*h);
                        mma16816(acc[mf][nf], aH[mf], bL4 + 2*h);
                        mma16816(acc[mf][nf], aL[mf], bH4 + 2*h);
                    }
                }
            }
        }
    }

    // --- epilogue ---
#pragma unroll
    for (int mf = 0; mf < 2; mf++) {
        int oA = o0 + warp_o*32 + mf*16 + qr;
        int oB = oA + 8;
        float bA = g_bf[layer*C_ + oA], bB = g_bf[layer*C_ + oB];
#pragma unroll
        for (int nf = 0; nf < 8; nf++) {
            int n = n0 + warp_n*64 + nf*8 + qc*2;
            float v0 = fmaxf(acc[mf][nf][0] + bA, 0.f) * oscale;
            float v1 = fmaxf(acc[mf][nf][1] + bA, 0.f) * oscale;
            float v2 = fmaxf(acc[mf][nf][2] + bB, 0.f) * oscale;
            float v3 = fmaxf(acc[mf][nf][3] + bB, 0.f) * oscale;
            size_t iA = (size_t)oA*NTOK + n, iB = (size_t)oB*NTOK + n;
            if (OUT_MODE == 0) {
                unsigned short* ohp = oh + (size_t)bz*C_*NTOK;
                unsigned short* olp = ol + (size_t)bz*C_*NTOK;
                __half h0 = __float2half_rn(v0), h1 = __float2half_rn(v1);
                __half h2 = __float2half_rn(v2), h3 = __float2half_rn(v3);
                *(unsigned*)&ohp[iA] = pack2us(__half_as_ushort(h0), __half_as_ushort(h1));
                *(unsigned*)&ohp[iB] = pack2us(__half_as_ushort(h2), __half_as_ushort(h3));
                __half e0 = __float2half_rn(v0 - __half2float(h0));
                __half e1 = __float2half_rn(v1 - __half2float(h1));
                __half e2 = __float2half_rn(v2 - __half2float(h2));
                __half e3 = __float2half_rn(v3 - __half2float(h3));
                *(unsigned*)&olp[iA] = pack2us(__half_as_ushort(e0), __half_as_ushort(e1));
                *(unsigned*)&olp[iB] = pack2us(__half_as_ushort(e2), __half_as_ushort(e3));
            } else if (OUT_MODE == 1) {
                unsigned short* ohp = oh + (size_t)bz*C_*NTOK;
                *(unsigned*)&ohp[iA] = packh2(v0, v1);
                *(unsigned*)&ohp[iB] = packh2(v2, v3);
            } else {
                float* op = o32 + (size_t)bz*C_*NTOK;
                *(float2*)&op[iA] = make_float2(v0, v1);
                *(float2*)&op[iB] = make_float2(v2, v3);
            }
        }
    }
}

// ---------------- pipelined HMMA flash attention ----------------
// smem: QH[256c][128n] 64K | QL 64K | KH[256c][64j] 32K | KL 32K | V[256c][64j] 32K
#define SM_QH 0
#define SM_QL 65536
#define SM_KH 131072
#define SM_KL 163840
#define SM_V  196608
#define SMEM_ATTN 229376

__global__ void __launch_bounds__(256, 1) attn_mma(
    const unsigned short* __restrict__ qhg, const unsigned short* __restrict__ qlg,
    const unsigned short* __restrict__ khg, const unsigned short* __restrict__ klg,
    const unsigned short* __restrict__ vhg,
    unsigned short* __restrict__ chg, unsigned short* __restrict__ clg)
{
    extern __shared__ char smem[];
    const unsigned sb = smem_u32(smem);
    const int tid = threadIdx.x, wid = tid >> 5, lane = tid & 31;
    const int n0 = blockIdx.x * TM;
    const size_t boff = (size_t)blockIdx.y * C_ * NTOK;
    const unsigned short* qh = qhg + boff;
    const unsigned short* ql = qlg + boff;
    const unsigned short* kh = khg + boff;
    const unsigned short* kl = klg + boff;
    const unsigned short* vh = vhg + boff;

    const int m0w = wid * 16;
    const int qr = lane >> 2, qc = lane & 3;
    const int r8 = lane & 7, khv = (lane >> 3) & 1, nsel = (lane >> 4) & 1;

    // ---- prologue: Q + K(0) (group 0), V(0) (group 1) ----
#pragma unroll
    for (int it = 0; it < 16; it++) {
        int idx = it*256 + tid;
        int row = idx >> 4, ch = idx & 15;
        size_t g = (size_t)row*NTOK + n0 + ch*8;
        unsigned d = sb + SM_QH + (unsigned)row*256 +
                     (unsigned)((ch & ~7) | ((ch ^ row) & 7))*16;
        cpa16(d, qh + g);
        cpa16(d + (SM_QL - SM_QH), ql + g);
    }
#pragma unroll
    for (int it = 0; it < 8; it++) {
        int idx = it*256 + tid;
        int row = idx >> 3, ch = idx & 7;
        size_t g = (size_t)row*NTOK + 0 + ch*8;
        unsigned d = sb + SM_KH + (unsigned)row*128 + (unsigned)((ch ^ (row & 7)) & 7)*16;
        cpa16(d, kh + g);
        cpa16(d + (SM_KL - SM_KH), kl + g);
    }
    CP_COMMIT();
#pragma unroll
    for (int it = 0; it < 8; it++) {
        int idx = it*256 + tid;
        int row = idx >> 3, ch = idx & 7;
        unsigned d = sb + SM_V + (unsigned)row*128 + (unsigned)((ch ^ (row & 7)) & 7)*16;
        cpa16(d, vh + (size_t)row*NTOK + 0 + ch*8);
    }
    CP_COMMIT();

    float O[32][4];
#pragma unroll
    for (int i = 0; i < 32; i++) { O[i][0]=0.f; O[i][1]=0.f; O[i][2]=0.f; O[i][3]=0.f; }
    float mA = -1e30f, mB = -1e30f, lA = 0.f, lB = 0.f;

    for (int t = 0; t < NT; t++) {
        CP_WAIT1();
        __syncthreads();

        // ---- S = Q Kᵀ ----
        float S[8][4];
#pragma unroll
        for (int i = 0; i < 8; i++) { S[i][0]=0.f; S[i][1]=0.f; S[i][2]=0.f; S[i][3]=0.f; }
#pragma unroll
        for (int kg = 0; kg < 16; kg++) {
            unsigned aH[4], aL[4];
            int krA = kg*16 + ((lane >> 4) & 1)*8 + (lane & 7);
            int mch = wid*2 + ((lane >> 3) & 1);
            unsigned aof = (unsigned)krA*256 +
                           (unsigned)((mch & ~7) | ((mch ^ (krA & 7)) & 7))*16;
            ldsm4t(aH, sb + SM_QH + aof);
            ldsm4t(aL, sb + SM_QL + aof);
            int krB = kg*16 + khv*8 + r8;
#pragma unroll
            for (int ntp = 0; ntp < 4; ntp++) {
                unsigned bH4[4], bL4[4];
                int nt = ntp*2 + nsel;
                unsigned bof = (unsigned)krB*128 + (unsigned)((nt ^ (krB & 7)) & 7)*16;
                ldsm4t(bH4, sb + SM_KH + bof);
                ldsm4t(bL4, sb + SM_KL + bof);
                mma16816(S[2*ntp],   aH, bH4);
                mma16816(S[2*ntp],   aH, bL4);
                mma16816(S[2*ntp],   aL, bH4);
                mma16816(S[2*ntp+1], aH, bH4 + 2);
                mma16816(S[2*ntp+1], aH, bL4 + 2);
                mma16816(S[2*ntp+1], aL, bH4 + 2);
            }
        }
        __syncthreads();

        if (t + 1 < NT) {                        // prefetch K(t+1)
            const int k1 = (t + 1) * TN;
#pragma unroll
            for (int it = 0; it < 8; it++) {
                int idx = it*256 + tid;
                int row = idx >> 3, ch = idx & 7;
                size_t g = (size_t)row*NTOK + k1 + ch*8;
                unsigned d = sb + SM_KH + (unsigned)row*128 + (unsigned)((ch ^ (row & 7)) & 7)*16;
                cpa16(d, kh + g);
                cpa16(d + (SM_KL - SM_KH), kl + g);
            }
            CP_COMMIT();
        }

        // ---- online softmax ----
        float mxA = -1e30f, mxB = -1e30f;
#pragma unroll
        for (int nt = 0; nt < 8; nt++) {
            mxA = fmaxf(mxA, fmaxf(S[nt][0], S[nt][1]));
            mxB = fmaxf(mxB, fmaxf(S[nt][2], S[nt][3]));
        }
        mxA = fmaxf(mxA, __shfl_xor_sync(0xffffffffu, mxA, 1));
        mxA = fmaxf(mxA, __shfl_xor_sync(0xffffffffu, mxA, 2));
        mxB = fmaxf(mxB, __shfl_xor_sync(0xffffffffu, mxB, 1));
        mxB = fmaxf(mxB, __shfl_xor_sync(0xffffffffu, mxB, 2));
        float mAn = fmaxf(mA, mxA), mBn = fmaxf(mB, mxB);
        float facA = ex2f(mA - mAn), facB = ex2f(mB - mBn);
        mA = mAn; mB = mBn;

        unsigned P[4][4];
        float sA = 0.f, sB = 0.f;
#pragma unroll
        for (int g = 0; g < 4; g++) {
#pragma unroll
            for (int h = 0; h < 2; h++) {
                int nt = 2*g + h;
                float e0 = ex2f(S[nt][0] - mAn), e1 = ex2f(S[nt][1] - mAn);
                float e2 = ex2f(S[nt][2] - mBn), e3 = ex2f(S[nt][3] - mBn);
                sA += e0 + e1; sB += e2 + e3;
                P[g][2*h]   = packh2(e0, e1);
                P[g][2*h+1] = packh2(e2, e3);
            }
        }
        sA += __shfl_xor_sync(0xffffffffu, sA, 1);
        sA += __shfl_xor_sync(0xffffffffu, sA, 2);
        sB += __shfl_xor_sync(0xffffffffu, sB, 1);
        sB += __shfl_xor_sync(0xffffffffu, sB, 2);
        lA = lA * facA + sA;
        lB = lB * facB + sB;
#pragma unroll
        for (int i = 0; i < 32; i++) {
            O[i][0] *= facA; O[i][1] *= facA; O[i][2] *= facB; O[i][3] *= facB;
        }

        if (t + 1 < NT) { CP_WAIT1(); } else { CP_WAIT0(); }   // V(t) ready
        __syncthreads();

        // ---- O += P V ----
#pragma unroll
        for (int jg = 0; jg < 4; jg++) {
#pragma unroll
            for (int ntp = 0; ntp < 16; ntp++) {
                unsigned bV4[4];
                int vrow = (ntp*2 + nsel)*8 + r8;
                int vch = 2*jg + khv;
                unsigned vof = (unsigned)vrow*128 + (unsigned)((vch ^ (vrow & 7)) & 7)*16;
                ldsm4(bV4, sb + SM_V + vof);
                mma16816(O[2*ntp],   P[jg], bV4);
                mma16816(O[2*ntp+1], P[jg], bV4 + 2);
            }
        }
        __syncthreads();

        if (t + 1 < NT) {                        // prefetch V(t+1)
            const int k1 = (t + 1) * TN;
#pragma unroll
            for (int it = 0; it < 8; it++) {
                int idx = it*256 + tid;
                int row = idx >> 3, ch = idx & 7;
                unsigned d = sb + SM_V + (unsigned)row*128 + (unsigned)((ch ^ (row & 7)) & 7)*16;
                cpa16(d, vh + (size_t)row*NTOK + k1 + ch*8);
            }
            CP_COMMIT();
        }
    }

    // ---- epilogue: stage split O planes in retired Q smem, copy out coalesced ----
    float iA = 1.f / lA, iB = 1.f / lB;
    const int nlA = m0w + qr, nlB = nlA + 8;
    __syncthreads();
#pragma unroll
    for (int nt = 0; nt < 32; nt++) {
        int c = nt*8 + qc*2;
        float v0 = O[nt][0]*iA, v1 = O[nt][1]*iA, v2 = O[nt][2]*iB, v3 = O[nt][3]*iB;
        __half h0 = __float2half_rn(v0), h1 = __float2half_rn(v1);
        __half h2 = __float2half_rn(v2), h3 = __float2half_rn(v3);
        __half e0 = __float2half_rn(v0 - __half2float(h0));
        __half e1 = __float2half_rn(v1 - __half2float(h1));
        __half e2 = __float2half_rn(v2 - __half2float(h2));
        __half e3 = __float2half_rn(v3 - __half2float(h3));
        *(unsigned short*)(smem + SM_QH + (c  )*256 + nlA*2) = __half_as_ushort(h0);
        *(unsigned short*)(smem + SM_QH + (c+1)*256 + nlA*2) = __half_as_ushort(h1);
        *(unsigned short*)(smem + SM_QH + (c  )*256 + nlB*2) = __half_as_ushort(h2);
        *(unsigned short*)(smem + SM_QH + (c+1)*256 + nlB*2) = __half_as_ushort(h3);
        *(unsigned short*)(smem + SM_QL + (c  )*256 + nlA*2) = __half_as_ushort(e0);
        *(unsigned short*)(smem + SM_QL + (c+1)*256 + nlA*2) = __half_as_ushort(e1);
        *(unsigned short*)(smem + SM_QL + (c  )*256 + nlB*2) = __half_as_ushort(e2);
        *(unsigned short*)(smem + SM_QL + (c+1)*256 + nlB*2) = __half_as_ushort(e3);
    }
    __syncthreads();
    unsigned short* cho = chg + boff;
    unsigned short* clo = clg + boff;
#pragma unroll
    for (int it = 0; it < 16; it++) {
        int idx = it*256 + tid;
        int row = idx >> 4, ch = idx & 15;
        uint4 vH = *(uint4*)(smem + SM_QH + row*256 + ch*16);
        uint4 vL = *(uint4*)(smem + SM_QL + row*256 + ch*16);
        *(uint4*)&cho[(size_t)row*NTOK + n0 + ch*8] = vH;
        *(uint4*)&clo[(size_t)row*NTOK + n0 + ch*8] = vL;
    }
}

// ---------------- launch ----------------
extern "C" void kernel_launch(void* const* d_in, const int* in_sizes, int n_in,
                              void* d_out, int out_size) {
    const float* x   = (const float*)d_in[0];
    const float* fk  = (const float*)d_in[1];
    const float* Ws  = (const float*)d_in[2];
    const float* gam = (const float*)d_in[3];
    const float* bet = (const float*)d_in[4];
    const float* mu  = (const float*)d_in[5];
    const float* var = (const float*)d_in[6];
    float* out = (float*)d_out;

    unsigned short *t1h, *t1l, *qh, *ql, *kh, *kl, *vh, *ch, *cl;
    cudaGetSymbolAddress((void**)&t1h, g_t1h);
    cudaGetSymbolAddress((void**)&t1l, g_t1l);
    cudaGetSymbolAddress((void**)&qh,  g_qh);
    cudaGetSymbolAddress((void**)&ql,  g_ql);
    cudaGetSymbolAddress((void**)&kh,  g_kh);
    cudaGetSymbolAddress((void**)&kl,  g_kl);
    cudaGetSymbolAddress((void**)&vh,  g_vh);
    cudaGetSymbolAddress((void**)&ch,  g_ch);
    cudaGetSymbolAddress((void**)&cl,  g_cl);

    cudaFuncSetAttribute(conv_hmma<0,0>, cudaFuncAttributeMaxDynamicSharedMemorySize, CV_SMEM);
    cudaFuncSetAttribute(conv_hmma<1,0>, cudaFuncAttributeMaxDynamicSharedMemorySize, CV_SMEM);
    cudaFuncSetAttribute(conv_hmma<0,1>, cudaFuncAttributeMaxDynamicSharedMemorySize, CV_SMEM);
    cudaFuncSetAttribute(conv_hmma<1,2>, cudaFuncAttributeMaxDynamicSharedMemorySize, CV_SMEM);
    cudaFuncSetAttribute(attn_mma, cudaFuncAttributeMaxDynamicSharedMemorySize, SMEM_ATTN);

    prep_kernel<<<L_, 256>>>(Ws, gam, bet, mu, var);

    dim3 cgrid(NTOK/128, C_/128, B_);
    conv_hmma<0,0><<<cgrid, 256, CV_SMEM>>>(x,  nullptr, nullptr, nullptr, t1h, t1l, 0, 1.0f);
    conv_hmma<1,0><<<cgrid, 256, CV_SMEM>>>(nullptr, t1h, t1l, nullptr, qh, ql, 1, LOG2E);
    conv_hmma<0,0><<<cgrid, 256, CV_SMEM>>>(fk, nullptr, nullptr, nullptr, t1h, t1l, 2, 1.0f);
    conv_hmma<1,0><<<cgrid, 256, CV_SMEM>>>(nullptr, t1h, t1l, nullptr, kh, kl, 3, 1.0f);
    conv_hmma<0,1><<<cgrid, 256, CV_SMEM>>>(fk, nullptr, nullptr, nullptr, vh, nullptr, 4, 1.0f);

    attn_mma<<<dim3(NQT, B_), 256, SMEM_ATTN>>>(qh, ql, kh, kl, vh, ch, cl);

    conv_hmma<1,2><<<cgrid, 256, CV_SMEM>>>(nullptr, ch, cl, out, nullptr, nullptr, 5, 1.0f);
}

// round 11
// speedup vs baseline: 11.1424x; 1.1408x over previous
#include <cuda_runtime.h>
#include <cuda_fp16.h>
#include <math.h>

#define B_    2
#define C_    256
#define NTOK  9216
#define L_    6
#define TM    128
#define TN    64
#define NT    (NTOK/TN)     // 144
#define NQT   (NTOK/TM)     // 72
#define LOG2E 1.4426950408889634f

// ---------------- scratch ----------------
__device__ unsigned short g_Wh[L_*C_*C_], g_Wl[L_*C_*C_];
__device__ float          g_bf[L_*C_];
__device__ unsigned short g_t1h[B_*C_*NTOK], g_t1l[B_*C_*NTOK];
__device__ unsigned short g_qh [B_*C_*NTOK];
__device__ unsigned short g_kh [B_*C_*NTOK], g_kl [B_*C_*NTOK];
__device__ unsigned short g_vh [B_*C_*NTOK];
__device__ unsigned short g_ch [B_*C_*NTOK], g_cl [B_*C_*NTOK];

// ---------------- helpers ----------------
__device__ __forceinline__ unsigned smem_u32(const void* p) {
    unsigned a;
    asm("{ .reg .u64 t; cvta.to.shared.u64 t, %1; cvt.u32.u64 %0, t; }" : "=r"(a) : "l"(p));
    return a;
}
__device__ __forceinline__ void cpa16(unsigned dst, const void* src) {
    asm volatile("cp.async.cg.shared.global [%0], [%1], 16;" :: "r"(dst), "l"(src));
}
#define CP_COMMIT() asm volatile("cp.async.commit_group;" ::: "memory")
#define CP_WAIT0()  asm volatile("cp.async.wait_group 0;" ::: "memory")
#define CP_WAIT1()  asm volatile("cp.async.wait_group 1;" ::: "memory")

__device__ __forceinline__ void ldsm4(unsigned* r, unsigned a) {
    asm volatile("ldmatrix.sync.aligned.m8n8.x4.shared.b16 {%0,%1,%2,%3}, [%4];"
        : "=r"(r[0]), "=r"(r[1]), "=r"(r[2]), "=r"(r[3]) : "r"(a));
}
__device__ __forceinline__ void ldsm4t(unsigned* r, unsigned a) {
    asm volatile("ldmatrix.sync.aligned.m8n8.x4.trans.shared.b16 {%0,%1,%2,%3}, [%4];"
        : "=r"(r[0]), "=r"(r[1]), "=r"(r[2]), "=r"(r[3]) : "r"(a));
}
__device__ __forceinline__ void mma16816(float* c, const unsigned* a, const unsigned* b) {
    asm volatile("mma.sync.aligned.m16n8k16.row.col.f32.f16.f16.f32 "
        "{%0,%1,%2,%3}, {%4,%5,%6,%7}, {%8,%9}, {%0,%1,%2,%3};"
        : "+f"(c[0]), "+f"(c[1]), "+f"(c[2]), "+f"(c[3])
        : "r"(a[0]), "r"(a[1]), "r"(a[2]), "r"(a[3]), "r"(b[0]), "r"(b[1]));
}
__device__ __forceinline__ float ex2f(float x) {
    float r; asm("ex2.approx.f32 %0, %1;" : "=f"(r) : "f"(x)); return r;
}
__device__ __forceinline__ unsigned packh2(float lo, float hi) {
    unsigned d;
    asm("cvt.rn.f16x2.f32 %0, %1, %2;" : "=r"(d) : "f"(hi), "f"(lo));
    return d;
}
__device__ __forceinline__ unsigned pack2us(unsigned short a, unsigned short b) {
    return (unsigned)a | ((unsigned)b << 16);
}

// ---------------- prep: fold BN, split W into fp16 planes ----------------
__global__ void prep_kernel(const float* __restrict__ Ws, const float* __restrict__ gam,
                            const float* __restrict__ bet, const float* __restrict__ mu,
                            const float* __restrict__ var) {
    int l = blockIdx.x, tid = threadIdx.x;
    __shared__ float sc[C_];
    float s = gam[l*C_+tid] * rsqrtf(var[l*C_+tid] + 1e-5f);
    sc[tid] = s;
    g_bf[l*C_+tid] = bet[l*C_+tid] - mu[l*C_+tid]*s;
    __syncthreads();
    const float* Wl = Ws + l*C_*C_;
    for (int t = tid; t < C_*C_; t += blockDim.x) {
        float wf = Wl[t] * sc[t >> 8];
        __half h = __float2half_rn(wf);
        __half lo = __float2half_rn(wf - __half2float(h));
        g_Wh[l*C_*C_ + t] = __half_as_ushort(h);
        g_Wl[l*C_*C_ + t] = __half_as_ushort(lo);
    }
}

// ---------------- split fp32 -> fp16 hi/lo planes ----------------
__global__ void __launch_bounds__(256) split32(const float* __restrict__ in,
                                               unsigned short* __restrict__ oh,
                                               unsigned short* __restrict__ ol) {
    size_t i = ((size_t)blockIdx.x*256 + threadIdx.x) * 4;
    float4 w = *(const float4*)(in + i);
    __half h0 = __float2half_rn(w.x), h1 = __float2half_rn(w.y);
    __half h2 = __float2half_rn(w.z), h3 = __float2half_rn(w.w);
    __half l0 = __float2half_rn(w.x - __half2float(h0));
    __half l1 = __float2half_rn(w.y - __half2float(h1));
    __half l2 = __float2half_rn(w.z - __half2float(h2));
    __half l3 = __float2half_rn(w.w - __half2float(h3));
    uint2 vh, vl;
    vh.x = pack2us(__half_as_ushort(h0), __half_as_ushort(h1));
    vh.y = pack2us(__half_as_ushort(h2), __half_as_ushort(h3));
    vl.x = pack2us(__half_as_ushort(l0), __half_as_ushort(l1));
    vl.y = pack2us(__half_as_ushort(l2), __half_as_ushort(l3));
    *(uint2*)(oh + i) = vh;
    *(uint2*)(ol + i) = vl;
}

// ---------------- HMMA convbn+relu, IN double-buffered ----------------
// CTA tile 128o x 128n, 2 CTAs/SM. 8 warps = 4(o) x 2(n).
// smem: W hi 16K | W lo 16K | IN buf0 (hi16K+lo16K) | IN buf1 (hi16K+lo16K) = 96K
#define CV_WH  0
#define CV_WL  16384
#define CV_IN  32768
#define CV_SMEM 98304

template<int OUT_MODE>   // 0 = split planes; 1 = fp16 plane; 2 = fp32
__global__ void __launch_bounds__(256, 2) conv_hmma(
    const unsigned short* __restrict__ inh, const unsigned short* __restrict__ inl,
    float* __restrict__ o32, unsigned short* __restrict__ oh, unsigned short* __restrict__ ol,
    int layer, float oscale)
{
    extern __shared__ char cs[];
    const unsigned sb = smem_u32(cs);
    const int tid = threadIdx.x, wid = tid >> 5, lane = tid & 31;
    const int n0 = blockIdx.x * 128;
    const int o0 = blockIdx.y * 128;
    const int bz = blockIdx.z;
    const int warp_o = wid & 3, warp_n = wid >> 2;
    const int qr = lane >> 2, qc = lane & 3;
    const int r8 = lane & 7, khv = (lane >> 3) & 1, nsel = (lane >> 4) & 1;

    float acc[2][8][4];
#pragma unroll
    for (int mf = 0; mf < 2; mf++)
#pragma unroll
        for (int nf = 0; nf < 8; nf++)
#pragma unroll
            for (int u = 0; u < 4; u++) acc[mf][nf][u] = 0.f;

    const unsigned short* gWh = g_Wh + (size_t)layer*C_*C_;
    const unsigned short* gWl = g_Wl + (size_t)layer*C_*C_;

    // prologue: IN(0) -> buf0
#pragma unroll
    for (int it = 0; it < 4; it++) {
        int idx = it*256 + tid;
        int row = idx >> 4, ch = idx & 15;
        size_t g = (size_t)(bz*C_ + row)*NTOK + n0 + ch*8;
        unsigned d = sb + CV_IN + (unsigned)row*256 +
                     (unsigned)((ch & ~7) | ((ch ^ row) & 7))*16;
        cpa16(d, inh + g);
        cpa16(d + 16384, inl + g);
    }
    CP_COMMIT();

    for (int kc = 0; kc < 4; kc++) {
        const int c0k = kc * 64;
        // W(kc)
#pragma unroll
        for (int it = 0; it < 4; it++) {
            int idx = it*256 + tid;
            int row = idx >> 3, ch = idx & 7;
            size_t g = (size_t)(o0 + row)*C_ + c0k + ch*8;
            unsigned d = sb + CV_WH + (unsigned)row*128 + (unsigned)((ch ^ (row & 7)) & 7)*16;
            cpa16(d, gWh + g);
            cpa16(d + (CV_WL - CV_WH), gWl + g);
        }
        CP_COMMIT();
        if (kc < 3) {   // prefetch IN(kc+1)
            const int c1 = (kc + 1) * 64;
            unsigned nb = sb + CV_IN + (unsigned)((kc + 1) & 1) * 32768;
#pragma unroll
            for (int it = 0; it < 4; it++) {
                int idx = it*256 + tid;
                int row = idx >> 4, ch = idx & 15;
                size_t g = (size_t)(bz*C_ + c1 + row)*NTOK + n0 + ch*8;
                unsigned d = nb + (unsigned)row*256 +
                             (unsigned)((ch & ~7) | ((ch ^ row) & 7))*16;
                cpa16(d, inh + g);
                cpa16(d + 16384, inl + g);
            }
            CP_COMMIT();
            CP_WAIT1();
        } else {
            CP_WAIT0();
        }
        __syncthreads();

        const unsigned inbH = sb + CV_IN + (unsigned)(kc & 1) * 32768;
        const unsigned inbL = inbH + 16384;
#pragma unroll
        for (int kg = 0; kg < 4; kg++) {
            unsigned aH[2][4], aL[2][4];
#pragma unroll
            for (int mf = 0; mf < 2; mf++) {
                int mrow = warp_o*32 + mf*16 + (lane & 15);
                int ch = kg*2 + (lane >> 4);
                unsigned aof = (unsigned)mrow*128 + (unsigned)((ch ^ (mrow & 7)) & 7)*16;
                ldsm4(aH[mf], sb + CV_WH + aof);
                ldsm4(aL[mf], sb + CV_WL + aof);
            }
            int krB = kg*16 + khv*8 + r8;
#pragma unroll
            for (int nfp = 0; nfp < 4; nfp++) {
                unsigned bH4[4], bL4[4];
                int nch = warp_n*8 + nfp*2 + nsel;
                unsigned bof = (unsigned)krB*256 +
                               (unsigned)((nch & ~7) | ((nch ^ (krB & 7)) & 7))*16;
                ldsm4t(bH4, inbH + bof);
                ldsm4t(bL4, inbL + bof);
#pragma unroll
                for (int h = 0; h < 2; h++) {
                    int nf = nfp*2 + h;
#pragma unroll
                    for (int mf = 0; mf < 2; mf++) {
                        mma16816(acc[mf][nf], aH[mf], bH4 + 2*h);
                        mma16816(acc[mf][nf], aH[mf], bL4 + 2*h);
                        mma16816(acc[mf][nf], aL[mf], bH4 + 2*h);
                    }
                }
            }
        }
        __syncthreads();
    }

    // epilogue
#pragma unroll
    for (int mf = 0; mf < 2; mf++) {
        int oA = o0 + warp_o*32 + mf*16 + qr;
        int oB = oA + 8;
        float bA = g_bf[layer*C_ + oA], bB = g_bf[layer*C_ + oB];
#pragma unroll
        for (int nf = 0; nf < 8; nf++) {
            int n = n0 + warp_n*64 + nf*8 + qc*2;
            float v0 = fmaxf(acc[mf][nf][0] + bA, 0.f) * oscale;
            float v1 = fmaxf(acc[mf][nf][1] + bA, 0.f) * oscale;
            float v2 = fmaxf(acc[mf][nf][2] + bB, 0.f) * oscale;
            float v3 = fmaxf(acc[mf][nf][3] + bB, 0.f) * oscale;
            size_t iA = (size_t)oA*NTOK + n, iB = (size_t)oB*NTOK + n;
            if (OUT_MODE == 0) {
                unsigned short* ohp = oh + (size_t)bz*C_*NTOK;
                unsigned short* olp = ol + (size_t)bz*C_*NTOK;
                __half h0 = __float2half_rn(v0), h1 = __float2half_rn(v1);
                __half h2 = __float2half_rn(v2), h3 = __float2half_rn(v3);
                *(unsigned*)&ohp[iA] = pack2us(__half_as_ushort(h0), __half_as_ushort(h1));
                *(unsigned*)&ohp[iB] = pack2us(__half_as_ushort(h2), __half_as_ushort(h3));
                __half e0 = __float2half_rn(v0 - __half2float(h0));
                __half e1 = __float2half_rn(v1 - __half2float(h1));
                __half e2 = __float2half_rn(v2 - __half2float(h2));
                __half e3 = __float2half_rn(v3 - __half2float(h3));
                *(unsigned*)&olp[iA] = pack2us(__half_as_ushort(e0), __half_as_ushort(e1));
                *(unsigned*)&olp[iB] = pack2us(__half_as_ushort(e2), __half_as_ushort(e3));
            } else if (OUT_MODE == 1) {
                unsigned short* ohp = oh + (size_t)bz*C_*NTOK;
                *(unsigned*)&ohp[iA] = packh2(v0, v1);
                *(unsigned*)&ohp[iB] = packh2(v2, v3);
            } else {
                float* op = o32 + (size_t)bz*C_*NTOK;
                *(float2*)&op[iA] = make_float2(v0, v1);
                *(float2*)&op[iB] = make_float2(v2, v3);
            }
        }
    }
}

// ---------------- pipelined HMMA flash attention (2-term QK) ----------------
// smem: QH[256c][128n] 64K | KH 32K | KL 32K | V 32K = 160K
#define SM_QH 0
#define SM_KH 65536
#define SM_KL 98304
#define SM_V  131072
#define SM_OL 65536           // epilogue lo staging (overwrites KH+KL)
#define SMEM_ATTN 163840

__global__ void __launch_bounds__(256, 1) attn_mma(
    const unsigned short* __restrict__ qhg,
    const unsigned short* __restrict__ khg, const unsigned short* __restrict__ klg,
    const unsigned short* __restrict__ vhg,
    unsigned short* __restrict__ chg, unsigned short* __restrict__ clg)
{
    extern __shared__ char smem[];
    const unsigned sb = smem_u32(smem);
    const int tid = threadIdx.x, wid = tid >> 5, lane = tid & 31;
    const int n0 = blockIdx.x * TM;
    const size_t boff = (size_t)blockIdx.y * C_ * NTOK;
    const unsigned short* qh = qhg + boff;
    const unsigned short* kh = khg + boff;
    const unsigned short* kl = klg + boff;
    const unsigned short* vh = vhg + boff;

    const int m0w = wid * 16;
    const int qr = lane >> 2, qc = lane & 3;
    const int r8 = lane & 7, khv = (lane >> 3) & 1, nsel = (lane >> 4) & 1;

    // ---- prologue: Q + K(0) (group 0), V(0) (group 1) ----
#pragma unroll
    for (int it = 0; it < 16; it++) {
        int idx = it*256 + tid;
        int row = idx >> 4, ch = idx & 15;
        size_t g = (size_t)row*NTOK + n0 + ch*8;
        unsigned d = sb + SM_QH + (unsigned)row*256 +
                     (unsigned)((ch & ~7) | ((ch ^ row) & 7))*16;
        cpa16(d, qh + g);
    }
#pragma unroll
    for (int it = 0; it < 8; it++) {
        int idx = it*256 + tid;
        int row = idx >> 3, ch = idx & 7;
        size_t g = (size_t)row*NTOK + 0 + ch*8;
        unsigned d = sb + SM_KH + (unsigned)row*128 + (unsigned)((ch ^ (row & 7)) & 7)*16;
        cpa16(d, kh + g);
        cpa16(d + (SM_KL - SM_KH), kl + g);
    }
    CP_COMMIT();
#pragma unroll
    for (int it = 0; it < 8; it++) {
        int idx = it*256 + tid;
        int row = idx >> 3, ch = idx & 7;
        unsigned d = sb + SM_V + (unsigned)row*128 + (unsigned)((ch ^ (row & 7)) & 7)*16;
        cpa16(d, vh + (size_t)row*NTOK + 0 + ch*8);
    }
    CP_COMMIT();

    float O[32][4];
#pragma unroll
    for (int i = 0; i < 32; i++) { O[i][0]=0.f; O[i][1]=0.f; O[i][2]=0.f; O[i][3]=0.f; }
    float mA = -1e30f, mB = -1e30f, lA = 0.f, lB = 0.f;

    for (int t = 0; t < NT; t++) {
        CP_WAIT1();
        __syncthreads();

        // ---- S = Qh Kᵀ (k split: 2 terms) ----
        float S[8][4];
#pragma unroll
        for (int i = 0; i < 8; i++) { S[i][0]=0.f; S[i][1]=0.f; S[i][2]=0.f; S[i][3]=0.f; }
#pragma unroll
        for (int kg = 0; kg < 16; kg++) {
            unsigned aH[4];
            int krA = kg*16 + ((lane >> 4) & 1)*8 + (lane & 7);
            int mch = wid*2 + ((lane >> 3) & 1);
            unsigned aof = (unsigned)krA*256 +
                           (unsigned)((mch & ~7) | ((mch ^ (krA & 7)) & 7))*16;
            ldsm4t(aH, sb + SM_QH + aof);
            int krB = kg*16 + khv*8 + r8;
#pragma unroll
            for (int ntp = 0; ntp < 4; ntp++) {
                unsigned bH4[4], bL4[4];
                int nt = ntp*2 + nsel;
                unsigned bof = (unsigned)krB*128 + (unsigned)((nt ^ (krB & 7)) & 7)*16;
                ldsm4t(bH4, sb + SM_KH + bof);
                ldsm4t(bL4, sb + SM_KL + bof);
                mma16816(S[2*ntp],   aH, bH4);
                mma16816(S[2*ntp],   aH, bL4);
                mma16816(S[2*ntp+1], aH, bH4 + 2);
                mma16816(S[2*ntp+1], aH, bL4 + 2);
            }
        }
        __syncthreads();

        if (t + 1 < NT) {                        // prefetch K(t+1)
            const int k1 = (t + 1) * TN;
#pragma unroll
            for (int it = 0; it < 8; it++) {
                int idx = it*256 + tid;
                int row = idx >> 3, ch = idx & 7;
                size_t g = (size_t)row*NTOK + k1 + ch*8;
                unsigned d = sb + SM_KH + (unsigned)row*128 + (unsigned)((ch ^ (row & 7)) & 7)*16;
                cpa16(d, kh + g);
                cpa16(d + (SM_KL - SM_KH), kl + g);
            }
            CP_COMMIT();
        }

        // ---- online softmax ----
        float mxA = -1e30f, mxB = -1e30f;
#pragma unroll
        for (int nt = 0; nt < 8; nt++) {
            mxA = fmaxf(mxA, fmaxf(S[nt][0], S[nt][1]));
            mxB = fmaxf(mxB, fmaxf(S[nt][2], S[nt][3]));
        }
        mxA = fmaxf(mxA, __shfl_xor_sync(0xffffffffu, mxA, 1));
        mxA = fmaxf(mxA, __shfl_xor_sync(0xffffffffu, mxA, 2));
        mxB = fmaxf(mxB, __shfl_xor_sync(0xffffffffu, mxB, 1));
        mxB = fmaxf(mxB, __shfl_xor_sync(0xffffffffu, mxB, 2));
        float mAn = fmaxf(mA, mxA), mBn = fmaxf(mB, mxB);
        float facA = ex2f(mA - mAn), facB = ex2f(mB - mBn);
        mA = mAn; mB = mBn;

        unsigned P[4][4];
        float sA = 0.f, sB = 0.f;
#pragma unroll
        for (int g = 0; g < 4; g++) {
#pragma unroll
            for (int h = 0; h < 2; h++) {
                int nt = 2*g + h;
                float e0 = ex2f(S[nt][0] - mAn), e1 = ex2f(S[nt][1] - mAn);
                float e2 = ex2f(S[nt][2] - mBn), e3 = ex2f(S[nt][3] - mBn);
                sA += e0 + e1; sB += e2 + e3;
                P[g][2*h]   = packh2(e0, e1);
                P[g][2*h+1] = packh2(e2, e3);
            }
        }
        sA += __shfl_xor_sync(0xffffffffu, sA, 1);
        sA += __shfl_xor_sync(0xffffffffu, sA, 2);
        sB += __shfl_xor_sync(0xffffffffu, sB, 1);
        sB += __shfl_xor_sync(0xffffffffu, sB, 2);
        lA = lA * facA + sA;
        lB = lB * facB + sB;
        bool nochg = (facA == 1.f) && (facB == 1.f);
        if (!__all_sync(0xffffffffu, nochg)) {
#pragma unroll
            for (int i = 0; i < 32; i++) {
                O[i][0] *= facA; O[i][1] *= facA; O[i][2] *= facB; O[i][3] *= facB;
            }
        }

        if (t + 1 < NT) { CP_WAIT1(); } else { CP_WAIT0(); }   // V(t) ready
        __syncthreads();

        // ---- O += P V ----
#pragma unroll
        for (int jg = 0; jg < 4; jg++) {
#pragma unroll
            for (int ntp = 0; ntp < 16; ntp++) {
                unsigned bV4[4];
                int vrow = (ntp*2 + nsel)*8 + r8;
                int vch = 2*jg + khv;
                unsigned vof = (unsigned)vrow*128 + (unsigned)((vch ^ (vrow & 7)) & 7)*16;
                ldsm4(bV4, sb + SM_V + vof);
                mma16816(O[2*ntp],   P[jg], bV4);
                mma16816(O[2*ntp+1], P[jg], bV4 + 2);
            }
        }
        __syncthreads();

        if (t + 1 < NT) {                        // prefetch V(t+1)
            const int k1 = (t + 1) * TN;
#pragma unroll
            for (int it = 0; it < 8; it++) {
                int idx = it*256 + tid;
                int row = idx >> 3, ch = idx & 7;
                unsigned d = sb + SM_V + (unsigned)row*128 + (unsigned)((ch ^ (row & 7)) & 7)*16;
                cpa16(d, vh + (size_t)row*NTOK + k1 + ch*8);
            }
            CP_COMMIT();
        }
    }

    // ---- epilogue: stage split O planes (hi @0, lo @SM_OL), copy out coalesced ----
    float iA = 1.f / lA, iB = 1.f / lB;
    const int nlA = m0w + qr, nlB = nlA + 8;
    __syncthreads();
#pragma unroll
    for (int nt = 0; nt < 32; nt++) {
        int c = nt*8 + qc*2;
        float v0 = O[nt][0]*iA, v1 = O[nt][1]*iA, v2 = O[nt][2]*iB, v3 = O[nt][3]*iB;
        __half h0 = __float2half_rn(v0), h1 = __float2half_rn(v1);
        __half h2 = __float2half_rn(v2), h3 = __float2half_rn(v3);
        __half e0 = __float2half_rn(v0 - __half2float(h0));
        __half e1 = __float2half_rn(v1 - __half2float(h1));
        __half e2 = __float2half_rn(v2 - __half2float(h2));
        __half e3 = __float2half_rn(v3 - __half2float(h3));
        *(unsigned short*)(smem + SM_QH + (c  )*256 + nlA*2) = __half_as_ushort(h0);
        *(unsigned short*)(smem + SM_QH + (c+1)*256 + nlA*2) = __half_as_ushort(h1);
        *(unsigned short*)(smem + SM_QH + (c  )*256 + nlB*2) = __half_as_ushort(h2);
        *(unsigned short*)(smem + SM_QH + (c+1)*256 + nlB*2) = __half_as_ushort(h3);
        *(unsigned short*)(smem + SM_OL + (c  )*256 + nlA*2) = __half_as_ushort(e0);
        *(unsigned short*)(smem + SM_OL + (c+1)*256 + nlA*2) = __half_as_ushort(e1);
        *(unsigned short*)(smem + SM_OL + (c  )*256 + nlB*2) = __half_as_ushort(e2);
        *(unsigned short*)(smem + SM_OL + (c+1)*256 + nlB*2) = __half_as_ushort(e3);
    }
    __syncthreads();
    unsigned short* cho = chg + boff;
    unsigned short* clo = clg + boff;
#pragma unroll
    for (int it = 0; it < 16; it++) {
        int idx = it*256 + tid;
        int row = idx >> 4, ch = idx & 15;
        uint4 vH = *(uint4*)(smem + SM_QH + row*256 + ch*16);
        uint4 vL = *(uint4*)(smem + SM_OL + row*256 + ch*16);
        *(uint4*)&cho[(size_t)row*NTOK + n0 + ch*8] = vH;
        *(uint4*)&clo[(size_t)row*NTOK + n0 + ch*8] = vL;
    }
}

// ---------------- launch ----------------
extern "C" void kernel_launch(void* const* d_in, const int* in_sizes, int n_in,
                              void* d_out, int out_size) {
    const float* x   = (const float*)d_in[0];
    const float* fk  = (const float*)d_in[1];
    const float* Ws  = (const float*)d_in[2];
    const float* gam = (const float*)d_in[3];
    const float* bet = (const float*)d_in[4];
    const float* mu  = (const float*)d_in[5];
    const float* var = (const float*)d_in[6];
    float* out = (float*)d_out;

    unsigned short *t1h, *t1l, *qh, *kh, *kl, *vh, *ch, *cl;
    cudaGetSymbolAddress((void**)&t1h, g_t1h);
    cudaGetSymbolAddress((void**)&t1l, g_t1l);
    cudaGetSymbolAddress((void**)&qh,  g_qh);
    cudaGetSymbolAddress((void**)&kh,  g_kh);
    cudaGetSymbolAddress((void**)&kl,  g_kl);
    cudaGetSymbolAddress((void**)&vh,  g_vh);
    cudaGetSymbolAddress((void**)&ch,  g_ch);
    cudaGetSymbolAddress((void**)&cl,  g_cl);

    cudaFuncSetAttribute(conv_hmma<0>, cudaFuncAttributeMaxDynamicSharedMemorySize, CV_SMEM);
    cudaFuncSetAttribute(conv_hmma<1>, cudaFuncAttributeMaxDynamicSharedMemorySize, CV_SMEM);
    cudaFuncSetAttribute(conv_hmma<2>, cudaFuncAttributeMaxDynamicSharedMemorySize, CV_SMEM);
    cudaFuncSetAttribute(attn_mma, cudaFuncAttributeMaxDynamicSharedMemorySize, SMEM_ATTN);

    prep_kernel<<<L_, 256>>>(Ws, gam, bet, mu, var);
    const int nsplit = (B_*C_*NTOK) / (256*4);
    split32<<<nsplit, 256>>>(x,  ch, cl);    // x planes -> ctx scratch
    split32<<<nsplit, 256>>>(fk, kh, kl);    // fk planes -> k scratch

    dim3 cgrid(NTOK/128, C_/128, B_);
    conv_hmma<0><<<cgrid, 256, CV_SMEM>>>(ch, cl,  nullptr, t1h, t1l, 0, 1.0f);   // psi1
    conv_hmma<1><<<cgrid, 256, CV_SMEM>>>(t1h, t1l, nullptr, qh, nullptr, 1, LOG2E); // psi2 -> q (hi only)
    conv_hmma<0><<<cgrid, 256, CV_SMEM>>>(kh, kl,  nullptr, t1h, t1l, 2, 1.0f);   // phi1
    conv_hmma<1><<<cgrid, 256, CV_SMEM>>>(kh, kl,  nullptr, vh, nullptr, 4, 1.0f);// f_down -> v (before k overwrite)
    conv_hmma<0><<<cgrid, 256, CV_SMEM>>>(t1h, t1l, nullptr, kh, kl, 3, 1.0f);    // phi2 -> k

    attn_mma<<<dim3(NQT, B_), 256, SMEM_ATTN>>>(qh, kh, kl, vh, ch, cl);

    conv_hmma<2><<<cgrid, 256, CV_SMEM>>>(ch, cl, out, nullptr, nullptr, 5, 1.0f); // f_up
}

// round 13
// speedup vs baseline: 11.1703x; 1.0025x over previous
#include <cuda_runtime.h>
#include <cuda_fp16.h>
#include <math.h>

#define B_    2
#define C_    256
#define NTOK  9216
#define L_    6
#define TM    128
#define TN    64
#define NT    (NTOK/TN)     // 144
#define NQT   (NTOK/TM)     // 72
#define LOG2E 1.4426950408889634f

// ---------------- scratch ----------------
__device__ unsigned short g_Wh[L_*C_*C_], g_Wl[L_*C_*C_];
__device__ float          g_bf[L_*C_];
__device__ unsigned short g_t1h[B_*C_*NTOK], g_t1l[B_*C_*NTOK];
__device__ unsigned short g_qh [B_*C_*NTOK];
__device__ unsigned short g_kh [B_*C_*NTOK], g_kl [B_*C_*NTOK];
__device__ unsigned short g_vh [B_*C_*NTOK];
__device__ unsigned short g_ch [B_*C_*NTOK], g_cl [B_*C_*NTOK];

// ---------------- helpers ----------------
__device__ __forceinline__ unsigned smem_u32(const void* p) {
    unsigned a;
    asm("{ .reg .u64 t; cvta.to.shared.u64 t, %1; cvt.u32.u64 %0, t; }" : "=r"(a) : "l"(p));
    return a;
}
__device__ __forceinline__ void cpa16(unsigned dst, const void* src) {
    asm volatile("cp.async.cg.shared.global [%0], [%1], 16;" :: "r"(dst), "l"(src));
}
#define CP_COMMIT() asm volatile("cp.async.commit_group;" ::: "memory")
#define CP_WAIT0()  asm volatile("cp.async.wait_group 0;" ::: "memory")
#define CP_WAIT1()  asm volatile("cp.async.wait_group 1;" ::: "memory")

__device__ __forceinline__ void ldsm4(unsigned* r, unsigned a) {
    asm volatile("ldmatrix.sync.aligned.m8n8.x4.shared.b16 {%0,%1,%2,%3}, [%4];"
        : "=r"(r[0]), "=r"(r[1]), "=r"(r[2]), "=r"(r[3]) : "r"(a));
}
__device__ __forceinline__ void ldsm4t(unsigned* r, unsigned a) {
    asm volatile("ldmatrix.sync.aligned.m8n8.x4.trans.shared.b16 {%0,%1,%2,%3}, [%4];"
        : "=r"(r[0]), "=r"(r[1]), "=r"(r[2]), "=r"(r[3]) : "r"(a));
}
__device__ __forceinline__ void mma16816(float* c, const unsigned* a, const unsigned* b) {
    asm volatile("mma.sync.aligned.m16n8k16.row.col.f32.f16.f16.f32 "
        "{%0,%1,%2,%3}, {%4,%5,%6,%7}, {%8,%9}, {%0,%1,%2,%3};"
        : "+f"(c[0]), "+f"(c[1]), "+f"(c[2]), "+f"(c[3])
        : "r"(a[0]), "r"(a[1]), "r"(a[2]), "r"(a[3]), "r"(b[0]), "r"(b[1]));
}
__device__ __forceinline__ float ex2f(float x) {
    float r; asm("ex2.approx.f32 %0, %1;" : "=f"(r) : "f"(x)); return r;
}
__device__ __forceinline__ unsigned packh2(float lo, float hi) {
    unsigned d;
    asm("cvt.rn.f16x2.f32 %0, %1, %2;" : "=r"(d) : "f"(hi), "f"(lo));
    return d;
}
__device__ __forceinline__ unsigned pack2us(unsigned short a, unsigned short b) {
    return (unsigned)a | ((unsigned)b << 16);
}

// ---------------- prep: fold BN, split W into fp16 planes ----------------
__global__ void prep_kernel(const float* __restrict__ Ws, const float* __restrict__ gam,
                            const float* __restrict__ bet, const float* __restrict__ mu,
                            const float* __restrict__ var) {
    int l = blockIdx.x, tid = threadIdx.x;
    __shared__ float sc[C_];
    float s = gam[l*C_+tid] * rsqrtf(var[l*C_+tid] + 1e-5f);
    sc[tid] = s;
    g_bf[l*C_+tid] = bet[l*C_+tid] - mu[l*C_+tid]*s;
    __syncthreads();
    const float* Wl = Ws + l*C_*C_;
    for (int t = tid; t < C_*C_; t += blockDim.x) {
        float wf = Wl[t] * sc[t >> 8];
        __half h = __float2half_rn(wf);
        __half lo = __float2half_rn(wf - __half2float(h));
        g_Wh[l*C_*C_ + t] = __half_as_ushort(h);
        g_Wl[l*C_*C_ + t] = __half_as_ushort(lo);
    }
}

// ---------------- split both fp32 inputs -> fp16 hi/lo planes (one launch) ----------------
#define NELEM (B_*C_*NTOK)
__global__ void __launch_bounds__(256) split2(const float* __restrict__ a, const float* __restrict__ b,
                                              unsigned short* __restrict__ ah, unsigned short* __restrict__ al,
                                              unsigned short* __restrict__ bh, unsigned short* __restrict__ bl) {
    size_t i = ((size_t)blockIdx.x*256 + threadIdx.x) * 4;
    const float* src; unsigned short *oh, *ol;
    if (i < (size_t)NELEM) { src = a; oh = ah; ol = al; }
    else { i -= NELEM; src = b; oh = bh; ol = bl; }
    float4 w = *(const float4*)(src + i);
    __half h0 = __float2half_rn(w.x), h1 = __float2half_rn(w.y);
    __half h2 = __float2half_rn(w.z), h3 = __float2half_rn(w.w);
    __half l0 = __float2half_rn(w.x - __half2float(h0));
    __half l1 = __float2half_rn(w.y - __half2float(h1));
    __half l2 = __float2half_rn(w.z - __half2float(h2));
    __half l3 = __float2half_rn(w.w - __half2float(h3));
    uint2 vh, vl;
    vh.x = pack2us(__half_as_ushort(h0), __half_as_ushort(h1));
    vh.y = pack2us(__half_as_ushort(h2), __half_as_ushort(h3));
    vl.x = pack2us(__half_as_ushort(l0), __half_as_ushort(l1));
    vl.y = pack2us(__half_as_ushort(l2), __half_as_ushort(l3));
    *(uint2*)(oh + i) = vh;
    *(uint2*)(ol + i) = vl;
}

// ---------------- HMMA convbn+relu: 1 CTA/SM, depth-2 pipelined W+IN ----------------
// CTA tile 128o x 256n, 512 threads = 16 warps (4o x 4n), warp 32o x 64n.
// smem: W stage s at s*32K (hi 16K + lo 16K); IN stage s at 64K + s*64K (hi 32K + lo 32K) = 192K
#define CV_IN0  65536
#define CV_SMEM 196608

__device__ __forceinline__ void cv_fill_w(unsigned sb, int st, const unsigned short* gWh,
                                          const unsigned short* gWl, int o0, int c0k, int tid) {
    unsigned wbase = sb + (unsigned)st * 32768u;
#pragma unroll
    for (int it = 0; it < 2; it++) {
        int idx = it*512 + tid;
        int row = idx >> 3, ch = idx & 7;
        size_t g = (size_t)(o0 + row)*C_ + c0k + ch*8;
        unsigned d = wbase + (unsigned)row*128 + (unsigned)((ch ^ (row & 7)) & 7)*16;
        cpa16(d, gWh + g);
        cpa16(d + 16384, gWl + g);
    }
}
__device__ __forceinline__ void cv_fill_in(unsigned sb, int st, const unsigned short* inh,
                                           const unsigned short* inl, size_t inoff, int c0k,
                                           int n0, int tid) {
    unsigned ibase = sb + CV_IN0 + (unsigned)st * 65536u;
#pragma unroll
    for (int it = 0; it < 4; it++) {
        int idx = it*512 + tid;
        int row = idx >> 5, ch = idx & 31;
        size_t g = inoff + (size_t)(c0k + row)*NTOK + n0 + ch*8;
        unsigned d = ibase + (unsigned)row*512 +
                     (unsigned)((ch & ~7) | ((ch ^ row) & 7))*16;
        cpa16(d, inh + g);
        cpa16(d + 32768, inl + g);
    }
}

template<int OUT_MODE>   // 0 = split planes; 1 = fp16 plane; 2 = fp32
__global__ void __launch_bounds__(512, 1) conv_hmma(
    const unsigned short* __restrict__ inh, const unsigned short* __restrict__ inl,
    float* __restrict__ o32, unsigned short* __restrict__ oh, unsigned short* __restrict__ ol,
    int layer, float oscale)
{
    extern __shared__ char cs[];
    const unsigned sb = smem_u32(cs);
    const int tid = threadIdx.x, wid = tid >> 5, lane = tid & 31;
    const int n0 = blockIdx.x * 256;
    const int o0 = blockIdx.y * 128;
    const int bz = blockIdx.z;
    const int warp_o = wid & 3, warp_n = wid >> 2;
    const int qr = lane >> 2, qc = lane & 3;
    const int r8 = lane & 7, khv = (lane >> 3) & 1, nsel = (lane >> 4) & 1;
    const size_t inoff = (size_t)bz * C_ * NTOK;

    float acc[2][8][4];
#pragma unroll
    for (int mf = 0; mf < 2; mf++)
#pragma unroll
        for (int nf = 0; nf < 8; nf++)
#pragma unroll
            for (int u = 0; u < 4; u++) acc[mf][nf][u] = 0.f;

    const unsigned short* gWh = g_Wh + (size_t)layer*C_*C_;
    const unsigned short* gWl = g_Wl + (size_t)layer*C_*C_;

    // prologue: stages 0,1
    cv_fill_w(sb, 0, gWh, gWl, o0, 0, tid);
    cv_fill_in(sb, 0, inh, inl, inoff, 0, n0, tid);
    CP_COMMIT();
    cv_fill_w(sb, 1, gWh, gWl, o0, 64, tid);
    cv_fill_in(sb, 1, inh, inl, inoff, 64, n0, tid);
    CP_COMMIT();

    for (int kc = 0; kc < 4; kc++) {
        if (kc < 3) { CP_WAIT1(); } else { CP_WAIT0(); }
        __syncthreads();
        const unsigned wbase = sb + (unsigned)(kc & 1) * 32768u;
        const unsigned ibH = sb + CV_IN0 + (unsigned)(kc & 1) * 65536u;
        const unsigned ibL = ibH + 32768u;
#pragma unroll
        for (int kg = 0; kg < 4; kg++) {
            unsigned aH[2][4], aL[2][4];
#pragma unroll
            for (int mf = 0; mf < 2; mf++) {
                int mrow = warp_o*32 + mf*16 + (lane & 15);
                int ch = kg*2 + (lane >> 4);
                unsigned aof = (unsigned)mrow*128 + (unsigned)((ch ^ (mrow & 7)) & 7)*16;
                ldsm4(aH[mf], wbase + aof);
                ldsm4(aL[mf], wbase + 16384u + aof);
            }
            int krB = kg*16 + khv*8 + r8;
#pragma unroll
            for (int nfp = 0; nfp < 4; nfp++) {
                unsigned bH4[4], bL4[4];
                int nch = warp_n*8 + nfp*2 + nsel;
                unsigned bof = (unsigned)krB*512 +
                               (unsigned)((nch & ~7) | ((nch ^ (krB & 7)) & 7))*16;
                ldsm4t(bH4, ibH + bof);
                ldsm4t(bL4, ibL + bof);
#pragma unroll
                for (int h = 0; h < 2; h++) {
                    int nf = nfp*2 + h;
#pragma unroll
                    for (int mf = 0; mf < 2; mf++) {
                        mma16816(acc[mf][nf], aH[mf], bH4 + 2*h);
                        mma16816(acc[mf][nf], aH[mf], bL4 + 2*h);
                        mma16816(acc[mf][nf], aL[mf], bH4 + 2*h);
                    }
                }
            }
        }
        __syncthreads();      // all warps done with stage (kc&1) before refill
        if (kc + 2 < 4) {
            int c2 = (kc + 2) * 64;
            cv_fill_w(sb, kc & 1, gWh, gWl, o0, c2, tid);
            cv_fill_in(sb, kc & 1, inh, inl, inoff, c2, n0, tid);
            CP_COMMIT();
        }
    }

    // epilogue
#pragma unroll
    for (int mf = 0; mf < 2; mf++) {
        int oA = o0 + warp_o*32 + mf*16 + qr;
        int oB = oA + 8;
        float bA = g_bf[layer*C_ + oA], bB = g_bf[layer*C_ + oB];
#pragma unroll
        for (int nf = 0; nf < 8; nf++) {
            int n = n0 + warp_n*64 + nf*8 + qc*2;
            float v0 = fmaxf(acc[mf][nf][0] + bA, 0.f) * oscale;
            float v1 = fmaxf(acc[mf][nf][1] + bA, 0.f) * oscale;
            float v2 = fmaxf(acc[mf][nf][2] + bB, 0.f) * oscale;
            float v3 = fmaxf(acc[mf][nf][3] + bB, 0.f) * oscale;
            size_t iA = inoff + (size_t)oA*NTOK + n, iB = inoff + (size_t)oB*NTOK + n;
            if (OUT_MODE == 0) {
                __half h0 = __float2half_rn(v0), h1 = __float2half_rn(v1);
                __half h2 = __float2half_rn(v2), h3 = __float2half_rn(v3);
                *(unsigned*)&oh[iA] = pack2us(__half_as_ushort(h0), __half_as_ushort(h1));
                *(unsigned*)&oh[iB] = pack2us(__half_as_ushort(h2), __half_as_ushort(h3));
                __half e0 = __float2half_rn(v0 - __half2float(h0));
                __half e1 = __float2half_rn(v1 - __half2float(h1));
                __half e2 = __float2half_rn(v2 - __half2float(h2));
                __half e3 = __float2half_rn(v3 - __half2float(h3));
                *(unsigned*)&ol[iA] = pack2us(__half_as_ushort(e0), __half_as_ushort(e1));
                *(unsigned*)&ol[iB] = pack2us(__half_as_ushort(e2), __half_as_ushort(e3));
            } else if (OUT_MODE == 1) {
                *(unsigned*)&oh[iA] = packh2(v0, v1);
                *(unsigned*)&oh[iB] = packh2(v2, v3);
            } else {
                *(float2*)&o32[iA] = make_float2(v0, v1);
                *(float2*)&o32[iB] = make_float2(v2, v3);
            }
        }
    }
}

// ---------------- pipelined HMMA flash attention (2-term QK) — unchanged from R10 ----------------
#define SM_QH 0
#define SM_KH 65536
#define SM_KL 98304
#define SM_V  131072
#define SM_OL 65536
#define SMEM_ATTN 163840

__global__ void __launch_bounds__(256, 1) attn_mma(
    const unsigned short* __restrict__ qhg,
    const unsigned short* __restrict__ khg, const unsigned short* __restrict__ klg,
    const unsigned short* __restrict__ vhg,
    unsigned short* __restrict__ chg, unsigned short* __restrict__ clg)
{
    extern __shared__ char smem[];
    const unsigned sb = smem_u32(smem);
    const int tid = threadIdx.x, wid = tid >> 5, lane = tid & 31;
    const int n0 = blockIdx.x * TM;
    const size_t boff = (size_t)blockIdx.y * C_ * NTOK;
    const unsigned short* qh = qhg + boff;
    const unsigned short* kh = khg + boff;
    const unsigned short* kl = klg + boff;
    const unsigned short* vh = vhg + boff;

    const int m0w = wid * 16;
    const int qr = lane >> 2, qc = lane & 3;
    const int r8 = lane & 7, khv = (lane >> 3) & 1, nsel = (lane >> 4) & 1;

#pragma unroll
    for (int it = 0; it < 16; it++) {
        int idx = it*256 + tid;
        int row = idx >> 4, ch = idx & 15;
        size_t g = (size_t)row*NTOK + n0 + ch*8;
        unsigned d = sb + SM_QH + (unsigned)row*256 +
                     (unsigned)((ch & ~7) | ((ch ^ row) & 7))*16;
        cpa16(d, qh + g);
    }
#pragma unroll
    for (int it = 0; it < 8; it++) {
        int idx = it*256 + tid;
        int row = idx >> 3, ch = idx & 7;
        size_t g = (size_t)row*NTOK + 0 + ch*8;
        unsigned d = sb + SM_KH + (unsigned)row*128 + (unsigned)((ch ^ (row & 7)) & 7)*16;
        cpa16(d, kh + g);
        cpa16(d + (SM_KL - SM_KH), kl + g);
    }
    CP_COMMIT();
#pragma unroll
    for (int it = 0; it < 8; it++) {
        int idx = it*256 + tid;
        int row = idx >> 3, ch = idx & 7;
        unsigned d = sb + SM_V + (unsigned)row*128 + (unsigned)((ch ^ (row & 7)) & 7)*16;
        cpa16(d, vh + (size_t)row*NTOK + 0 + ch*8);
    }
    CP_COMMIT();

    float O[32][4];
#pragma unroll
    for (int i = 0; i < 32; i++) { O[i][0]=0.f; O[i][1]=0.f; O[i][2]=0.f; O[i][3]=0.f; }
    float mA = -1e30f, mB = -1e30f, lA = 0.f, lB = 0.f;

    for (int t = 0; t < NT; t++) {
        CP_WAIT1();
        __syncthreads();

        float S[8][4];
#pragma unroll
        for (int i = 0; i < 8; i++) { S[i][0]=0.f; S[i][1]=0.f; S[i][2]=0.f; S[i][3]=0.f; }
#pragma unroll
        for (int kg = 0; kg < 16; kg++) {
            unsigned aH[4];
            int krA = kg*16 + ((lane >> 4) & 1)*8 + (lane & 7);
            int mch = wid*2 + ((lane >> 3) & 1);
            unsigned aof = (unsigned)krA*256 +
                           (unsigned)((mch & ~7) | ((mch ^ (krA & 7)) & 7))*16;
            ldsm4t(aH, sb + SM_QH + aof);
            int krB = kg*16 + khv*8 + r8;
#pragma unroll
            for (int ntp = 0; ntp < 4; ntp++) {
                unsigned bH4[4], bL4[4];
                int nt = ntp*2 + nsel;
                unsigned bof = (unsigned)krB*128 + (unsigned)((nt ^ (krB & 7)) & 7)*16;
                ldsm4t(bH4, sb + SM_KH + bof);
                ldsm4t(bL4, sb + SM_KL + bof);
                mma16816(S[2*ntp],   aH, bH4);
                mma16816(S[2*ntp],   aH, bL4);
                mma16816(S[2*ntp+1], aH, bH4 + 2);
                mma16816(S[2*ntp+1], aH, bL4 + 2);
            }
        }
        __syncthreads();

        if (t + 1 < NT) {
            const int k1 = (t + 1) * TN;
#pragma unroll
            for (int it = 0; it < 8; it++) {
                int idx = it*256 + tid;
                int row = idx >> 3, ch = idx & 7;
                size_t g = (size_t)row*NTOK + k1 + ch*8;
                unsigned d = sb + SM_KH + (unsigned)row*128 + (unsigned)((ch ^ (row & 7)) & 7)*16;
                cpa16(d, kh + g);
                cpa16(d + (SM_KL - SM_KH), kl + g);
            }
            CP_COMMIT();
        }

        float mxA = -1e30f, mxB = -1e30f;
#pragma unroll
        for (int nt = 0; nt < 8; nt++) {
            mxA = fmaxf(mxA, fmaxf(S[nt][0], S[nt][1]));
            mxB = fmaxf(mxB, fmaxf(S[nt][2], S[nt][3]));
        }
        mxA = fmaxf(mxA, __shfl_xor_sync(0xffffffffu, mxA, 1));
        mxA = fmaxf(mxA, __shfl_xor_sync(0xffffffffu, mxA, 2));
        mxB = fmaxf(mxB, __shfl_xor_sync(0xffffffffu, mxB, 1));
        mxB = fmaxf(mxB, __shfl_xor_sync(0xffffffffu, mxB, 2));
        float mAn = fmaxf(mA, mxA), mBn = fmaxf(mB, mxB);
        float facA = ex2f(mA - mAn), facB = ex2f(mB - mBn);
        mA = mAn; mB = mBn;

        unsigned P[4][4];
        float sA = 0.f, sB = 0.f;
#pragma unroll
        for (int g = 0; g < 4; g++) {
#pragma unroll
            for (int h = 0; h < 2; h++) {
                int nt = 2*g + h;
                float e0 = ex2f(S[nt][0] - mAn), e1 = ex2f(S[nt][1] - mAn);
                float e2 = ex2f(S[nt][2] - mBn), e3 = ex2f(S[nt][3] - mBn);
                sA += e0 + e1; sB += e2 + e3;
                P[g][2*h]   = packh2(e0, e1);
                P[g][2*h+1] = packh2(e2, e3);
            }
        }
        sA += __shfl_xor_sync(0xffffffffu, sA, 1);
        sA += __shfl_xor_sync(0xffffffffu, sA, 2);
        sB += __shfl_xor_sync(0xffffffffu, sB, 1);
        sB += __shfl_xor_sync(0xffffffffu, sB, 2);
        lA = lA * facA + sA;
        lB = lB * facB + sB;
        bool nochg = (facA == 1.f) && (facB == 1.f);
        if (!__all_sync(0xffffffffu, nochg)) {
#pragma unroll
            for (int i = 0; i < 32; i++) {
                O[i][0] *= facA; O[i][1] *= facA; O[i][2] *= facB; O[i][3] *= facB;
            }
        }

        if (t + 1 < NT) { CP_WAIT1(); } else { CP_WAIT0(); }
        __syncthreads();

#pragma unroll
        for (int jg = 0; jg < 4; jg++) {
#pragma unroll
            for (int ntp = 0; ntp < 16; ntp++) {
                unsigned bV4[4];
                int vrow = (ntp*2 + nsel)*8 + r8;
                int vch = 2*jg + khv;
                unsigned vof = (unsigned)vrow*128 + (unsigned)((vch ^ (vrow & 7)) & 7)*16;
                ldsm4(bV4, sb + SM_V + vof);
                mma16816(O[2*ntp],   P[jg], bV4);
                mma16816(O[2*ntp+1], P[jg], bV4 + 2);
            }
        }
        __syncthreads();

        if (t + 1 < NT) {
            const int k1 = (t + 1) * TN;
#pragma unroll
            for (int it = 0; it < 8; it++) {
                int idx = it*256 + tid;
                int row = idx >> 3, ch = idx & 7;
                unsigned d = sb + SM_V + (unsigned)row*128 + (unsigned)((ch ^ (row & 7)) & 7)*16;
                cpa16(d, vh + (size_t)row*NTOK + k1 + ch*8);
            }
            CP_COMMIT();
        }
    }

    float iA = 1.f / lA, iB = 1.f / lB;
    const int nlA = m0w + qr, nlB = nlA + 8;
    __syncthreads();
#pragma unroll
    for (int nt = 0; nt < 32; nt++) {
        int c = nt*8 + qc*2;
        float v0 = O[nt][0]*iA, v1 = O[nt][1]*iA, v2 = O[nt][2]*iB, v3 = O[nt][3]*iB;
        __half h0 = __float2half_rn(v0), h1 = __float2half_rn(v1);
        __half h2 = __float2half_rn(v2), h3 = __float2half_rn(v3);
        __half e0 = __float2half_rn(v0 - __half2float(h0));
        __half e1 = __float2half_rn(v1 - __half2float(h1));
        __half e2 = __float2half_rn(v2 - __half2float(h2));
        __half e3 = __float2half_rn(v3 - __half2float(h3));
        *(unsigned short*)(smem + SM_QH + (c  )*256 + nlA*2) = __half_as_ushort(h0);
        *(unsigned short*)(smem + SM_QH + (c+1)*256 + nlA*2) = __half_as_ushort(h1);
        *(unsigned short*)(smem + SM_QH + (c  )*256 + nlB*2) = __half_as_ushort(h2);
        *(unsigned short*)(smem + SM_QH + (c+1)*256 + nlB*2) = __half_as_ushort(h3);
        *(unsigned short*)(smem + SM_OL + (c  )*256 + nlA*2) = __half_as_ushort(e0);
        *(unsigned short*)(smem + SM_OL + (c+1)*256 + nlA*2) = __half_as_ushort(e1);
        *(unsigned short*)(smem + SM_OL + (c  )*256 + nlB*2) = __half_as_ushort(e2);
        *(unsigned short*)(smem + SM_OL + (c+1)*256 + nlB*2) = __half_as_ushort(e3);
    }
    __syncthreads();
    unsigned short* cho = chg + boff;
    unsigned short* clo = clg + boff;
#pragma unroll
    for (int it = 0; it < 16; it++) {
        int idx = it*256 + tid;
        int row = idx >> 4, ch = idx & 15;
        uint4 vH = *(uint4*)(smem + SM_QH + row*256 + ch*16);
        uint4 vL = *(uint4*)(smem + SM_OL + row*256 + ch*16);
        *(uint4*)&cho[(size_t)row*NTOK + n0 + ch*8] = vH;
        *(uint4*)&clo[(size_t)row*NTOK + n0 + ch*8] = vL;
    }
}

// ---------------- launch ----------------
extern "C" void kernel_launch(void* const* d_in, const int* in_sizes, int n_in,
                              void* d_out, int out_size) {
    const float* x   = (const float*)d_in[0];
    const float* fk  = (const float*)d_in[1];
    const float* Ws  = (const float*)d_in[2];
    const float* gam = (const float*)d_in[3];
    const float* bet = (const float*)d_in[4];
    const float* mu  = (const float*)d_in[5];
    const float* var = (const float*)d_in[6];
    float* out = (float*)d_out;

    unsigned short *t1h, *t1l, *qh, *kh, *kl, *vh, *ch, *cl;
    cudaGetSymbolAddress((void**)&t1h, g_t1h);
    cudaGetSymbolAddress((void**)&t1l, g_t1l);
    cudaGetSymbolAddress((void**)&qh,  g_qh);
    cudaGetSymbolAddress((void**)&kh,  g_kh);
    cudaGetSymbolAddress((void**)&kl,  g_kl);
    cudaGetSymbolAddress((void**)&vh,  g_vh);
    cudaGetSymbolAddress((void**)&ch,  g_ch);
    cudaGetSymbolAddress((void**)&cl,  g_cl);

    cudaFuncSetAttribute(conv_hmma<0>, cudaFuncAttributeMaxDynamicSharedMemorySize, CV_SMEM);
    cudaFuncSetAttribute(conv_hmma<1>, cudaFuncAttributeMaxDynamicSharedMemorySize, CV_SMEM);
    cudaFuncSetAttribute(conv_hmma<2>, cudaFuncAttributeMaxDynamicSharedMemorySize, CV_SMEM);
    cudaFuncSetAttribute(attn_mma, cudaFuncAttributeMaxDynamicSharedMemorySize, SMEM_ATTN);

    prep_kernel<<<L_, 256>>>(Ws, gam, bet, mu, var);
    split2<<<(2*NELEM)/(256*4), 256>>>(x, fk, ch, cl, kh, kl);  // x -> ctx scratch, fk -> k scratch

    dim3 cgrid(NTOK/256, C_/128, B_);
    conv_hmma<0><<<cgrid, 512, CV_SMEM>>>(ch, cl,  nullptr, t1h, t1l, 0, 1.0f);     // psi1
    conv_hmma<1><<<cgrid, 512, CV_SMEM>>>(t1h, t1l, nullptr, qh, nullptr, 1, LOG2E); // psi2 -> q
    conv_hmma<0><<<cgrid, 512, CV_SMEM>>>(kh, kl,  nullptr, t1h, t1l, 2, 1.0f);     // phi1
    conv_hmma<1><<<cgrid, 512, CV_SMEM>>>(kh, kl,  nullptr, vh, nullptr, 4, 1.0f);  // f_down -> v
    conv_hmma<0><<<cgrid, 512, CV_SMEM>>>(t1h, t1l, nullptr, kh, kl, 3, 1.0f);      // phi2 -> k

    attn_mma<<<dim3(NQT, B_), 256, SMEM_ATTN>>>(qh, kh, kl, vh, ch, cl);

    conv_hmma<2><<<cgrid, 512, CV_SMEM>>>(ch, cl, out, nullptr, nullptr, 5, 1.0f);  // f_up
}

// round 14
// speedup vs baseline: 11.4200x; 1.0224x over previous
#include <cuda_runtime.h>
#include <cuda_fp16.h>
#include <math.h>

#define B_    2
#define C_    256
#define NTOK  9216
#define L_    6
#define TM    128
#define TN    64
#define NT    (NTOK/TN)     // 144
#define NQT   (NTOK/TM)     // 72
#define LOG2E 1.4426950408889634f

// ---------------- scratch ----------------
__device__ unsigned short g_Wh[L_*C_*C_], g_Wl[L_*C_*C_];
__device__ float          g_bf[L_*C_];
__device__ unsigned short g_t1h[B_*C_*NTOK], g_t1l[B_*C_*NTOK];
__device__ unsigned short g_qh [B_*C_*NTOK];
__device__ unsigned short g_kh [B_*C_*NTOK], g_kl [B_*C_*NTOK];
__device__ unsigned short g_vh [B_*C_*NTOK];
__device__ unsigned short g_ch [B_*C_*NTOK], g_cl [B_*C_*NTOK];

// ---------------- helpers ----------------
__device__ __forceinline__ unsigned smem_u32(const void* p) {
    unsigned a;
    asm("{ .reg .u64 t; cvta.to.shared.u64 t, %1; cvt.u32.u64 %0, t; }" : "=r"(a) : "l"(p));
    return a;
}
__device__ __forceinline__ void cpa16(unsigned dst, const void* src) {
    asm volatile("cp.async.cg.shared.global [%0], [%1], 16;" :: "r"(dst), "l"(src));
}
#define CP_COMMIT() asm volatile("cp.async.commit_group;" ::: "memory")
#define CP_WAIT0()  asm volatile("cp.async.wait_group 0;" ::: "memory")
#define CP_WAIT1()  asm volatile("cp.async.wait_group 1;" ::: "memory")

__device__ __forceinline__ void ldsm4(unsigned* r, unsigned a) {
    asm volatile("ldmatrix.sync.aligned.m8n8.x4.shared.b16 {%0,%1,%2,%3}, [%4];"
        : "=r"(r[0]), "=r"(r[1]), "=r"(r[2]), "=r"(r[3]) : "r"(a));
}
__device__ __forceinline__ void ldsm4t(unsigned* r, unsigned a) {
    asm volatile("ldmatrix.sync.aligned.m8n8.x4.trans.shared.b16 {%0,%1,%2,%3}, [%4];"
        : "=r"(r[0]), "=r"(r[1]), "=r"(r[2]), "=r"(r[3]) : "r"(a));
}
__device__ __forceinline__ void mma16816(float* c, const unsigned* a, const unsigned* b) {
    asm volatile("mma.sync.aligned.m16n8k16.row.col.f32.f16.f16.f32 "
        "{%0,%1,%2,%3}, {%4,%5,%6,%7}, {%8,%9}, {%0,%1,%2,%3};"
        : "+f"(c[0]), "+f"(c[1]), "+f"(c[2]), "+f"(c[3])
        : "r"(a[0]), "r"(a[1]), "r"(a[2]), "r"(a[3]), "r"(b[0]), "r"(b[1]));
}
__device__ __forceinline__ float ex2f(float x) {
    float r; asm("ex2.approx.f32 %0, %1;" : "=f"(r) : "f"(x)); return r;
}
__device__ __forceinline__ unsigned packh2(float lo, float hi) {
    unsigned d;
    asm("cvt.rn.f16x2.f32 %0, %1, %2;" : "=r"(d) : "f"(hi), "f"(lo));
    return d;
}
__device__ __forceinline__ unsigned pack2us(unsigned short a, unsigned short b) {
    return (unsigned)a | ((unsigned)b << 16);
}

// ---------------- prep: fold BN, split W into fp16 planes ----------------
__global__ void prep_kernel(const float* __restrict__ Ws, const float* __restrict__ gam,
                            const float* __restrict__ bet, const float* __restrict__ mu,
                            const float* __restrict__ var) {
    int l = blockIdx.x, tid = threadIdx.x;
    __shared__ float sc[C_];
    float s = gam[l*C_+tid] * rsqrtf(var[l*C_+tid] + 1e-5f);
    sc[tid] = s;
    g_bf[l*C_+tid] = bet[l*C_+tid] - mu[l*C_+tid]*s;
    __syncthreads();
    const float* Wl = Ws + l*C_*C_;
    for (int t = tid; t < C_*C_; t += blockDim.x) {
        float wf = Wl[t] * sc[t >> 8];
        __half h = __float2half_rn(wf);
        __half lo = __float2half_rn(wf - __half2float(h));
        g_Wh[l*C_*C_ + t] = __half_as_ushort(h);
        g_Wl[l*C_*C_ + t] = __half_as_ushort(lo);
    }
}

// ---------------- split both fp32 inputs -> fp16 hi/lo planes ----------------
#define NELEM (B_*C_*NTOK)
__global__ void __launch_bounds__(256) split2(const float* __restrict__ a, const float* __restrict__ b,
                                              unsigned short* __restrict__ ah, unsigned short* __restrict__ al,
                                              unsigned short* __restrict__ bh, unsigned short* __restrict__ bl) {
    size_t i = ((size_t)blockIdx.x*256 + threadIdx.x) * 4;
    const float* src; unsigned short *oh, *ol;
    if (i < (size_t)NELEM) { src = a; oh = ah; ol = al; }
    else { i -= NELEM; src = b; oh = bh; ol = bl; }
    float4 w = *(const float4*)(src + i);
    __half h0 = __float2half_rn(w.x), h1 = __float2half_rn(w.y);
    __half h2 = __float2half_rn(w.z), h3 = __float2half_rn(w.w);
    __half l0 = __float2half_rn(w.x - __half2float(h0));
    __half l1 = __float2half_rn(w.y - __half2float(h1));
    __half l2 = __float2half_rn(w.z - __half2float(h2));
    __half l3 = __float2half_rn(w.w - __half2float(h3));
    uint2 vh, vl;
    vh.x = pack2us(__half_as_ushort(h0), __half_as_ushort(h1));
    vh.y = pack2us(__half_as_ushort(h2), __half_as_ushort(h3));
    vl.x = pack2us(__half_as_ushort(l0), __half_as_ushort(l1));
    vl.y = pack2us(__half_as_ushort(l2), __half_as_ushort(l3));
    *(uint2*)(oh + i) = vh;
    *(uint2*)(ol + i) = vl;
}

// ---------------- HMMA convbn+relu: 1 CTA/SM, depth-2 pipelined W+IN ----------------
#define CV_IN0  65536
#define CV_SMEM 196608

__device__ __forceinline__ void cv_fill_w(unsigned sb, int st, const unsigned short* gWh,
                                          const unsigned short* gWl, int o0, int c0k, int tid) {
    unsigned wbase = sb + (unsigned)st * 32768u;
#pragma unroll
    for (int it = 0; it < 2; it++) {
        int idx = it*512 + tid;
        int row = idx >> 3, ch = idx & 7;
        size_t g = (size_t)(o0 + row)*C_ + c0k + ch*8;
        unsigned d = wbase + (unsigned)row*128 + (unsigned)((ch ^ (row & 7)) & 7)*16;
        cpa16(d, gWh + g);
        cpa16(d + 16384, gWl + g);
    }
}
__device__ __forceinline__ void cv_fill_in(unsigned sb, int st, const unsigned short* inh,
                                           const unsigned short* inl, size_t inoff, int c0k,
                                           int n0, int tid) {
    unsigned ibase = sb + CV_IN0 + (unsigned)st * 65536u;
#pragma unroll
    for (int it = 0; it < 4; it++) {
        int idx = it*512 + tid;
        int row = idx >> 5, ch = idx & 31;
        size_t g = inoff + (size_t)(c0k + row)*NTOK + n0 + ch*8;
        unsigned d = ibase + (unsigned)row*512 +
                     (unsigned)((ch & ~7) | ((ch ^ row) & 7))*16;
        cpa16(d, inh + g);
        cpa16(d + 32768, inl + g);
    }
}

template<int OUT_MODE>   // 0 = split planes; 1 = fp16 plane; 2 = fp32
__global__ void __launch_bounds__(512, 1) conv_hmma(
    const unsigned short* __restrict__ inh, const unsigned short* __restrict__ inl,
    float* __restrict__ o32, unsigned short* __restrict__ oh, unsigned short* __restrict__ ol,
    int layer, float oscale)
{
    extern __shared__ char cs[];
    const unsigned sb = smem_u32(cs);
    const int tid = threadIdx.x, wid = tid >> 5, lane = tid & 31;
    const int n0 = blockIdx.x * 256;
    const int o0 = blockIdx.y * 128;
    const int bz = blockIdx.z;
    const int warp_o = wid & 3, warp_n = wid >> 2;
    const int qr = lane >> 2, qc = lane & 3;
    const int r8 = lane & 7, khv = (lane >> 3) & 1, nsel = (lane >> 4) & 1;
    const size_t inoff = (size_t)bz * C_ * NTOK;

    float acc[2][8][4];
#pragma unroll
    for (int mf = 0; mf < 2; mf++)
#pragma unroll
        for (int nf = 0; nf < 8; nf++)
#pragma unroll
            for (int u = 0; u < 4; u++) acc[mf][nf][u] = 0.f;

    const unsigned short* gWh = g_Wh + (size_t)layer*C_*C_;
    const unsigned short* gWl = g_Wl + (size_t)layer*C_*C_;

    cv_fill_w(sb, 0, gWh, gWl, o0, 0, tid);
    cv_fill_in(sb, 0, inh, inl, inoff, 0, n0, tid);
    CP_COMMIT();
    cv_fill_w(sb, 1, gWh, gWl, o0, 64, tid);
    cv_fill_in(sb, 1, inh, inl, inoff, 64, n0, tid);
    CP_COMMIT();

    for (int kc = 0; kc < 4; kc++) {
        if (kc < 3) { CP_WAIT1(); } else { CP_WAIT0(); }
        __syncthreads();
        const unsigned wbase = sb + (unsigned)(kc & 1) * 32768u;
        const unsigned ibH = sb + CV_IN0 + (unsigned)(kc & 1) * 65536u;
        const unsigned ibL = ibH + 32768u;
#pragma unroll
        for (int kg = 0; kg < 4; kg++) {
            unsigned aH[2][4], aL[2][4];
#pragma unroll
            for (int mf = 0; mf < 2; mf++) {
                int mrow = warp_o*32 + mf*16 + (lane & 15);
                int ch = kg*2 + (lane >> 4);
                unsigned aof = (unsigned)mrow*128 + (unsigned)((ch ^ (mrow & 7)) & 7)*16;
                ldsm4(aH[mf], wbase + aof);
                ldsm4(aL[mf], wbase + 16384u + aof);
            }
            int krB = kg*16 + khv*8 + r8;
#pragma unroll
            for (int nfp = 0; nfp < 4; nfp++) {
                unsigned bH4[4], bL4[4];
                int nch = warp_n*8 + nfp*2 + nsel;
                unsigned bof = (unsigned)krB*512 +
                               (unsigned)((nch & ~7) | ((nch ^ (krB & 7)) & 7))*16;
                ldsm4t(bH4, ibH + bof);
                ldsm4t(bL4, ibL + bof);
                // term-major order: same-acc MMAs at distance 4
#pragma unroll
                for (int h = 0; h < 2; h++)
#pragma unroll
                    for (int mf = 0; mf < 2; mf++)
                        mma16816(acc[mf][nfp*2+h], aH[mf], bH4 + 2*h);
#pragma unroll
                for (int h = 0; h < 2; h++)
#pragma unroll
                    for (int mf = 0; mf < 2; mf++)
                        mma16816(acc[mf][nfp*2+h], aH[mf], bL4 + 2*h);
#pragma unroll
                for (int h = 0; h < 2; h++)
#pragma unroll
                    for (int mf = 0; mf < 2; mf++)
                        mma16816(acc[mf][nfp*2+h], aL[mf], bH4 + 2*h);
            }
        }
        __syncthreads();
        if (kc + 2 < 4) {
            int c2 = (kc + 2) * 64;
            cv_fill_w(sb, kc & 1, gWh, gWl, o0, c2, tid);
            cv_fill_in(sb, kc & 1, inh, inl, inoff, c2, n0, tid);
            CP_COMMIT();
        }
    }

#pragma unroll
    for (int mf = 0; mf < 2; mf++) {
        int oA = o0 + warp_o*32 + mf*16 + qr;
        int oB = oA + 8;
        float bA = g_bf[layer*C_ + oA], bB = g_bf[layer*C_ + oB];
#pragma unroll
        for (int nf = 0; nf < 8; nf++) {
            int n = n0 + warp_n*64 + nf*8 + qc*2;
            float v0 = fmaxf(acc[mf][nf][0] + bA, 0.f) * oscale;
            float v1 = fmaxf(acc[mf][nf][1] + bA, 0.f) * oscale;
            float v2 = fmaxf(acc[mf][nf][2] + bB, 0.f) * oscale;
            float v3 = fmaxf(acc[mf][nf][3] + bB, 0.f) * oscale;
            size_t iA = inoff + (size_t)oA*NTOK + n, iB = inoff + (size_t)oB*NTOK + n;
            if (OUT_MODE == 0) {
                __half h0 = __float2half_rn(v0), h1 = __float2half_rn(v1);
                __half h2 = __float2half_rn(v2), h3 = __float2half_rn(v3);
                *(unsigned*)&oh[iA] = pack2us(__half_as_ushort(h0), __half_as_ushort(h1));
                *(unsigned*)&oh[iB] = pack2us(__half_as_ushort(h2), __half_as_ushort(h3));
                __half e0 = __float2half_rn(v0 - __half2float(h0));
                __half e1 = __float2half_rn(v1 - __half2float(h1));
                __half e2 = __float2half_rn(v2 - __half2float(h2));
                __half e3 = __float2half_rn(v3 - __half2float(h3));
                *(unsigned*)&ol[iA] = pack2us(__half_as_ushort(e0), __half_as_ushort(e1));
                *(unsigned*)&ol[iB] = pack2us(__half_as_ushort(e2), __half_as_ushort(e3));
            } else if (OUT_MODE == 1) {
                *(unsigned*)&oh[iA] = packh2(v0, v1);
                *(unsigned*)&oh[iB] = packh2(v2, v3);
            } else {
                *(float2*)&o32[iA] = make_float2(v0, v1);
                *(float2*)&o32[iB] = make_float2(v2, v3);
            }
        }
    }
}

// ---------------- pipelined HMMA flash attention (2-term QK, barrier-light) ----------------
// smem: QH[256c][128n] 64K | KH 32K | KL 32K | V 32K = 160K
#define SM_QH 0
#define SM_KH 65536
#define SM_KL 98304
#define SM_V  131072
#define SM_OL 65536
#define SMEM_ATTN 163840

__global__ void __launch_bounds__(256, 1) attn_mma(
    const unsigned short* __restrict__ qhg,
    const unsigned short* __restrict__ khg, const unsigned short* __restrict__ klg,
    const unsigned short* __restrict__ vhg,
    unsigned short* __restrict__ chg, unsigned short* __restrict__ clg)
{
    extern __shared__ char smem[];
    const unsigned sb = smem_u32(smem);
    const int tid = threadIdx.x, wid = tid >> 5, lane = tid & 31;
    const int n0 = blockIdx.x * TM;
    const size_t boff = (size_t)blockIdx.y * C_ * NTOK;
    const unsigned short* qh = qhg + boff;
    const unsigned short* kh = khg + boff;
    const unsigned short* kl = klg + boff;
    const unsigned short* vh = vhg + boff;

    const int m0w = wid * 16;
    const int qr = lane >> 2, qc = lane & 3;
    const int r8 = lane & 7, khv = (lane >> 3) & 1, nsel = (lane >> 4) & 1;

    // prologue: group1 = Q + K(0); group2 = V(0)
#pragma unroll
    for (int it = 0; it < 16; it++) {
        int idx = it*256 + tid;
        int row = idx >> 4, ch = idx & 15;
        size_t g = (size_t)row*NTOK + n0 + ch*8;
        unsigned d = sb + SM_QH + (unsigned)row*256 +
                     (unsigned)((ch & ~7) | ((ch ^ row) & 7))*16;
        cpa16(d, qh + g);
    }
#pragma unroll
    for (int it = 0; it < 8; it++) {
        int idx = it*256 + tid;
        int row = idx >> 3, ch = idx & 7;
        size_t g = (size_t)row*NTOK + 0 + ch*8;
        unsigned d = sb + SM_KH + (unsigned)row*128 + (unsigned)((ch ^ (row & 7)) & 7)*16;
        cpa16(d, kh + g);
        cpa16(d + (SM_KL - SM_KH), kl + g);
    }
    CP_COMMIT();
#pragma unroll
    for (int it = 0; it < 8; it++) {
        int idx = it*256 + tid;
        int row = idx >> 3, ch = idx & 7;
        unsigned d = sb + SM_V + (unsigned)row*128 + (unsigned)((ch ^ (row & 7)) & 7)*16;
        cpa16(d, vh + (size_t)row*NTOK + 0 + ch*8);
    }
    CP_COMMIT();

    float O[32][4];
#pragma unroll
    for (int i = 0; i < 32; i++) { O[i][0]=0.f; O[i][1]=0.f; O[i][2]=0.f; O[i][3]=0.f; }
    float mA = -1e30f, mB = -1e30f, lA = 0.f, lB = 0.f;

    for (int t = 0; t < NT; t++) {
        CP_WAIT1();              // K(t) [+Q at t=0] arrived; V(t) still in flight
        __syncthreads();         // K visible to all warps

        // ---- S = Qh Kᵀ (2-term k split, same-acc distance 2) ----
        float S[8][4];
#pragma unroll
        for (int i = 0; i < 8; i++) { S[i][0]=0.f; S[i][1]=0.f; S[i][2]=0.f; S[i][3]=0.f; }
#pragma unroll
        for (int kg = 0; kg < 16; kg++) {
            unsigned aH[4];
            int krA = kg*16 + ((lane >> 4) & 1)*8 + (lane & 7);
            int mch = wid*2 + ((lane >> 3) & 1);
            unsigned aof = (unsigned)krA*256 +
                           (unsigned)((mch & ~7) | ((mch ^ (krA & 7)) & 7))*16;
            ldsm4t(aH, sb + SM_QH + aof);
            int krB = kg*16 + khv*8 + r8;
#pragma unroll
            for (int ntp = 0; ntp < 4; ntp++) {
                unsigned bH4[4], bL4[4];
                int nt = ntp*2 + nsel;
                unsigned bof = (unsigned)krB*128 + (unsigned)((nt ^ (krB & 7)) & 7)*16;
                ldsm4t(bH4, sb + SM_KH + bof);
                ldsm4t(bL4, sb + SM_KL + bof);
                mma16816(S[2*ntp],   aH, bH4);
                mma16816(S[2*ntp+1], aH, bH4 + 2);
                mma16816(S[2*ntp],   aH, bL4);
                mma16816(S[2*ntp+1], aH, bL4 + 2);
            }
        }

        CP_WAIT0();              // V(t) arrived (only group left in flight)
        __syncthreads();         // V visible; all warps done with K smem

        if (t + 1 < NT) {        // prefetch K(t+1) — overlaps softmax + PV
            const int k1 = (t + 1) * TN;
#pragma unroll
            for (int it = 0; it < 8; it++) {
                int idx = it*256 + tid;
                int row = idx >> 3, ch = idx & 7;
                size_t g = (size_t)row*NTOK + k1 + ch*8;
                unsigned d = sb + SM_KH + (unsigned)row*128 + (unsigned)((ch ^ (row & 7)) & 7)*16;
                cpa16(d, kh + g);
                cpa16(d + (SM_KL - SM_KH), kl + g);
            }
            CP_COMMIT();
        }

        // ---- online softmax (no barrier until after PV: warps overlap) ----
        float mxA = -1e30f, mxB = -1e30f;
#pragma unroll
        for (int nt = 0; nt < 8; nt++) {
            mxA = fmaxf(mxA, fmaxf(S[nt][0], S[nt][1]));
            mxB = fmaxf(mxB, fmaxf(S[nt][2], S[nt][3]));
        }
        mxA = fmaxf(mxA, __shfl_xor_sync(0xffffffffu, mxA, 1));
        mxA = fmaxf(mxA, __shfl_xor_sync(0xffffffffu, mxA, 2));
        mxB = fmaxf(mxB, __shfl_xor_sync(0xffffffffu, mxB, 1));
        mxB = fmaxf(mxB, __shfl_xor_sync(0xffffffffu, mxB, 2));
        float mAn = fmaxf(mA, mxA), mBn = fmaxf(mB, mxB);
        float facA = ex2f(mA - mAn), facB = ex2f(mB - mBn);
        mA = mAn; mB = mBn;

        unsigned P[4][4];
        float sA = 0.f, sB = 0.f;
#pragma unroll
        for (int g = 0; g < 4; g++) {
#pragma unroll
            for (int h = 0; h < 2; h++) {
                int nt = 2*g + h;
                float e0 = ex2f(S[nt][0] - mAn), e1 = ex2f(S[nt][1] - mAn);
                float e2 = ex2f(S[nt][2] - mBn), e3 = ex2f(S[nt][3] - mBn);
                sA += e0 + e1; sB += e2 + e3;
                P[g][2*h]   = packh2(e0, e1);
                P[g][2*h+1] = packh2(e2, e3);
            }
        }
        sA += __shfl_xor_sync(0xffffffffu, sA, 1);
        sA += __shfl_xor_sync(0xffffffffu, sA, 2);
        sB += __shfl_xor_sync(0xffffffffu, sB, 1);
        sB += __shfl_xor_sync(0xffffffffu, sB, 2);
        lA = lA * facA + sA;
        lB = lB * facB + sB;
        bool nochg = (facA == 1.f) && (facB == 1.f);
        if (!__all_sync(0xffffffffu, nochg)) {
#pragma unroll
            for (int i = 0; i < 32; i++) {
                O[i][0] *= facA; O[i][1] *= facA; O[i][2] *= facB; O[i][3] *= facB;
            }
        }

        // ---- O += P V (V already visible; no barrier crossed) ----
#pragma unroll
        for (int jg = 0; jg < 4; jg++) {
#pragma unroll
            for (int ntp = 0; ntp < 16; ntp++) {
                unsigned bV4[4];
                int vrow = (ntp*2 + nsel)*8 + r8;
                int vch = 2*jg + khv;
                unsigned vof = (unsigned)vrow*128 + (unsigned)((vch ^ (vrow & 7)) & 7)*16;
                ldsm4(bV4, sb + SM_V + vof);
                mma16816(O[2*ntp],   P[jg], bV4);
                mma16816(O[2*ntp+1], P[jg], bV4 + 2);
            }
        }

        if (t + 1 < NT) {
            __syncthreads();     // all warps done reading V(t)
            const int k1 = (t + 1) * TN;
#pragma unroll
            for (int it = 0; it < 8; it++) {
                int idx = it*256 + tid;
                int row = idx >> 3, ch = idx & 7;
                unsigned d = sb + SM_V + (unsigned)row*128 + (unsigned)((ch ^ (row & 7)) & 7)*16;
                cpa16(d, vh + (size_t)row*NTOK + k1 + ch*8);
            }
            CP_COMMIT();
        }
    }

    // ---- epilogue: stage split O planes (hi @QH, lo @OL), copy out coalesced ----
    float iA = 1.f / lA, iB = 1.f / lB;
    const int nlA = m0w + qr, nlB = nlA + 8;
    __syncthreads();
#pragma unroll
    for (int nt = 0; nt < 32; nt++) {
        int c = nt*8 + qc*2;
        float v0 = O[nt][0]*iA, v1 = O[nt][1]*iA, v2 = O[nt][2]*iB, v3 = O[nt][3]*iB;
        __half h0 = __float2half_rn(v0), h1 = __float2half_rn(v1);
        __half h2 = __float2half_rn(v2), h3 = __float2half_rn(v3);
        __half e0 = __float2half_rn(v0 - __half2float(h0));
        __half e1 = __float2half_rn(v1 - __half2float(h1));
        __half e2 = __float2half_rn(v2 - __half2float(h2));
        __half e3 = __float2half_rn(v3 - __half2float(h3));
        *(unsigned short*)(smem + SM_QH + (c  )*256 + nlA*2) = __half_as_ushort(h0);
        *(unsigned short*)(smem + SM_QH + (c+1)*256 + nlA*2) = __half_as_ushort(h1);
        *(unsigned short*)(smem + SM_QH + (c  )*256 + nlB*2) = __half_as_ushort(h2);
        *(unsigned short*)(smem + SM_QH + (c+1)*256 + nlB*2) = __half_as_ushort(h3);
        *(unsigned short*)(smem + SM_OL + (c  )*256 + nlA*2) = __half_as_ushort(e0);
        *(unsigned short*)(smem + SM_OL + (c+1)*256 + nlA*2) = __half_as_ushort(e1);
        *(unsigned short*)(smem + SM_OL + (c  )*256 + nlB*2) = __half_as_ushort(e2);
        *(unsigned short*)(smem + SM_OL + (c+1)*256 + nlB*2) = __half_as_ushort(e3);
    }
    __syncthreads();
    unsigned short* cho = chg + boff;
    unsigned short* clo = clg + boff;
#pragma unroll
    for (int it = 0; it < 16; it++) {
        int idx = it*256 + tid;
        int row = idx >> 4, ch = idx & 15;
        uint4 vH = *(uint4*)(smem + SM_QH + row*256 + ch*16);
        uint4 vL = *(uint4*)(smem + SM_OL + row*256 + ch*16);
        *(uint4*)&cho[(size_t)row*NTOK + n0 + ch*8] = vH;
        *(uint4*)&clo[(size_t)row*NTOK + n0 + ch*8] = vL;
    }
}

// ---------------- launch ----------------
extern "C" void kernel_launch(void* const* d_in, const int* in_sizes, int n_in,
                              void* d_out, int out_size) {
    const float* x   = (const float*)d_in[0];
    const float* fk  = (const float*)d_in[1];
    const float* Ws  = (const float*)d_in[2];
    const float* gam = (const float*)d_in[3];
    const float* bet = (const float*)d_in[4];
    const float* mu  = (const float*)d_in[5];
    const float* var = (const float*)d_in[6];
    float* out = (float*)d_out;

    unsigned short *t1h, *t1l, *qh, *kh, *kl, *vh, *ch, *cl;
    cudaGetSymbolAddress((void**)&t1h, g_t1h);
    cudaGetSymbolAddress((void**)&t1l, g_t1l);
    cudaGetSymbolAddress((void**)&qh,  g_qh);
    cudaGetSymbolAddress((void**)&kh,  g_kh);
    cudaGetSymbolAddress((void**)&kl,  g_kl);
    cudaGetSymbolAddress((void**)&vh,  g_vh);
    cudaGetSymbolAddress((void**)&ch,  g_ch);
    cudaGetSymbolAddress((void**)&cl,  g_cl);

    cudaFuncSetAttribute(conv_hmma<0>, cudaFuncAttributeMaxDynamicSharedMemorySize, CV_SMEM);
    cudaFuncSetAttribute(conv_hmma<1>, cudaFuncAttributeMaxDynamicSharedMemorySize, CV_SMEM);
    cudaFuncSetAttribute(conv_hmma<2>, cudaFuncAttributeMaxDynamicSharedMemorySize, CV_SMEM);
    cudaFuncSetAttribute(attn_mma, cudaFuncAttributeMaxDynamicSharedMemorySize, SMEM_ATTN);

    prep_kernel<<<L_, 256>>>(Ws, gam, bet, mu, var);
    split2<<<(2*NELEM)/(256*4), 256>>>(x, fk, ch, cl, kh, kl);

    dim3 cgrid(NTOK/256, C_/128, B_);
    conv_hmma<0><<<cgrid, 512, CV_SMEM>>>(ch, cl,  nullptr, t1h, t1l, 0, 1.0f);      // psi1
    conv_hmma<1><<<cgrid, 512, CV_SMEM>>>(t1h, t1l, nullptr, qh, nullptr, 1, LOG2E); // psi2 -> q
    conv_hmma<0><<<cgrid, 512, CV_SMEM>>>(kh, kl,  nullptr, t1h, t1l, 2, 1.0f);      // phi1
    conv_hmma<1><<<cgrid, 512, CV_SMEM>>>(kh, kl,  nullptr, vh, nullptr, 4, 1.0f);   // f_down -> v
    conv_hmma<0><<<cgrid, 512, CV_SMEM>>>(t1h, t1l, nullptr, kh, kl, 3, 1.0f);       // phi2 -> k

    attn_mma<<<dim3(NQT, B_), 256, SMEM_ATTN>>>(qh, kh, kl, vh, ch, cl);

    conv_hmma<2><<<cgrid, 512, CV_SMEM>>>(ch, cl, out, nullptr, nullptr, 5, 1.0f);   // f_up
}

// round 15
// speedup vs baseline: 11.4718x; 1.0045x over previous
#include <cuda_runtime.h>
#include <cuda_fp16.h>
#include <math.h>

#define B_    2
#define C_    256
#define NTOK  9216
#define L_    6
#define TM    128
#define TN    64
#define NT    (NTOK/TN)     // 144
#define NQT   (NTOK/TM)     // 72
#define LOG2E 1.4426950408889634f

// ---------------- scratch ----------------
__device__ unsigned short g_Wh[L_*C_*C_], g_Wl[L_*C_*C_];
__device__ float          g_bf[L_*C_];
__device__ unsigned short g_t1h[B_*C_*NTOK], g_t1l[B_*C_*NTOK];
__device__ unsigned short g_t2h[B_*C_*NTOK], g_t2l[B_*C_*NTOK];
__device__ unsigned short g_fkh[B_*C_*NTOK], g_fkl[B_*C_*NTOK];
__device__ unsigned short g_qh [B_*C_*NTOK];
__device__ unsigned short g_kh [B_*C_*NTOK], g_kl [B_*C_*NTOK];
__device__ unsigned short g_vh [B_*C_*NTOK];
__device__ unsigned short g_ch [B_*C_*NTOK], g_cl [B_*C_*NTOK];

// ---------------- helpers ----------------
__device__ __forceinline__ unsigned smem_u32(const void* p) {
    unsigned a;
    asm("{ .reg .u64 t; cvta.to.shared.u64 t, %1; cvt.u32.u64 %0, t; }" : "=r"(a) : "l"(p));
    return a;
}
__device__ __forceinline__ void cpa16(unsigned dst, const void* src) {
    asm volatile("cp.async.cg.shared.global [%0], [%1], 16;" :: "r"(dst), "l"(src));
}
#define CP_COMMIT() asm volatile("cp.async.commit_group;" ::: "memory")
#define CP_WAIT0()  asm volatile("cp.async.wait_group 0;" ::: "memory")
#define CP_WAIT1()  asm volatile("cp.async.wait_group 1;" ::: "memory")

__device__ __forceinline__ void ldsm4(unsigned* r, unsigned a) {
    asm volatile("ldmatrix.sync.aligned.m8n8.x4.shared.b16 {%0,%1,%2,%3}, [%4];"
        : "=r"(r[0]), "=r"(r[1]), "=r"(r[2]), "=r"(r[3]) : "r"(a));
}
__device__ __forceinline__ void ldsm4t(unsigned* r, unsigned a) {
    asm volatile("ldmatrix.sync.aligned.m8n8.x4.trans.shared.b16 {%0,%1,%2,%3}, [%4];"
        : "=r"(r[0]), "=r"(r[1]), "=r"(r[2]), "=r"(r[3]) : "r"(a));
}
__device__ __forceinline__ void mma16816(float* c, const unsigned* a, const unsigned* b) {
    asm volatile("mma.sync.aligned.m16n8k16.row.col.f32.f16.f16.f32 "
        "{%0,%1,%2,%3}, {%4,%5,%6,%7}, {%8,%9}, {%0,%1,%2,%3};"
        : "+f"(c[0]), "+f"(c[1]), "+f"(c[2]), "+f"(c[3])
        : "r"(a[0]), "r"(a[1]), "r"(a[2]), "r"(a[3]), "r"(b[0]), "r"(b[1]));
}
__device__ __forceinline__ float ex2f(float x) {
    float r; asm("ex2.approx.f32 %0, %1;" : "=f"(r) : "f"(x)); return r;
}
__device__ __forceinline__ unsigned ex2h2(unsigned a) {
    unsigned d; asm("ex2.approx.f16x2 %0, %1;" : "=r"(d) : "r"(a)); return d;
}
__device__ __forceinline__ unsigned hadd2u(unsigned a, unsigned b) {
    unsigned d; asm("add.f16x2 %0, %1, %2;" : "=r"(d) : "r"(a), "r"(b)); return d;
}
__device__ __forceinline__ unsigned packh2(float lo, float hi) {
    unsigned d;
    asm("cvt.rn.f16x2.f32 %0, %1, %2;" : "=r"(d) : "f"(hi), "f"(lo));
    return d;
}
__device__ __forceinline__ float h2sum(unsigned u) {
    __half2 h = *(__half2*)&u;
    return __low2float(h) + __high2float(h);
}
__device__ __forceinline__ unsigned pack2us(unsigned short a, unsigned short b) {
    return (unsigned)a | ((unsigned)b << 16);
}

// ---------------- prep: fold BN, split W into fp16 planes ----------------
__global__ void prep_kernel(const float* __restrict__ Ws, const float* __restrict__ gam,
                            const float* __restrict__ bet, const float* __restrict__ mu,
                            const float* __restrict__ var) {
    int l = blockIdx.x, tid = threadIdx.x;
    __shared__ float sc[C_];
    float s = gam[l*C_+tid] * rsqrtf(var[l*C_+tid] + 1e-5f);
    sc[tid] = s;
    g_bf[l*C_+tid] = bet[l*C_+tid] - mu[l*C_+tid]*s;
    __syncthreads();
    const float* Wl = Ws + l*C_*C_;
    for (int t = tid; t < C_*C_; t += blockDim.x) {
        float wf = Wl[t] * sc[t >> 8];
        __half h = __float2half_rn(wf);
        __half lo = __float2half_rn(wf - __half2float(h));
        g_Wh[l*C_*C_ + t] = __half_as_ushort(h);
        g_Wl[l*C_*C_ + t] = __half_as_ushort(lo);
    }
}

// ---------------- split both fp32 inputs -> fp16 hi/lo planes ----------------
#define NELEM (B_*C_*NTOK)
__global__ void __launch_bounds__(256) split2(const float* __restrict__ a, const float* __restrict__ b,
                                              unsigned short* __restrict__ ah, unsigned short* __restrict__ al,
                                              unsigned short* __restrict__ bh, unsigned short* __restrict__ bl) {
    size_t i = ((size_t)blockIdx.x*256 + threadIdx.x) * 4;
    const float* src; unsigned short *oh, *ol;
    if (i < (size_t)NELEM) { src = a; oh = ah; ol = al; }
    else { i -= NELEM; src = b; oh = bh; ol = bl; }
    float4 w = *(const float4*)(src + i);
    __half h0 = __float2half_rn(w.x), h1 = __float2half_rn(w.y);
    __half h2 = __float2half_rn(w.z), h3 = __float2half_rn(w.w);
    __half l0 = __float2half_rn(w.x - __half2float(h0));
    __half l1 = __float2half_rn(w.y - __half2float(h1));
    __half l2 = __float2half_rn(w.z - __half2float(h2));
    __half l3 = __float2half_rn(w.w - __half2float(h3));
    uint2 vh, vl;
    vh.x = pack2us(__half_as_ushort(h0), __half_as_ushort(h1));
    vh.y = pack2us(__half_as_ushort(h2), __half_as_ushort(h3));
    vl.x = pack2us(__half_as_ushort(l0), __half_as_ushort(l1));
    vl.y = pack2us(__half_as_ushort(l2), __half_as_ushort(l3));
    *(uint2*)(oh + i) = vh;
    *(uint2*)(ol + i) = vl;
}

// ---------------- HMMA convbn+relu: multi-op launch, depth-2 pipelined W+IN ----------------
struct ConvOp {
    const unsigned short *inh, *inl;
    float *o32; unsigned short *oh, *ol;
    int layer; float oscale;
};

#define CV_IN0  65536
#define CV_SMEM 196608

__device__ __forceinline__ void cv_fill_w(unsigned sb, int st, const unsigned short* gWh,
                                          const unsigned short* gWl, int o0, int c0k, int tid) {
    unsigned wbase = sb + (unsigned)st * 32768u;
#pragma unroll
    for (int it = 0; it < 2; it++) {
        int idx = it*512 + tid;
        int row = idx >> 3, ch = idx & 7;
        size_t g = (size_t)(o0 + row)*C_ + c0k + ch*8;
        unsigned d = wbase + (unsigned)row*128 + (unsigned)((ch ^ (row & 7)) & 7)*16;
        cpa16(d, gWh + g);
        cpa16(d + 16384, gWl + g);
    }
}
__device__ __forceinline__ void cv_fill_in(unsigned sb, int st, const unsigned short* inh,
                                           const unsigned short* inl, size_t inoff, int c0k,
                                           int n0, int tid) {
    unsigned ibase = sb + CV_IN0 + (unsigned)st * 65536u;
#pragma unroll
    for (int it = 0; it < 4; it++) {
        int idx = it*512 + tid;
        int row = idx >> 5, ch = idx & 31;
        size_t g = inoff + (size_t)(c0k + row)*NTOK + n0 + ch*8;
        unsigned d = ibase + (unsigned)row*512 +
                     (unsigned)((ch & ~7) | ((ch ^ row) & 7))*16;
        cpa16(d, inh + g);
        cpa16(d + 32768, inl + g);
    }
}

__global__ void __launch_bounds__(512, 1) conv_multi(ConvOp opA, ConvOp opB, ConvOp opC) {
    extern __shared__ char cs[];
    const unsigned sb = smem_u32(cs);
    const int tid = threadIdx.x, wid = tid >> 5, lane = tid & 31;
    const int n0 = blockIdx.x * 256;
    const int o0 = blockIdx.y * 128;
    const int opi = blockIdx.z >> 1;
    const int bz = blockIdx.z & 1;
    const ConvOp op = (opi == 0) ? opA : ((opi == 1) ? opB : opC);
    const int warp_o = wid & 3, warp_n = wid >> 2;
    const int qr = lane >> 2, qc = lane & 3;
    const int r8 = lane & 7, khv = (lane >> 3) & 1, nsel = (lane >> 4) & 1;
    const size_t inoff = (size_t)bz * C_ * NTOK;

    float acc[2][8][4];
#pragma unroll
    for (int mf = 0; mf < 2; mf++)
#pragma unroll
        for (int nf = 0; nf < 8; nf++)
#pragma unroll
            for (int u = 0; u < 4; u++) acc[mf][nf][u] = 0.f;

    const unsigned short* gWh = g_Wh + (size_t)op.layer*C_*C_;
    const unsigned short* gWl = g_Wl + (size_t)op.layer*C_*C_;

    cv_fill_w(sb, 0, gWh, gWl, o0, 0, tid);
    cv_fill_in(sb, 0, op.inh, op.inl, inoff, 0, n0, tid);
    CP_COMMIT();
    cv_fill_w(sb, 1, gWh, gWl, o0, 64, tid);
    cv_fill_in(sb, 1, op.inh, op.inl, inoff, 64, n0, tid);
    CP_COMMIT();

    for (int kc = 0; kc < 4; kc++) {
        if (kc < 3) { CP_WAIT1(); } else { CP_WAIT0(); }
        __syncthreads();
        const unsigned wbase = sb + (unsigned)(kc & 1) * 32768u;
        const unsigned ibH = sb + CV_IN0 + (unsigned)(kc & 1) * 65536u;
        const unsigned ibL = ibH + 32768u;
#pragma unroll
        for (int kg = 0; kg < 4; kg++) {
            unsigned aH[2][4], aL[2][4];
#pragma unroll
            for (int mf = 0; mf < 2; mf++) {
                int mrow = warp_o*32 + mf*16 + (lane & 15);
                int ch = kg*2 + (lane >> 4);
                unsigned aof = (unsigned)mrow*128 + (unsigned)((ch ^ (mrow & 7)) & 7)*16;
                ldsm4(aH[mf], wbase + aof);
                ldsm4(aL[mf], wbase + 16384u + aof);
            }
            int krB = kg*16 + khv*8 + r8;
#pragma unroll
            for (int nfp = 0; nfp < 4; nfp++) {
                unsigned bH4[4], bL4[4];
                int nch = warp_n*8 + nfp*2 + nsel;
                unsigned bof = (unsigned)krB*512 +
                               (unsigned)((nch & ~7) | ((nch ^ (krB & 7)) & 7))*16;
                ldsm4t(bH4, ibH + bof);
                ldsm4t(bL4, ibL + bof);
#pragma unroll
                for (int h = 0; h < 2; h++)
#pragma unroll
                    for (int mf = 0; mf < 2; mf++)
                        mma16816(acc[mf][nfp*2+h], aH[mf], bH4 + 2*h);
#pragma unroll
                for (int h = 0; h < 2; h++)
#pragma unroll
                    for (int mf = 0; mf < 2; mf++)
                        mma16816(acc[mf][nfp*2+h], aH[mf], bL4 + 2*h);
#pragma unroll
                for (int h = 0; h < 2; h++)
#pragma unroll
                    for (int mf = 0; mf < 2; mf++)
                        mma16816(acc[mf][nfp*2+h], aL[mf], bH4 + 2*h);
            }
        }
        __syncthreads();
        if (kc + 2 < 4) {
            int c2 = (kc + 2) * 64;
            cv_fill_w(sb, kc & 1, gWh, gWl, o0, c2, tid);
            cv_fill_in(sb, kc & 1, op.inh, op.inl, inoff, c2, n0, tid);
            CP_COMMIT();
        }
    }

#pragma unroll
    for (int mf = 0; mf < 2; mf++) {
        int oA = o0 + warp_o*32 + mf*16 + qr;
        int oB = oA + 8;
        float bA = g_bf[op.layer*C_ + oA], bB = g_bf[op.layer*C_ + oB];
#pragma unroll
        for (int nf = 0; nf < 8; nf++) {
            int n = n0 + warp_n*64 + nf*8 + qc*2;
            float v0 = fmaxf(acc[mf][nf][0] + bA, 0.f) * op.oscale;
            float v1 = fmaxf(acc[mf][nf][1] + bA, 0.f) * op.oscale;
            float v2 = fmaxf(acc[mf][nf][2] + bB, 0.f) * op.oscale;
            float v3 = fmaxf(acc[mf][nf][3] + bB, 0.f) * op.oscale;
            size_t iA = inoff + (size_t)oA*NTOK + n, iB = inoff + (size_t)oB*NTOK + n;
            if (op.ol) {
                __half h0 = __float2half_rn(v0), h1 = __float2half_rn(v1);
                __half h2 = __float2half_rn(v2), h3 = __float2half_rn(v3);
                *(unsigned*)&op.oh[iA] = pack2us(__half_as_ushort(h0), __half_as_ushort(h1));
                *(unsigned*)&op.oh[iB] = pack2us(__half_as_ushort(h2), __half_as_ushort(h3));
                __half e0 = __float2half_rn(v0 - __half2float(h0));
                __half e1 = __float2half_rn(v1 - __half2float(h1));
                __half e2 = __float2half_rn(v2 - __half2float(h2));
                __half e3 = __float2half_rn(v3 - __half2float(h3));
                *(unsigned*)&op.ol[iA] = pack2us(__half_as_ushort(e0), __half_as_ushort(e1));
                *(unsigned*)&op.ol[iB] = pack2us(__half_as_ushort(e2), __half_as_ushort(e3));
            } else if (op.oh) {
                *(unsigned*)&op.oh[iA] = packh2(v0, v1);
                *(unsigned*)&op.oh[iB] = packh2(v2, v3);
            } else {
                *(float2*)&op.o32[iA] = make_float2(v0, v1);
                *(float2*)&op.o32[iB] = make_float2(v2, v3);
            }
        }
    }
}

// ---------------- pipelined HMMA flash attention (2-term QK, f16x2 softmax) ----------------
#define SM_QH 0
#define SM_KH 65536
#define SM_KL 98304
#define SM_V  131072
#define SM_OL 65536
#define SMEM_ATTN 163840

__global__ void __launch_bounds__(256, 1) attn_mma(
    const unsigned short* __restrict__ qhg,
    const unsigned short* __restrict__ khg, const unsigned short* __restrict__ klg,
    const unsigned short* __restrict__ vhg,
    unsigned short* __restrict__ chg, unsigned short* __restrict__ clg)
{
    extern __shared__ char smem[];
    const unsigned sb = smem_u32(smem);
    const int tid = threadIdx.x, wid = tid >> 5, lane = tid & 31;
    const int n0 = blockIdx.x * TM;
    const size_t boff = (size_t)blockIdx.y * C_ * NTOK;
    const unsigned short* qh = qhg + boff;
    const unsigned short* kh = khg + boff;
    const unsigned short* kl = klg + boff;
    const unsigned short* vh = vhg + boff;

    const int m0w = wid * 16;
    const int qr = lane >> 2, qc = lane & 3;
    const int r8 = lane & 7, khv = (lane >> 3) & 1, nsel = (lane >> 4) & 1;

    // prologue: group1 = Q + K(0); group2 = V(0)
#pragma unroll
    for (int it = 0; it < 16; it++) {
        int idx = it*256 + tid;
        int row = idx >> 4, ch = idx & 15;
        size_t g = (size_t)row*NTOK + n0 + ch*8;
        unsigned d = sb + SM_QH + (unsigned)row*256 +
                     (unsigned)((ch & ~7) | ((ch ^ row) & 7))*16;
        cpa16(d, qh + g);
    }
#pragma unroll
    for (int it = 0; it < 8; it++) {
        int idx = it*256 + tid;
        int row = idx >> 3, ch = idx & 7;
        size_t g = (size_t)row*NTOK + 0 + ch*8;
        unsigned d = sb + SM_KH + (unsigned)row*128 + (unsigned)((ch ^ (row & 7)) & 7)*16;
        cpa16(d, kh + g);
        cpa16(d + (SM_KL - SM_KH), kl + g);
    }
    CP_COMMIT();
#pragma unroll
    for (int it = 0; it < 8; it++) {
        int idx = it*256 + tid;
        int row = idx >> 3, ch = idx & 7;
        unsigned d = sb + SM_V + (unsigned)row*128 + (unsigned)((ch ^ (row & 7)) & 7)*16;
        cpa16(d, vh + (size_t)row*NTOK + 0 + ch*8);
    }
    CP_COMMIT();

    float O[32][4];
#pragma unroll
    for (int i = 0; i < 32; i++) { O[i][0]=0.f; O[i][1]=0.f; O[i][2]=0.f; O[i][3]=0.f; }
    float mA = -1e30f, mB = -1e30f, lA = 0.f, lB = 0.f;

    for (int t = 0; t < NT; t++) {
        CP_WAIT1();              // K(t) [+Q at t=0] arrived
        __syncthreads();

        // ---- S = Qh Kᵀ (2-term k split, same-acc distance 2) ----
        float S[8][4];
#pragma unroll
        for (int i = 0; i < 8; i++) { S[i][0]=0.f; S[i][1]=0.f; S[i][2]=0.f; S[i][3]=0.f; }
#pragma unroll
        for (int kg = 0; kg < 16; kg++) {
            unsigned aH[4];
            int krA = kg*16 + ((lane >> 4) & 1)*8 + (lane & 7);
            int mch = wid*2 + ((lane >> 3) & 1);
            unsigned aof = (unsigned)krA*256 +
                           (unsigned)((mch & ~7) | ((mch ^ (krA & 7)) & 7))*16;
            ldsm4t(aH, sb + SM_QH + aof);
            int krB = kg*16 + khv*8 + r8;
#pragma unroll
            for (int ntp = 0; ntp < 4; ntp++) {
                unsigned bH4[4], bL4[4];
                int nt = ntp*2 + nsel;
                unsigned bof = (unsigned)krB*128 + (unsigned)((nt ^ (krB & 7)) & 7)*16;
                ldsm4t(bH4, sb + SM_KH + bof);
                ldsm4t(bL4, sb + SM_KL + bof);
                mma16816(S[2*ntp],   aH, bH4);
                mma16816(S[2*ntp+1], aH, bH4 + 2);
                mma16816(S[2*ntp],   aH, bL4);
                mma16816(S[2*ntp+1], aH, bL4 + 2);
            }
        }

        CP_WAIT0();              // V(t) arrived
        __syncthreads();         // V visible; K smem free

        if (t + 1 < NT) {        // prefetch K(t+1) — overlaps softmax + PV
            const int k1 = (t + 1) * TN;
#pragma unroll
            for (int it = 0; it < 8; it++) {
                int idx = it*256 + tid;
                int row = idx >> 3, ch = idx & 7;
                size_t g = (size_t)row*NTOK + k1 + ch*8;
                unsigned d = sb + SM_KH + (unsigned)row*128 + (unsigned)((ch ^ (row & 7)) & 7)*16;
                cpa16(d, kh + g);
                cpa16(d + (SM_KL - SM_KH), kl + g);
            }
            CP_COMMIT();
        }

        // ---- online softmax (f16x2 exp path) ----
        float mxA = -1e30f, mxB = -1e30f;
#pragma unroll
        for (int nt = 0; nt < 8; nt++) {
            mxA = fmaxf(mxA, fmaxf(S[nt][0], S[nt][1]));
            mxB = fmaxf(mxB, fmaxf(S[nt][2], S[nt][3]));
        }
        mxA = fmaxf(mxA, __shfl_xor_sync(0xffffffffu, mxA, 1));
        mxA = fmaxf(mxA, __shfl_xor_sync(0xffffffffu, mxA, 2));
        mxB = fmaxf(mxB, __shfl_xor_sync(0xffffffffu, mxB, 1));
        mxB = fmaxf(mxB, __shfl_xor_sync(0xffffffffu, mxB, 2));
        float mAn = fmaxf(mA, mxA), mBn = fmaxf(mB, mxB);
        float facA = ex2f(mA - mAn), facB = ex2f(mB - mBn);
        mA = mAn; mB = mBn;

        unsigned P[4][4];
        unsigned accA0 = 0, accA1 = 0, accB0 = 0, accB1 = 0;   // +0.0 | +0.0
#pragma unroll
        for (int g = 0; g < 4; g++) {
#pragma unroll
            for (int h = 0; h < 2; h++) {
                int nt = 2*g + h;
                unsigned pA = packh2(S[nt][0] - mAn, S[nt][1] - mAn);
                unsigned pB = packh2(S[nt][2] - mBn, S[nt][3] - mBn);
                unsigned eA = ex2h2(pA), eB = ex2h2(pB);
                P[g][2*h]   = eA;
                P[g][2*h+1] = eB;
                if (h == 0) { accA0 = hadd2u(accA0, eA); accB0 = hadd2u(accB0, eB); }
                else        { accA1 = hadd2u(accA1, eA); accB1 = hadd2u(accB1, eB); }
            }
        }
        float sA = h2sum(hadd2u(accA0, accA1));
        float sB = h2sum(hadd2u(accB0, accB1));
        sA += __shfl_xor_sync(0xffffffffu, sA, 1);
        sA += __shfl_xor_sync(0xffffffffu, sA, 2);
        sB += __shfl_xor_sync(0xffffffffu, sB, 1);
        sB += __shfl_xor_sync(0xffffffffu, sB, 2);
        lA = lA * facA + sA;
        lB = lB * facB + sB;
        bool nochg = (facA == 1.f) && (facB == 1.f);
        if (!__all_sync(0xffffffffu, nochg)) {
#pragma unroll
            for (int i = 0; i < 32; i++) {
                O[i][0] *= facA; O[i][1] *= facA; O[i][2] *= facB; O[i][3] *= facB;
            }
        }

        // ---- O += P V ----
#pragma unroll
        for (int jg = 0; jg < 4; jg++) {
#pragma unroll
            for (int ntp = 0; ntp < 16; ntp++) {
                unsigned bV4[4];
                int vrow = (ntp*2 + nsel)*8 + r8;
                int vch = 2*jg + khv;
                unsigned vof = (unsigned)vrow*128 + (unsigned)((vch ^ (vrow & 7)) & 7)*16;
                ldsm4(bV4, sb + SM_V + vof);
                mma16816(O[2*ntp],   P[jg], bV4);
                mma16816(O[2*ntp+1], P[jg], bV4 + 2);
            }
        }

        if (t + 1 < NT) {
            __syncthreads();     // all warps done reading V(t)
            const int k1 = (t + 1) * TN;
#pragma unroll
            for (int it = 0; it < 8; it++) {
                int idx = it*256 + tid;
                int row = idx >> 3, ch = idx & 7;
                unsigned d = sb + SM_V + (unsigned)row*128 + (unsigned)((ch ^ (row & 7)) & 7)*16;
                cpa16(d, vh + (size_t)row*NTOK + k1 + ch*8);
            }
            CP_COMMIT();
        }
    }

    // ---- epilogue: stage split O planes, copy out coalesced ----
    float iA = 1.f / lA, iB = 1.f / lB;
    const int nlA = m0w + qr, nlB = nlA + 8;
    __syncthreads();
#pragma unroll
    for (int nt = 0; nt < 32; nt++) {
        int c = nt*8 + qc*2;
        float v0 = O[nt][0]*iA, v1 = O[nt][1]*iA, v2 = O[nt][2]*iB, v3 = O[nt][3]*iB;
        __half h0 = __float2half_rn(v0), h1 = __float2half_rn(v1);
        __half h2 = __float2half_rn(v2), h3 = __float2half_rn(v3);
        __half e0 = __float2half_rn(v0 - __half2float(h0));
        __half e1 = __float2half_rn(v1 - __half2float(h1));
        __half e2 = __float2half_rn(v2 - __half2float(h2));
        __half e3 = __float2half_rn(v3 - __half2float(h3));
        *(unsigned short*)(smem + SM_QH + (c  )*256 + nlA*2) = __half_as_ushort(h0);
        *(unsigned short*)(smem + SM_QH + (c+1)*256 + nlA*2) = __half_as_ushort(h1);
        *(unsigned short*)(smem + SM_QH + (c  )*256 + nlB*2) = __half_as_ushort(h2);
        *(unsigned short*)(smem + SM_QH + (c+1)*256 + nlB*2) = __half_as_ushort(h3);
        *(unsigned short*)(smem + SM_OL + (c  )*256 + nlA*2) = __half_as_ushort(e0);
        *(unsigned short*)(smem + SM_OL + (c+1)*256 + nlA*2) = __half_as_ushort(e1);
        *(unsigned short*)(smem + SM_OL + (c  )*256 + nlB*2) = __half_as_ushort(e2);
        *(unsigned short*)(smem + SM_OL + (c+1)*256 + nlB*2) = __half_as_ushort(e3);
    }
    __syncthreads();
    unsigned short* cho = chg + boff;
    unsigned short* clo = clg + boff;
#pragma unroll
    for (int it = 0; it < 16; it++) {
        int idx = it*256 + tid;
        int row = idx >> 4, ch = idx & 15;
        uint4 vH = *(uint4*)(smem + SM_QH + row*256 + ch*16);
        uint4 vL = *(uint4*)(smem + SM_OL + row*256 + ch*16);
        *(uint4*)&cho[(size_t)row*NTOK + n0 + ch*8] = vH;
        *(uint4*)&clo[(size_t)row*NTOK + n0 + ch*8] = vL;
    }
}

// ---------------- launch ----------------
extern "C" void kernel_launch(void* const* d_in, const int* in_sizes, int n_in,
                              void* d_out, int out_size) {
    const float* x   = (const float*)d_in[0];
    const float* fk  = (const float*)d_in[1];
    const float* Ws  = (const float*)d_in[2];
    const float* gam = (const float*)d_in[3];
    const float* bet = (const float*)d_in[4];
    const float* mu  = (const float*)d_in[5];
    const float* var = (const float*)d_in[6];
    float* out = (float*)d_out;

    unsigned short *t1h, *t1l, *t2h, *t2l, *fkh, *fkl, *qh, *kh, *kl, *vh, *ch, *cl;
    cudaGetSymbolAddress((void**)&t1h, g_t1h);
    cudaGetSymbolAddress((void**)&t1l, g_t1l);
    cudaGetSymbolAddress((void**)&t2h, g_t2h);
    cudaGetSymbolAddress((void**)&t2l, g_t2l);
    cudaGetSymbolAddress((void**)&fkh, g_fkh);
    cudaGetSymbolAddress((void**)&fkl, g_fkl);
    cudaGetSymbolAddress((void**)&qh,  g_qh);
    cudaGetSymbolAddress((void**)&kh,  g_kh);
    cudaGetSymbolAddress((void**)&kl,  g_kl);
    cudaGetSymbolAddress((void**)&vh,  g_vh);
    cudaGetSymbolAddress((void**)&ch,  g_ch);
    cudaGetSymbolAddress((void**)&cl,  g_cl);

    cudaFuncSetAttribute(conv_multi, cudaFuncAttributeMaxDynamicSharedMemorySize, CV_SMEM);
    cudaFuncSetAttribute(attn_mma, cudaFuncAttributeMaxDynamicSharedMemorySize, SMEM_ATTN);

    prep_kernel<<<L_, 256>>>(Ws, gam, bet, mu, var);
    split2<<<(2*NELEM)/(256*4), 256>>>(x, fk, ch, cl, fkh, fkl);

    ConvOp nop = {};
    // level A: psi1 (x->t1), phi1 (fk->t2)
    ConvOp a0 = {ch,  cl,  nullptr, t1h, t1l, 0, 1.0f};
    ConvOp a1 = {fkh, fkl, nullptr, t2h, t2l, 2, 1.0f};
    conv_multi<<<dim3(NTOK/256, C_/128, 2*B_), 512, CV_SMEM>>>(a0, a1, nop);
    // level B: psi2 (t1->q), phi2 (t2->k), f_down (fk->v)
    ConvOp b0 = {t1h, t1l, nullptr, qh, nullptr, 1, LOG2E};
    ConvOp b1 = {t2h, t2l, nullptr, kh, kl,      3, 1.0f};
    ConvOp b2 = {fkh, fkl, nullptr, vh, nullptr, 4, 1.0f};
    conv_multi<<<dim3(NTOK/256, C_/128, 3*B_), 512, CV_SMEM>>>(b0, b1, b2);

    attn_mma<<<dim3(NQT, B_), 256, SMEM_ATTN>>>(qh, kh, kl, vh, ch, cl);

    // f_up (ctx->out fp32)
    ConvOp f0 = {ch, cl, out, nullptr, nullptr, 5, 1.0f};
    conv_multi<<<dim3(NTOK/256, C_/128, B_), 512, CV_SMEM>>>(f0, nop, nop);
}

// round 16
// speedup vs baseline: 14.5503x; 1.2684x over previous
#include <cuda_runtime.h>
#include <cuda_fp16.h>
#include <math.h>

#define B_    2
#define C_    256
#define NTOK  9216
#define L_    6
#define TM    128
#define TN    64
#define NT    (NTOK/TN)     // 144
#define NQT   (NTOK/TM)     // 72
#define LOG2E 1.4426950408889634f

// ---------------- scratch ----------------
__device__ unsigned short g_Wh[L_*C_*C_], g_Wl[L_*C_*C_];
__device__ float          g_bf[L_*C_];
__device__ unsigned short g_t1h[B_*C_*NTOK], g_t1l[B_*C_*NTOK];
__device__ unsigned short g_t2h[B_*C_*NTOK], g_t2l[B_*C_*NTOK];
__device__ unsigned short g_fkh[B_*C_*NTOK], g_fkl[B_*C_*NTOK];
__device__ unsigned short g_qh [B_*C_*NTOK];
__device__ unsigned short g_kh [B_*C_*NTOK];
__device__ unsigned short g_vh [B_*C_*NTOK];
__device__ unsigned short g_ch [B_*C_*NTOK], g_cl [B_*C_*NTOK];

// ---------------- helpers ----------------
__device__ __forceinline__ unsigned smem_u32(const void* p) {
    unsigned a;
    asm("{ .reg .u64 t; cvta.to.shared.u64 t, %1; cvt.u32.u64 %0, t; }" : "=r"(a) : "l"(p));
    return a;
}
__device__ __forceinline__ void cpa16(unsigned dst, const void* src) {
    asm volatile("cp.async.cg.shared.global [%0], [%1], 16;" :: "r"(dst), "l"(src));
}
#define CP_COMMIT() asm volatile("cp.async.commit_group;" ::: "memory")
#define CP_WAIT0()  asm volatile("cp.async.wait_group 0;" ::: "memory")
#define CP_WAIT1()  asm volatile("cp.async.wait_group 1;" ::: "memory")

__device__ __forceinline__ void ldsm4(unsigned* r, unsigned a) {
    asm volatile("ldmatrix.sync.aligned.m8n8.x4.shared.b16 {%0,%1,%2,%3}, [%4];"
        : "=r"(r[0]), "=r"(r[1]), "=r"(r[2]), "=r"(r[3]) : "r"(a));
}
__device__ __forceinline__ void ldsm4t(unsigned* r, unsigned a) {
    asm volatile("ldmatrix.sync.aligned.m8n8.x4.trans.shared.b16 {%0,%1,%2,%3}, [%4];"
        : "=r"(r[0]), "=r"(r[1]), "=r"(r[2]), "=r"(r[3]) : "r"(a));
}
__device__ __forceinline__ void mma16816(float* c, const unsigned* a, const unsigned* b) {
    asm volatile("mma.sync.aligned.m16n8k16.row.col.f32.f16.f16.f32 "
        "{%0,%1,%2,%3}, {%4,%5,%6,%7}, {%8,%9}, {%0,%1,%2,%3};"
        : "+f"(c[0]), "+f"(c[1]), "+f"(c[2]), "+f"(c[3])
        : "r"(a[0]), "r"(a[1]), "r"(a[2]), "r"(a[3]), "r"(b[0]), "r"(b[1]));
}
__device__ __forceinline__ float ex2f(float x) {
    float r; asm("ex2.approx.f32 %0, %1;" : "=f"(r) : "f"(x)); return r;
}
__device__ __forceinline__ unsigned ex2h2(unsigned a) {
    unsigned d; asm("ex2.approx.f16x2 %0, %1;" : "=r"(d) : "r"(a)); return d;
}
__device__ __forceinline__ unsigned hadd2u(unsigned a, unsigned b) {
    unsigned d; asm("add.f16x2 %0, %1, %2;" : "=r"(d) : "r"(a), "r"(b)); return d;
}
__device__ __forceinline__ unsigned packh2(float lo, float hi) {
    unsigned d;
    asm("cvt.rn.f16x2.f32 %0, %1, %2;" : "=r"(d) : "f"(hi), "f"(lo));
    return d;
}
__device__ __forceinline__ float h2sum(unsigned u) {
    __half2 h = *(__half2*)&u;
    return __low2float(h) + __high2float(h);
}
__device__ __forceinline__ unsigned pack2us(unsigned short a, unsigned short b) {
    return (unsigned)a | ((unsigned)b << 16);
}

// ---------------- prep: fold BN, split W into fp16 planes ----------------
__global__ void prep_kernel(const float* __restrict__ Ws, const float* __restrict__ gam,
                            const float* __restrict__ bet, const float* __restrict__ mu,
                            const float* __restrict__ var) {
    int l = blockIdx.x, tid = threadIdx.x;
    __shared__ float sc[C_];
    float s = gam[l*C_+tid] * rsqrtf(var[l*C_+tid] + 1e-5f);
    sc[tid] = s;
    g_bf[l*C_+tid] = bet[l*C_+tid] - mu[l*C_+tid]*s;
    __syncthreads();
    const float* Wl = Ws + l*C_*C_;
    for (int t = tid; t < C_*C_; t += blockDim.x) {
        float wf = Wl[t] * sc[t >> 8];
        __half h = __float2half_rn(wf);
        __half lo = __float2half_rn(wf - __half2float(h));
        g_Wh[l*C_*C_ + t] = __half_as_ushort(h);
        g_Wl[l*C_*C_ + t] = __half_as_ushort(lo);
    }
}

// ---------------- split both fp32 inputs -> fp16 hi/lo planes ----------------
#define NELEM (B_*C_*NTOK)
__global__ void __launch_bounds__(256) split2(const float* __restrict__ a, const float* __restrict__ b,
                                              unsigned short* __restrict__ ah, unsigned short* __restrict__ al,
                                              unsigned short* __restrict__ bh, unsigned short* __restrict__ bl) {
    size_t i = ((size_t)blockIdx.x*256 + threadIdx.x) * 4;
    const float* src; unsigned short *oh, *ol;
    if (i < (size_t)NELEM) { src = a; oh = ah; ol = al; }
    else { i -= NELEM; src = b; oh = bh; ol = bl; }
    float4 w = *(const float4*)(src + i);
    __half h0 = __float2half_rn(w.x), h1 = __float2half_rn(w.y);
    __half h2 = __float2half_rn(w.z), h3 = __float2half_rn(w.w);
    __half l0 = __float2half_rn(w.x - __half2float(h0));
    __half l1 = __float2half_rn(w.y - __half2float(h1));
    __half l2 = __float2half_rn(w.z - __half2float(h2));
    __half l3 = __float2half_rn(w.w - __half2float(h3));
    uint2 vh, vl;
    vh.x = pack2us(__half_as_ushort(h0), __half_as_ushort(h1));
    vh.y = pack2us(__half_as_ushort(h2), __half_as_ushort(h3));
    vl.x = pack2us(__half_as_ushort(l0), __half_as_ushort(l1));
    vl.y = pack2us(__half_as_ushort(l2), __half_as_ushort(l3));
    *(uint2*)(oh + i) = vh;
    *(uint2*)(ol + i) = vl;
}

// ---------------- HMMA convbn+relu: multi-op launch, depth-2 pipelined W+IN ----------------
struct ConvOp {
    const unsigned short *inh, *inl;
    float *o32; unsigned short *oh, *ol;
    int layer; float oscale;
};

#define CV_IN0  65536
#define CV_SMEM 196608

__device__ __forceinline__ void cv_fill_w(unsigned sb, int st, const unsigned short* gWh,
                                          const unsigned short* gWl, int o0, int c0k, int tid) {
    unsigned wbase = sb + (unsigned)st * 32768u;
#pragma unroll
    for (int it = 0; it < 2; it++) {
        int idx = it*512 + tid;
        int row = idx >> 3, ch = idx & 7;
        size_t g = (size_t)(o0 + row)*C_ + c0k + ch*8;
        unsigned d = wbase + (unsigned)row*128 + (unsigned)((ch ^ (row & 7)) & 7)*16;
        cpa16(d, gWh + g);
        cpa16(d + 16384, gWl + g);
    }
}
__device__ __forceinline__ void cv_fill_in(unsigned sb, int st, const unsigned short* inh,
                                           const unsigned short* inl, size_t inoff, int c0k,
                                           int n0, int tid) {
    unsigned ibase = sb + CV_IN0 + (unsigned)st * 65536u;
#pragma unroll
    for (int it = 0; it < 4; it++) {
        int idx = it*512 + tid;
        int row = idx >> 5, ch = idx & 31;
        size_t g = inoff + (size_t)(c0k + row)*NTOK + n0 + ch*8;
        unsigned d = ibase + (unsigned)row*512 +
                     (unsigned)((ch & ~7) | ((ch ^ row) & 7))*16;
        cpa16(d, inh + g);
        cpa16(d + 32768, inl + g);
    }
}

__global__ void __launch_bounds__(512, 1) conv_multi(ConvOp opA, ConvOp opB, ConvOp opC) {
    extern __shared__ char cs[];
    const unsigned sb = smem_u32(cs);
    const int tid = threadIdx.x, wid = tid >> 5, lane = tid & 31;
    const int n0 = blockIdx.x * 256;
    const int o0 = blockIdx.y * 128;
    const int opi = blockIdx.z >> 1;
    const int bz = blockIdx.z & 1;
    const ConvOp op = (opi == 0) ? opA : ((opi == 1) ? opB : opC);
    const int warp_o = wid & 3, warp_n = wid >> 2;
    const int qr = lane >> 2, qc = lane & 3;
    const int r8 = lane & 7, khv = (lane >> 3) & 1, nsel = (lane >> 4) & 1;
    const size_t inoff = (size_t)bz * C_ * NTOK;

    float acc[2][8][4];
#pragma unroll
    for (int mf = 0; mf < 2; mf++)
#pragma unroll
        for (int nf = 0; nf < 8; nf++)
#pragma unroll
            for (int u = 0; u < 4; u++) acc[mf][nf][u] = 0.f;

    const unsigned short* gWh = g_Wh + (size_t)op.layer*C_*C_;
    const unsigned short* gWl = g_Wl + (size_t)op.layer*C_*C_;

    cv_fill_w(sb, 0, gWh, gWl, o0, 0, tid);
    cv_fill_in(sb, 0, op.inh, op.inl, inoff, 0, n0, tid);
    CP_COMMIT();
    cv_fill_w(sb, 1, gWh, gWl, o0, 64, tid);
    cv_fill_in(sb, 1, op.inh, op.inl, inoff, 64, n0, tid);
    CP_COMMIT();

    for (int kc = 0; kc < 4; kc++) {
        if (kc < 3) { CP_WAIT1(); } else { CP_WAIT0(); }
        __syncthreads();
        const unsigned wbase = sb + (unsigned)(kc & 1) * 32768u;
        const unsigned ibH = sb + CV_IN0 + (unsigned)(kc & 1) * 65536u;
        const unsigned ibL = ibH + 32768u;
#pragma unroll
        for (int kg = 0; kg < 4; kg++) {
            unsigned aH[2][4], aL[2][4];
#pragma unroll
            for (int mf = 0; mf < 2; mf++) {
                int mrow = warp_o*32 + mf*16 + (lane & 15);
                int ch = kg*2 + (lane >> 4);
                unsigned aof = (unsigned)mrow*128 + (unsigned)((ch ^ (mrow & 7)) & 7)*16;
                ldsm4(aH[mf], wbase + aof);
                ldsm4(aL[mf], wbase + 16384u + aof);
            }
            int krB = kg*16 + khv*8 + r8;
#pragma unroll
            for (int nfp = 0; nfp < 4; nfp++) {
                unsigned bH4[4], bL4[4];
                int nch = warp_n*8 + nfp*2 + nsel;
                unsigned bof = (unsigned)krB*512 +
                               (unsigned)((nch & ~7) | ((nch ^ (krB & 7)) & 7))*16;
                ldsm4t(bH4, ibH + bof);
                ldsm4t(bL4, ibL + bof);
#pragma unroll
                for (int h = 0; h < 2; h++)
#pragma unroll
                    for (int mf = 0; mf < 2; mf++)
                        mma16816(acc[mf][nfp*2+h], aH[mf], bH4 + 2*h);
#pragma unroll
                for (int h = 0; h < 2; h++)
#pragma unroll
                    for (int mf = 0; mf < 2; mf++)
                        mma16816(acc[mf][nfp*2+h], aH[mf], bL4 + 2*h);
#pragma unroll
                for (int h = 0; h < 2; h++)
#pragma unroll
                    for (int mf = 0; mf < 2; mf++)
                        mma16816(acc[mf][nfp*2+h], aL[mf], bH4 + 2*h);
            }
        }
        __syncthreads();
        if (kc + 2 < 4) {
            int c2 = (kc + 2) * 64;
            cv_fill_w(sb, kc & 1, gWh, gWl, o0, c2, tid);
            cv_fill_in(sb, kc & 1, op.inh, op.inl, inoff, c2, n0, tid);
            CP_COMMIT();
        }
    }

#pragma unroll
    for (int mf = 0; mf < 2; mf++) {
        int oA = o0 + warp_o*32 + mf*16 + qr;
        int oB = oA + 8;
        float bA = g_bf[op.layer*C_ + oA], bB = g_bf[op.layer*C_ + oB];
#pragma unroll
        for (int nf = 0; nf < 8; nf++) {
            int n = n0 + warp_n*64 + nf*8 + qc*2;
            float v0 = fmaxf(acc[mf][nf][0] + bA, 0.f) * op.oscale;
            float v1 = fmaxf(acc[mf][nf][1] + bA, 0.f) * op.oscale;
            float v2 = fmaxf(acc[mf][nf][2] + bB, 0.f) * op.oscale;
            float v3 = fmaxf(acc[mf][nf][3] + bB, 0.f) * op.oscale;
            size_t iA = inoff + (size_t)oA*NTOK + n, iB = inoff + (size_t)oB*NTOK + n;
            if (op.ol) {
                __half h0 = __float2half_rn(v0), h1 = __float2half_rn(v1);
                __half h2 = __float2half_rn(v2), h3 = __float2half_rn(v3);
                *(unsigned*)&op.oh[iA] = pack2us(__half_as_ushort(h0), __half_as_ushort(h1));
                *(unsigned*)&op.oh[iB] = pack2us(__half_as_ushort(h2), __half_as_ushort(h3));
                __half e0 = __float2half_rn(v0 - __half2float(h0));
                __half e1 = __float2half_rn(v1 - __half2float(h1));
                __half e2 = __float2half_rn(v2 - __half2float(h2));
                __half e3 = __float2half_rn(v3 - __half2float(h3));
                *(unsigned*)&op.ol[iA] = pack2us(__half_as_ushort(e0), __half_as_ushort(e1));
                *(unsigned*)&op.ol[iB] = pack2us(__half_as_ushort(e2), __half_as_ushort(e3));
            } else if (op.oh) {
                *(unsigned*)&op.oh[iA] = packh2(v0, v1);
                *(unsigned*)&op.oh[iB] = packh2(v2, v3);
            } else {
                *(float2*)&op.o32[iA] = make_float2(v0, v1);
                *(float2*)&op.o32[iB] = make_float2(v2, v3);
            }
        }
    }
}

// ---------------- pipelined HMMA flash attention (1-term QK, f16x2 softmax) ----------------
// smem: QH[256c][128n] 64K | KH 32K | V 32K = 128K
#define SM_QH 0
#define SM_KH 65536
#define SM_V  98304
#define SM_OL 65536           // epilogue lo staging (overwrites KH+V)
#define SMEM_ATTN 131072

__global__ void __launch_bounds__(256, 1) attn_mma(
    const unsigned short* __restrict__ qhg,
    const unsigned short* __restrict__ khg,
    const unsigned short* __restrict__ vhg,
    unsigned short* __restrict__ chg, unsigned short* __restrict__ clg)
{
    extern __shared__ char smem[];
    const unsigned sb = smem_u32(smem);
    const int tid = threadIdx.x, wid = tid >> 5, lane = tid & 31;
    const int n0 = blockIdx.x * TM;
    const size_t boff = (size_t)blockIdx.y * C_ * NTOK;
    const unsigned short* qh = qhg + boff;
    const unsigned short* kh = khg + boff;
    const unsigned short* vh = vhg + boff;

    const int m0w = wid * 16;
    const int qr = lane >> 2, qc = lane & 3;
    const int r8 = lane & 7, khv = (lane >> 3) & 1, nsel = (lane >> 4) & 1;

    // prologue: group1 = Q + K(0); group2 = V(0)
#pragma unroll
    for (int it = 0; it < 16; it++) {
        int idx = it*256 + tid;
        int row = idx >> 4, ch = idx & 15;
        size_t g = (size_t)row*NTOK + n0 + ch*8;
        unsigned d = sb + SM_QH + (unsigned)row*256 +
                     (unsigned)((ch & ~7) | ((ch ^ row) & 7))*16;
        cpa16(d, qh + g);
    }
#pragma unroll
    for (int it = 0; it < 8; it++) {
        int idx = it*256 + tid;
        int row = idx >> 3, ch = idx & 7;
        unsigned d = sb + SM_KH + (unsigned)row*128 + (unsigned)((ch ^ (row & 7)) & 7)*16;
        cpa16(d, kh + (size_t)row*NTOK + 0 + ch*8);
    }
    CP_COMMIT();
#pragma unroll
    for (int it = 0; it < 8; it++) {
        int idx = it*256 + tid;
        int row = idx >> 3, ch = idx & 7;
        unsigned d = sb + SM_V + (unsigned)row*128 + (unsigned)((ch ^ (row & 7)) & 7)*16;
        cpa16(d, vh + (size_t)row*NTOK + 0 + ch*8);
    }
    CP_COMMIT();

    float O[32][4];
#pragma unroll
    for (int i = 0; i < 32; i++) { O[i][0]=0.f; O[i][1]=0.f; O[i][2]=0.f; O[i][3]=0.f; }
    float mA = -1e30f, mB = -1e30f, lA = 0.f, lB = 0.f;

    for (int t = 0; t < NT; t++) {
        CP_WAIT1();              // K(t) [+Q at t=0] arrived
        __syncthreads();

        // ---- S = Qh Khᵀ (single term) ----
        float S[8][4];
#pragma unroll
        for (int i = 0; i < 8; i++) { S[i][0]=0.f; S[i][1]=0.f; S[i][2]=0.f; S[i][3]=0.f; }
#pragma unroll
        for (int kg = 0; kg < 16; kg++) {
            unsigned aH[4];
            int krA = kg*16 + ((lane >> 4) & 1)*8 + (lane & 7);
            int mch = wid*2 + ((lane >> 3) & 1);
            unsigned aof = (unsigned)krA*256 +
                           (unsigned)((mch & ~7) | ((mch ^ (krA & 7)) & 7))*16;
            ldsm4t(aH, sb + SM_QH + aof);
            int krB = kg*16 + khv*8 + r8;
#pragma unroll
            for (int ntp = 0; ntp < 4; ntp++) {
                unsigned bH4[4];
                int nt = ntp*2 + nsel;
                unsigned bof = (unsigned)krB*128 + (unsigned)((nt ^ (krB & 7)) & 7)*16;
                ldsm4t(bH4, sb + SM_KH + bof);
                mma16816(S[2*ntp],   aH, bH4);
                mma16816(S[2*ntp+1], aH, bH4 + 2);
            }
        }

        CP_WAIT0();              // V(t) arrived
        __syncthreads();         // V visible; K smem free

        if (t + 1 < NT) {        // prefetch K(t+1) — overlaps softmax + PV
            const int k1 = (t + 1) * TN;
#pragma unroll
            for (int it = 0; it < 8; it++) {
                int idx = it*256 + tid;
                int row = idx >> 3, ch = idx & 7;
                unsigned d = sb + SM_KH + (unsigned)row*128 + (unsigned)((ch ^ (row & 7)) & 7)*16;
                cpa16(d, kh + (size_t)row*NTOK + k1 + ch*8);
            }
            CP_COMMIT();
        }

        // ---- online softmax (f16x2 exp path) ----
        float mxA = -1e30f, mxB = -1e30f;
#pragma unroll
        for (int nt = 0; nt < 8; nt++) {
            mxA = fmaxf(mxA, fmaxf(S[nt][0], S[nt][1]));
            mxB = fmaxf(mxB, fmaxf(S[nt][2], S[nt][3]));
        }
        mxA = fmaxf(mxA, __shfl_xor_sync(0xffffffffu, mxA, 1));
        mxA = fmaxf(mxA, __shfl_xor_sync(0xffffffffu, mxA, 2));
        mxB = fmaxf(mxB, __shfl_xor_sync(0xffffffffu, mxB, 1));
        mxB = fmaxf(mxB, __shfl_xor_sync(0xffffffffu, mxB, 2));
        float mAn = fmaxf(mA, mxA), mBn = fmaxf(mB, mxB);
        float facA = ex2f(mA - mAn), facB = ex2f(mB - mBn);
        mA = mAn; mB = mBn;

        unsigned P[4][4];
        unsigned accA0 = 0, accA1 = 0, accB0 = 0, accB1 = 0;
#pragma unroll
        for (int g = 0; g < 4; g++) {
#pragma unroll
            for (int h = 0; h < 2; h++) {
                int nt = 2*g + h;
                unsigned pA = packh2(S[nt][0] - mAn, S[nt][1] - mAn);
                unsigned pB = packh2(S[nt][2] - mBn, S[nt][3] - mBn);
                unsigned eA = ex2h2(pA), eB = ex2h2(pB);
                P[g][2*h]   = eA;
                P[g][2*h+1] = eB;
                if (h == 0) { accA0 = hadd2u(accA0, eA); accB0 = hadd2u(accB0, eB); }
                else        { accA1 = hadd2u(accA1, eA); accB1 = hadd2u(accB1, eB); }
            }
        }
        float sA = h2sum(hadd2u(accA0, accA1));
        float sB = h2sum(hadd2u(accB0, accB1));
        sA += __shfl_xor_sync(0xffffffffu, sA, 1);
        sA += __shfl_xor_sync(0xffffffffu, sA, 2);
        sB += __shfl_xor_sync(0xffffffffu, sB, 1);
        sB += __shfl_xor_sync(0xffffffffu, sB, 2);
        lA = lA * facA + sA;
        lB = lB * facB + sB;
        bool nochg = (facA == 1.f) && (facB == 1.f);
        if (!__all_sync(0xffffffffu, nochg)) {
#pragma unroll
            for (int i = 0; i < 32; i++) {
                O[i][0] *= facA; O[i][1] *= facA; O[i][2] *= facB; O[i][3] *= facB;
            }
        }

        // ---- O += P V ----
#pragma unroll
        for (int jg = 0; jg < 4; jg++) {
#pragma unroll
            for (int ntp = 0; ntp < 16; ntp++) {
                unsigned bV4[4];
                int vrow = (ntp*2 + nsel)*8 + r8;
                int vch = 2*jg + khv;
                unsigned vof = (unsigned)vrow*128 + (unsigned)((vch ^ (vrow & 7)) & 7)*16;
                ldsm4(bV4, sb + SM_V + vof);
                mma16816(O[2*ntp],   P[jg], bV4);
                mma16816(O[2*ntp+1], P[jg], bV4 + 2);
            }
        }

        if (t + 1 < NT) {
            __syncthreads();     // all warps done reading V(t)
            const int k1 = (t + 1) * TN;
#pragma unroll
            for (int it = 0; it < 8; it++) {
                int idx = it*256 + tid;
                int row = idx >> 3, ch = idx & 7;
                unsigned d = sb + SM_V + (unsigned)row*128 + (unsigned)((ch ^ (row & 7)) & 7)*16;
                cpa16(d, vh + (size_t)row*NTOK + k1 + ch*8);
            }
            CP_COMMIT();
        }
    }

    // ---- epilogue: stage split O planes, copy out coalesced ----
    float iA = 1.f / lA, iB = 1.f / lB;
    const int nlA = m0w + qr, nlB = nlA + 8;
    __syncthreads();
#pragma unroll
    for (int nt = 0; nt < 32; nt++) {
        int c = nt*8 + qc*2;
        float v0 = O[nt][0]*iA, v1 = O[nt][1]*iA, v2 = O[nt][2]*iB, v3 = O[nt][3]*iB;
        __half h0 = __float2half_rn(v0), h1 = __float2half_rn(v1);
        __half h2 = __float2half_rn(v2), h3 = __float2half_rn(v3);
        __half e0 = __float2half_rn(v0 - __half2float(h0));
        __half e1 = __float2half_rn(v1 - __half2float(h1));
        __half e2 = __float2half_rn(v2 - __half2float(h2));
        __half e3 = __float2half_rn(v3 - __half2float(h3));
        *(unsigned short*)(smem + SM_QH + (c  )*256 + nlA*2) = __half_as_ushort(h0);
        *(unsigned short*)(smem + SM_QH + (c+1)*256 + nlA*2) = __half_as_ushort(h1);
        *(unsigned short*)(smem + SM_QH + (c  )*256 + nlB*2) = __half_as_ushort(h2);
        *(unsigned short*)(smem + SM_QH + (c+1)*256 + nlB*2) = __half_as_ushort(h3);
        *(unsigned short*)(smem + SM_OL + (c  )*256 + nlA*2) = __half_as_ushort(e0);
        *(unsigned short*)(smem + SM_OL + (c+1)*256 + nlA*2) = __half_as_ushort(e1);
        *(unsigned short*)(smem + SM_OL + (c  )*256 + nlB*2) = __half_as_ushort(e2);
        *(unsigned short*)(smem + SM_OL + (c+1)*256 + nlB*2) = __half_as_ushort(e3);
    }
    __syncthreads();
    unsigned short* cho = chg + boff;
    unsigned short* clo = clg + boff;
#pragma unroll
    for (int it = 0; it < 16; it++) {
        int idx = it*256 + tid;
        int row = idx >> 4, ch = idx & 15;
        uint4 vH = *(uint4*)(smem + SM_QH + row*256 + ch*16);
        uint4 vL = *(uint4*)(smem + SM_OL + row*256 + ch*16);
        *(uint4*)&cho[(size_t)row*NTOK + n0 + ch*8] = vH;
        *(uint4*)&clo[(size_t)row*NTOK + n0 + ch*8] = vL;
    }
}

// ---------------- launch ----------------
extern "C" void kernel_launch(void* const* d_in, const int* in_sizes, int n_in,
                              void* d_out, int out_size) {
    const float* x   = (const float*)d_in[0];
    const float* fk  = (const float*)d_in[1];
    const float* Ws  = (const float*)d_in[2];
    const float* gam = (const float*)d_in[3];
    const float* bet = (const float*)d_in[4];
    const float* mu  = (const float*)d_in[5];
    const float* var = (const float*)d_in[6];
    float* out = (float*)d_out;

    unsigned short *t1h, *t1l, *t2h, *t2l, *fkh, *fkl, *qh, *kh, *vh, *ch, *cl;
    cudaGetSymbolAddress((void**)&t1h, g_t1h);
    cudaGetSymbolAddress((void**)&t1l, g_t1l);
    cudaGetSymbolAddress((void**)&t2h, g_t2h);
    cudaGetSymbolAddress((void**)&t2l, g_t2l);
    cudaGetSymbolAddress((void**)&fkh, g_fkh);
    cudaGetSymbolAddress((void**)&fkl, g_fkl);
    cudaGetSymbolAddress((void**)&qh,  g_qh);
    cudaGetSymbolAddress((void**)&kh,  g_kh);
    cudaGetSymbolAddress((void**)&vh,  g_vh);
    cudaGetSymbolAddress((void**)&ch,  g_ch);
    cudaGetSymbolAddress((void**)&cl,  g_cl);

    cudaFuncSetAttribute(conv_multi, cudaFuncAttributeMaxDynamicSharedMemorySize, CV_SMEM);
    cudaFuncSetAttribute(attn_mma, cudaFuncAttributeMaxDynamicSharedMemorySize, SMEM_ATTN);

    prep_kernel<<<L_, 256>>>(Ws, gam, bet, mu, var);
    split2<<<(2*NELEM)/(256*4), 256>>>(x, fk, ch, cl, fkh, fkl);

    ConvOp nop = {};
    // level A: psi1 (x->t1), phi1 (fk->t2)
    ConvOp a0 = {ch,  cl,  nullptr, t1h, t1l, 0, 1.0f};
    ConvOp a1 = {fkh, fkl, nullptr, t2h, t2l, 2, 1.0f};
    conv_multi<<<dim3(NTOK/256, C_/128, 2*B_), 512, CV_SMEM>>>(a0, a1, nop);
    // level B: psi2 (t1->q), phi2 (t2->k, single plane), f_down (fk->v)
    ConvOp b0 = {t1h, t1l, nullptr, qh, nullptr, 1, LOG2E};
    ConvOp b1 = {t2h, t2l, nullptr, kh, nullptr, 3, 1.0f};
    ConvOp b2 = {fkh, fkl, nullptr, vh, nullptr, 4, 1.0f};
    conv_multi<<<dim3(NTOK/256, C_/128, 3*B_), 512, CV_SMEM>>>(b0, b1, b2);

    attn_mma<<<dim3(NQT, B_), 256, SMEM_ATTN>>>(qh, kh, vh, ch, cl);

    // f_up (ctx->out fp32)
    ConvOp f0 = {ch, cl, out, nullptr, nullptr, 5, 1.0f};
    conv_multi<<<dim3(NTOK/256, C_/128, B_), 512, CV_SMEM>>>(f0, nop, nop);
}